// round 3
// baseline (speedup 1.0000x reference)
#include <cuda_runtime.h>
#include <stdint.h>

// Problem constants
#define T_  10
#define B_  4
#define C_  384
#define N_  384
#define H_  12
#define D_  32
#define SLICES (T_*B_)                 // 40
#define TEN (T_*B_*C_*N_)              // 5,898,240 elements

// Scratch (device globals — no allocations allowed)
__device__ float g_Sqs[TEN];   // spatial q spikes   layout [t][b][c][n]
__device__ float g_Sks[TEN];   // spatial k spikes
__device__ float g_Svs[TEN];   // spatial v spikes
__device__ float g_Sqt[TEN];   // temporal q spikes  layout [t][b][n][c]
__device__ float g_Skt[TEN];
__device__ float g_Svt[TEN];
__device__ float g_Sa [TEN];   // spatial post-attn spikes [t][b][c][n]
__device__ float g_St [TEN];   // temporal post-attn spikes (scrambled reshape) [t'][b][c'][n]
__device__ int   g_acnt[T_*B_*C_];   // spatial spike counts over n
__device__ int   g_bcnt[B_*C_*N_];   // temporal spike counts over t

// ---------------------------------------------------------------------------
// Tiled fp32 GEMM: Z[o][n] = sum_c W[o][c] * X[slice][c][n], then
// affine z*g[o]+b[o], spike = (z >= 2).  Epilogue selected by MODE:
//   MODE 0: store spike float, layout [c][n]      (spatial qkv)
//   MODE 1: store spike float, layout [n][c]      (temporal qkv)
//   MODE 2: count spikes over n -> atomicAdd cnt[slice*C + o]   (spatial back)
//   MODE 3: atomicAdd cnt[(b*C + o)*N + n] per spike (b=slice%B) (temporal back)
// Tile: 128x128, K-block 8, 256 threads, 8x8 micro (split 4+4 layout).
// ---------------------------------------------------------------------------
template<int MODE>
__global__ void __launch_bounds__(256)
conv_gemm(const float* __restrict__ W,
          const float* __restrict__ bn_g,
          const float* __restrict__ bn_b,
          const float* __restrict__ X,
          float* __restrict__ Sout,
          int*   __restrict__ cnt)
{
    __shared__ float As[2][8][132];
    __shared__ float Bs[2][8][132];
    __shared__ int   rcnt[128];

    const int slice = blockIdx.z;
    const float* Xs = X + (size_t)slice * C_ * N_;
    const int oT = blockIdx.y * 128;
    const int nT = blockIdx.x * 128;
    const int tid = threadIdx.x;
    const int tx = tid & 15, ty = tid >> 4;

    const int la_o = tid >> 1,  la_k = (tid & 1) * 4;   // A loader
    const int lb_k = tid >> 5,  lb_n = (tid & 31) * 4;  // B loader

    const float* Aptr = W  + (size_t)(oT + la_o) * C_ + la_k;
    const float* Bptr = Xs + (size_t)lb_k * N_ + nT + lb_n;

    float acc[8][8];
#pragma unroll
    for (int i = 0; i < 8; i++)
#pragma unroll
        for (int j = 0; j < 8; j++) acc[i][j] = 0.f;

    // preload k-block 0
    {
        float4 av = *(const float4*)(Aptr);
        float4 bv = *(const float4*)(Bptr);
        As[0][la_k+0][la_o] = av.x; As[0][la_k+1][la_o] = av.y;
        As[0][la_k+2][la_o] = av.z; As[0][la_k+3][la_o] = av.w;
        *(float4*)&Bs[0][lb_k][lb_n] = bv;
    }
    __syncthreads();

    int buf = 0;
    for (int k0 = 8; k0 < C_ + 8; k0 += 8) {
        float4 av2, bv2;
        const bool more = (k0 < C_);
        if (more) {
            av2 = *(const float4*)(Aptr + k0);
            bv2 = *(const float4*)(Bptr + (size_t)k0 * N_);
        }
#pragma unroll
        for (int kk = 0; kk < 8; kk++) {
            float4 a0 = *(const float4*)&As[buf][kk][ty*4];
            float4 a1 = *(const float4*)&As[buf][kk][64 + ty*4];
            float4 b0 = *(const float4*)&Bs[buf][kk][tx*4];
            float4 b1 = *(const float4*)&Bs[buf][kk][64 + tx*4];
            float ar[8] = {a0.x,a0.y,a0.z,a0.w,a1.x,a1.y,a1.z,a1.w};
            float br[8] = {b0.x,b0.y,b0.z,b0.w,b1.x,b1.y,b1.z,b1.w};
#pragma unroll
            for (int i = 0; i < 8; i++)
#pragma unroll
                for (int j = 0; j < 8; j++)
                    acc[i][j] = fmaf(ar[i], br[j], acc[i][j]);
        }
        if (more) {
            buf ^= 1;
            As[buf][la_k+0][la_o] = av2.x; As[buf][la_k+1][la_o] = av2.y;
            As[buf][la_k+2][la_o] = av2.z; As[buf][la_k+3][la_o] = av2.w;
            *(float4*)&Bs[buf][lb_k][lb_n] = bv2;
            __syncthreads();
        }
    }

    // epilogue: affine + threshold
    int rows[8], cols[8];
#pragma unroll
    for (int i = 0; i < 4; i++) {
        rows[i]   = oT + ty*4 + i;   rows[i+4] = oT + 64 + ty*4 + i;
        cols[i]   = nT + tx*4 + i;   cols[i+4] = nT + 64 + tx*4 + i;
    }
    float gv[8], sv[8];
#pragma unroll
    for (int i = 0; i < 8; i++) { gv[i] = bn_g[rows[i]]; sv[i] = bn_b[rows[i]]; }

    float s[8][8];
#pragma unroll
    for (int i = 0; i < 8; i++)
#pragma unroll
        for (int j = 0; j < 8; j++) {
            float z = __fadd_rn(__fmul_rn(acc[i][j], gv[i]), sv[i]);
            s[i][j] = (z >= 2.0f) ? 1.0f : 0.0f;
        }

    if (MODE == 0) {
        float* Op = Sout + (size_t)slice * C_ * N_;
#pragma unroll
        for (int i = 0; i < 8; i++) {
            float4 v0 = make_float4(s[i][0], s[i][1], s[i][2], s[i][3]);
            float4 v1 = make_float4(s[i][4], s[i][5], s[i][6], s[i][7]);
            *(float4*)&Op[(size_t)rows[i] * N_ + cols[0]] = v0;
            *(float4*)&Op[(size_t)rows[i] * N_ + cols[4]] = v1;
        }
    } else if (MODE == 1) {
        float* Op = Sout + (size_t)slice * C_ * N_;  // [n][c]
#pragma unroll
        for (int j = 0; j < 8; j++) {
            float4 v0 = make_float4(s[0][j], s[1][j], s[2][j], s[3][j]);
            float4 v1 = make_float4(s[4][j], s[5][j], s[6][j], s[7][j]);
            *(float4*)&Op[(size_t)cols[j] * C_ + rows[0]] = v0;
            *(float4*)&Op[(size_t)cols[j] * C_ + rows[4]] = v1;
        }
    } else if (MODE == 2) {
        if (tid < 128) rcnt[tid] = 0;
        __syncthreads();
#pragma unroll
        for (int i = 0; i < 8; i++) {
            float fs = s[i][0]+s[i][1]+s[i][2]+s[i][3]+s[i][4]+s[i][5]+s[i][6]+s[i][7];
            int ci = (int)fs;
            if (ci) atomicAdd(&rcnt[rows[i] - oT], ci);
        }
        __syncthreads();
        if (tid < 128) {
            int v = rcnt[tid];
            if (v) atomicAdd(&cnt[slice * C_ + oT + tid], v);
        }
    } else { // MODE 3
        const int b = slice & (B_ - 1);   // slice = t*B + b
#pragma unroll
        for (int i = 0; i < 8; i++)
#pragma unroll
            for (int j = 0; j < 8; j++)
                if (s[i][j] != 0.f)
                    atomicAdd(&cnt[(size_t)(b * C_ + rows[i]) * N_ + cols[j]], 1);
    }
}

// ---------------------------------------------------------------------------
// Spatial attention (exact integer): per (t,b,h):
//   M[d1][d2] = sum_n K[d1][n]*V[d2][n]  (32x32),  o[n][d2] = sum_d1 Q[d1][n]*M[d1][d2]
//   spike = (o >= 8)   [ == lif(o*0.25) ]
// q/k/v layout [t][b][c][n].  Output Sa same layout.
// ---------------------------------------------------------------------------
__global__ void __launch_bounds__(256)
attn_spatial(const float* __restrict__ Q, const float* __restrict__ K,
             const float* __restrict__ V, float* __restrict__ Sa)
{
    __shared__ float ks[D_][132];
    __shared__ float vs[D_][132];
    __shared__ float Ms[D_][33];

    const int blk = blockIdx.x;            // (t*B+b)*H + h
    const int h   = blk % H_;
    const int tb  = blk / H_;
    const size_t base = (size_t)tb * C_ * N_ + (size_t)h * D_ * N_;
    const int tid = threadIdx.x;

    // phase 1: M = K Vt  over all 384 n (3 chunks of 128)
    const int d1  = tid >> 3;
    const int d2b = (tid & 7) * 4;
    float m0 = 0.f, m1 = 0.f, m2 = 0.f, m3 = 0.f;
    for (int ch = 0; ch < 3; ch++) {
        __syncthreads();
#pragma unroll
        for (int q = 0; q < 4; q++) {
            int f = tid + 256 * q;
            int r = f >> 5, c4 = (f & 31) * 4;
            *(float4*)&ks[r][c4] = *(const float4*)&K[base + (size_t)r * N_ + ch*128 + c4];
            *(float4*)&vs[r][c4] = *(const float4*)&V[base + (size_t)r * N_ + ch*128 + c4];
        }
        __syncthreads();
#pragma unroll 8
        for (int nn = 0; nn < 128; nn++) {
            float kv = ks[d1][nn];
            m0 = fmaf(kv, vs[d2b+0][nn], m0);
            m1 = fmaf(kv, vs[d2b+1][nn], m1);
            m2 = fmaf(kv, vs[d2b+2][nn], m2);
            m3 = fmaf(kv, vs[d2b+3][nn], m3);
        }
    }
    Ms[d1][d2b+0] = m0; Ms[d1][d2b+1] = m1; Ms[d1][d2b+2] = m2; Ms[d1][d2b+3] = m3;
    __syncthreads();

    // phase 2: o = Q^T M, spike
    const int lane = tid & 31, nr = tid >> 5;
    float Mreg[32];
#pragma unroll
    for (int d = 0; d < 32; d++) Mreg[d] = Ms[d][lane];

    for (int ch = 0; ch < 3; ch++) {
        __syncthreads();
#pragma unroll
        for (int q = 0; q < 4; q++) {
            int f = tid + 256 * q;
            int r = f >> 5, c4 = (f & 31) * 4;
            *(float4*)&ks[r][c4] = *(const float4*)&Q[base + (size_t)r * N_ + ch*128 + c4];
        }
        __syncthreads();
        for (int nn = nr; nn < 128; nn += 8) {
            float o = 0.f;
#pragma unroll
            for (int d = 0; d < 32; d++) o = fmaf(ks[d][nn], Mreg[d], o);
            Sa[base + (size_t)lane * N_ + ch*128 + nn] = (o >= 8.0f) ? 1.0f : 0.0f;
        }
    }
}

// ---------------------------------------------------------------------------
// Temporal attention (exact integer): per (n,b,h), T=10, d=32.
// q/k/v layout [t][b][n][c].  Output St at scrambled (torch-reshape) position:
//   idx = 10*h + t;  t' = idx/12;  c' = (idx%12)*32 + d2;  St[t'][b][c'][n]
// ---------------------------------------------------------------------------
__global__ void __launch_bounds__(256)
attn_temporal(const float* __restrict__ Q, const float* __restrict__ K,
              const float* __restrict__ V, float* __restrict__ St)
{
    const int blk = blockIdx.x;            // b*H*(N/32) + h*(N/32) + nc
    const int nc  = blk % (N_ / 32);
    const int h   = (blk / (N_ / 32)) % H_;
    const int b   = blk / ((N_ / 32) * H_);
    const int wid = threadIdx.x >> 5, lane = threadIdx.x & 31;

    for (int ni = 0; ni < 4; ni++) {
        const int n = nc * 32 + wid * 4 + ni;
        float qr[10], kr[10], vr[10];
#pragma unroll
        for (int t = 0; t < 10; t++) {
            size_t a = ((size_t)(t * B_ + b) * N_ + n) * C_ + h * D_ + lane;
            qr[t] = Q[a]; kr[t] = K[a]; vr[t] = V[a];
        }
        float Mr[32];
#pragma unroll
        for (int d = 0; d < 32; d++) Mr[d] = 0.f;
#pragma unroll
        for (int t = 0; t < 10; t++) {
#pragma unroll
            for (int d = 0; d < 32; d++)
                Mr[d] = fmaf(vr[t], __shfl_sync(0xffffffffu, kr[t], d), Mr[d]);
        }
#pragma unroll
        for (int t = 0; t < 10; t++) {
            float o = 0.f;
#pragma unroll
            for (int d = 0; d < 32; d++)
                o = fmaf(__shfl_sync(0xffffffffu, qr[t], d), Mr[d], o);
            const int idx = 10 * h + t;
            const int tn = idx / 12, wn = idx % 12;
            St[(((size_t)tn * B_ + b) * C_ + wn * 32 + lane) * N_ + n] =
                (o >= 8.0f) ? 1.0f : 0.0f;
        }
    }
}

// out[t,b,c,n] = (acnt[t,b,c]/384) * (bcnt[b,c,n]/10)
__global__ void finalize_kernel(const int* __restrict__ acnt,
                                const int* __restrict__ bcnt,
                                float* __restrict__ out)
{
    int i = blockIdx.x * 256 + threadIdx.x;
    if (i >= TEN) return;
    int n  = i % N_;
    int c  = (i / N_) % C_;
    int bb = (i / (N_ * C_)) % B_;
    int t  = i / (N_ * C_ * B_);
    float a = (float)acnt[(t * B_ + bb) * C_ + c] / 384.0f;
    float bt = (float)bcnt[(bb * C_ + c) * N_ + n] / 10.0f;
    out[i] = a * bt;
}

extern "C" void kernel_launch(void* const* d_in, const int* in_sizes, int n_in,
                              void* d_out, int out_size)
{
    (void)in_sizes; (void)n_in; (void)out_size;
    const float* x  = (const float*)d_in[0];
    const float* y  = (const float*)d_in[1];
    const float* Ws = (const float*)d_in[2];
    const float* gs = (const float*)d_in[3];
    const float* bs = (const float*)d_in[4];
    const float* Wt = (const float*)d_in[5];
    const float* gt = (const float*)d_in[6];
    const float* bt = (const float*)d_in[7];
    float* out = (float*)d_out;

    float *Sqs, *Sks, *Svs, *Sqt, *Skt, *Svt, *Sa, *St;
    int *acnt, *bcnt;
    cudaGetSymbolAddress((void**)&Sqs, g_Sqs);
    cudaGetSymbolAddress((void**)&Sks, g_Sks);
    cudaGetSymbolAddress((void**)&Svs, g_Svs);
    cudaGetSymbolAddress((void**)&Sqt, g_Sqt);
    cudaGetSymbolAddress((void**)&Skt, g_Skt);
    cudaGetSymbolAddress((void**)&Svt, g_Svt);
    cudaGetSymbolAddress((void**)&Sa,  g_Sa);
    cudaGetSymbolAddress((void**)&St,  g_St);
    cudaGetSymbolAddress((void**)&acnt, g_acnt);
    cudaGetSymbolAddress((void**)&bcnt, g_bcnt);

    cudaMemsetAsync(acnt, 0, sizeof(int) * T_ * B_ * C_, 0);
    cudaMemsetAsync(bcnt, 0, sizeof(int) * B_ * C_ * N_, 0);

    dim3 g3(3, 3, SLICES);
    // front convs -> binary spike tensors
    conv_gemm<0><<<g3, 256>>>(Ws + 0*C_*C_, gs + 0*C_, bs + 0*C_, x, Sqs, nullptr);
    conv_gemm<0><<<g3, 256>>>(Ws + 1*C_*C_, gs + 1*C_, bs + 1*C_, y, Sks, nullptr);
    conv_gemm<0><<<g3, 256>>>(Ws + 2*C_*C_, gs + 2*C_, bs + 2*C_, y, Svs, nullptr);
    conv_gemm<1><<<g3, 256>>>(Wt + 0*C_*C_, gt + 0*C_, bt + 0*C_, x, Sqt, nullptr);
    conv_gemm<1><<<g3, 256>>>(Wt + 1*C_*C_, gt + 1*C_, bt + 1*C_, y, Skt, nullptr);
    conv_gemm<1><<<g3, 256>>>(Wt + 2*C_*C_, gt + 2*C_, bt + 2*C_, y, Svt, nullptr);
    // exact-integer factorized attention + LIF
    attn_spatial <<<SLICES * H_, 256>>>(Sqs, Sks, Svs, Sa);
    attn_temporal<<<B_ * H_ * (N_ / 32), 256>>>(Sqt, Skt, Svt, St);
    // back convs -> spike counts (rank-1 output factors)
    conv_gemm<2><<<g3, 256>>>(Ws + 3*C_*C_, gs + 3*C_, bs + 3*C_, Sa, nullptr, acnt);
    conv_gemm<3><<<g3, 256>>>(Wt + 3*C_*C_, gt + 3*C_, bt + 3*C_, St, nullptr, bcnt);
    // outer product
    finalize_kernel<<<(TEN + 255) / 256, 256>>>(acnt, bcnt, out);
}

// round 4
// speedup vs baseline: 1.1312x; 1.1312x over previous
#include <cuda_runtime.h>
#include <stdint.h>

// Problem constants
#define T_  10
#define B_  4
#define C_  384
#define N_  384
#define H_  12
#define D_  32
#define SLICES (T_*B_)                 // 40
#define TEN (T_*B_*C_*N_)              // 5,898,240 elements
#define C2  (C_*C_)
#define CN  (C_*N_)

typedef unsigned long long u64;

// Scratch (device globals — no allocations allowed)
__device__ float g_Sqs[TEN];   // spatial q spikes   [t][b][c][n]
__device__ float g_Sks[TEN];
__device__ float g_Svs[TEN];
__device__ float g_Sqt[TEN];   // temporal q spikes  [t][b][n][c]
__device__ float g_Skt[TEN];
__device__ float g_Svt[TEN];
__device__ float g_Sa [TEN];   // spatial post-attn spikes [t][b][c][n]
__device__ float g_St [TEN];   // temporal post-attn spikes (torch-reshape layout) [t'][b][c'][n]
__device__ int   g_acnt[T_*B_*C_];
__device__ int   g_bcnt[B_*C_*N_];

// ---------------------------------------------------------------------------
// Packed f32x2 helpers (FFMA2 — 2 MACs per fma-pipe slot on sm_103a)
// ---------------------------------------------------------------------------
__device__ __forceinline__ u64 pack2(float lo, float hi) {
    u64 r;
    asm("mov.b64 %0, {%1, %2};" : "=l"(r) : "f"(lo), "f"(hi));
    return r;
}
__device__ __forceinline__ void ffma2(u64 &d, u64 a, u64 b) {
    asm("fma.rn.f32x2 %0, %1, %2, %0;" : "+l"(d) : "l"(a), "l"(b));
}
__device__ __forceinline__ float2 unpack2(u64 v) {
    float2 f;
    asm("mov.b64 {%0, %1}, %2;" : "=f"(f.x), "=f"(f.y) : "l"(v));
    return f;
}

// ---------------------------------------------------------------------------
// Fused FFMA2 GEMM.  Z[o][n] = sum_c W[o][c] * X[slice][c][n], affine, spike.
// Block tile 192(o) x 128(n), KB=16, 256 threads, 12x8 per thread
// (6 row-pairs x 4 col-pairs, accumulators are f32x2 row-pairs).
// PHASE 0: blockIdx.z = conv*40+slice, conv 0..5 (3 spatial->[c][n], 3 temporal->[n][c])
// PHASE 1: blockIdx.z = which*40+slice, which 0: spatial back (row counts),
//          which 1: temporal back (per-(b,c,n) counts over t).
// ---------------------------------------------------------------------------
#define KB   16
#define APAD 194

template<int PHASE>
__global__ void __launch_bounds__(256, 1)
gemm_all(const float* __restrict__ x,  const float* __restrict__ y,
         const float* __restrict__ Ws, const float* __restrict__ gs, const float* __restrict__ bs,
         const float* __restrict__ Wt, const float* __restrict__ gt, const float* __restrict__ bt,
         float* __restrict__ Sqs, float* __restrict__ Sks, float* __restrict__ Svs,
         float* __restrict__ Sqt, float* __restrict__ Skt, float* __restrict__ Svt,
         const float* __restrict__ Sa, const float* __restrict__ St,
         int* __restrict__ acnt, int* __restrict__ bcnt)
{
    __shared__ float As[2][KB][APAD];   // [k][o], padded for conflict-free transposed STS
    __shared__ float Bs[2][KB][128];    // [k][n]
    __shared__ int   rcnt[192];

    const int z     = blockIdx.z;
    const int sel   = z / SLICES;
    const int slice = z % SLICES;

    const float *W, *G, *Bb, *X;
    float* O = nullptr;
    int mode;
    if (PHASE == 0) {
        if (sel < 3) { W = Ws + sel*C2;     G = gs + sel*C_;     Bb = bs + sel*C_;     mode = 0; }
        else         { W = Wt + (sel-3)*C2; G = gt + (sel-3)*C_; Bb = bt + (sel-3)*C_; mode = 1; }
        X = (sel == 0 || sel == 3) ? x : y;
        if      (sel == 0) O = Sqs; else if (sel == 1) O = Sks; else if (sel == 2) O = Svs;
        else if (sel == 3) O = Sqt; else if (sel == 4) O = Skt; else               O = Svt;
        O += (size_t)slice * CN;
    } else {
        if (sel == 0) { W = Ws + 3*C2; G = gs + 3*C_; Bb = bs + 3*C_; X = Sa; mode = 2; }
        else          { W = Wt + 3*C2; G = gt + 3*C_; Bb = bt + 3*C_; X = St; mode = 3; }
    }
    const float* Xs = X + (size_t)slice * CN;

    const int oT = blockIdx.y * 192;
    const int nT = blockIdx.x * 128;
    const int tid = threadIdx.x;
    const int tx = tid & 15, ty = tid >> 4;

    u64 acc[6][4][2];
#pragma unroll
    for (int q = 0; q < 6; q++)
#pragma unroll
        for (int p = 0; p < 4; p++) { acc[q][p][0] = 0ull; acc[q][p][1] = 0ull; }

    float4 av[3], bv[2];

    auto ldA = [&](int k0) {
#pragma unroll
        for (int it = 0; it < 3; it++) {
            int f = tid + 256*it;
            av[it] = *(const float4*)&W[(size_t)(oT + (f >> 2)) * C_ + k0 + (f & 3)*4];
        }
    };
    auto ldB = [&](int k0) {
#pragma unroll
        for (int it = 0; it < 2; it++) {
            int f = tid + 256*it;
            bv[it] = *(const float4*)&Xs[(size_t)(k0 + (f >> 5)) * N_ + nT + (f & 31)*4];
        }
    };
    auto stA = [&](int b2) {
#pragma unroll
        for (int it = 0; it < 3; it++) {
            int f = tid + 256*it;
            int row = f >> 2, c4 = (f & 3)*4;
            As[b2][c4+0][row] = av[it].x; As[b2][c4+1][row] = av[it].y;
            As[b2][c4+2][row] = av[it].z; As[b2][c4+3][row] = av[it].w;
        }
    };
    auto stB = [&](int b2) {
#pragma unroll
        for (int it = 0; it < 2; it++) {
            int f = tid + 256*it;
            *(float4*)&Bs[b2][f >> 5][(f & 31)*4] = bv[it];
        }
    };

    ldA(0); ldB(0);
    stA(0); stB(0);
    __syncthreads();

    int buf = 0;
#pragma unroll 1
    for (int kb = 1; kb <= C_/KB; kb++) {
        const bool more = (kb < C_/KB);
        if (more) { ldA(kb*KB); ldB(kb*KB); }

        const float* Ab  = &As[buf][0][0];
        const float* Bp  = &Bs[buf][0][0];
#pragma unroll
        for (int kk = 0; kk < KB; kk++) {
            u64 a2[6];
#pragma unroll
            for (int q = 0; q < 6; q++)
                a2[q] = *(const u64*)&Ab[kk*APAD + 2*ty + 32*q];
#pragma unroll
            for (int p = 0; p < 4; p++) {
                float2 b = *(const float2*)&Bp[kk*128 + 2*tx + 32*p];
                u64 b0 = pack2(b.x, b.x);
                u64 b1 = pack2(b.y, b.y);
#pragma unroll
                for (int q = 0; q < 6; q++) {
                    ffma2(acc[q][p][0], a2[q], b0);
                    ffma2(acc[q][p][1], a2[q], b1);
                }
            }
        }

        if (more) {
            stA(buf ^ 1); stB(buf ^ 1);
            __syncthreads();
            buf ^= 1;
        }
    }

    // ---------------- epilogue: affine + threshold, per-mode output ----------
    float gv[12], sv[12];
#pragma unroll
    for (int q = 0; q < 6; q++) {
        int r = oT + 2*ty + 32*q;
        gv[2*q]   = G[r];    gv[2*q+1]  = G[r+1];
        sv[2*q]   = Bb[r];   sv[2*q+1]  = Bb[r+1];
    }

    if (PHASE == 1 && mode == 2) {
        if (tid < 192) rcnt[tid] = 0;
        __syncthreads();
    }

    const int bb2 = slice & (B_ - 1);

#pragma unroll
    for (int q = 0; q < 6; q++) {
        const int r0 = oT + 2*ty + 32*q;
        float cr0 = 0.f, cr1 = 0.f;   // mode-2 row counts
#pragma unroll
        for (int p = 0; p < 4; p++) {
            const int c0 = nT + 2*tx + 32*p;
            float2 a0 = unpack2(acc[q][p][0]);   // col c0, rows r0,r0+1
            float2 a1 = unpack2(acc[q][p][1]);   // col c0+1
            float s00 = (__fadd_rn(__fmul_rn(a0.x, gv[2*q]),   sv[2*q])   >= 2.0f) ? 1.f : 0.f;
            float s10 = (__fadd_rn(__fmul_rn(a0.y, gv[2*q+1]), sv[2*q+1]) >= 2.0f) ? 1.f : 0.f;
            float s01 = (__fadd_rn(__fmul_rn(a1.x, gv[2*q]),   sv[2*q])   >= 2.0f) ? 1.f : 0.f;
            float s11 = (__fadd_rn(__fmul_rn(a1.y, gv[2*q+1]), sv[2*q+1]) >= 2.0f) ? 1.f : 0.f;

            if (PHASE == 0) {
                if (mode == 0) {          // spatial: [c][n]
                    *(float2*)&O[(size_t)r0     * N_ + c0] = make_float2(s00, s01);
                    *(float2*)&O[(size_t)(r0+1) * N_ + c0] = make_float2(s10, s11);
                } else {                  // temporal: [n][c]
                    *(float2*)&O[(size_t)c0     * C_ + r0] = make_float2(s00, s10);
                    *(float2*)&O[(size_t)(c0+1) * C_ + r0] = make_float2(s01, s11);
                }
            } else {
                if (mode == 2) {
                    cr0 += s00 + s01;
                    cr1 += s10 + s11;
                } else {
                    if (s00 != 0.f) atomicAdd(&bcnt[(size_t)(bb2*C_ + r0    )*N_ + c0    ], 1);
                    if (s01 != 0.f) atomicAdd(&bcnt[(size_t)(bb2*C_ + r0    )*N_ + c0 + 1], 1);
                    if (s10 != 0.f) atomicAdd(&bcnt[(size_t)(bb2*C_ + r0 + 1)*N_ + c0    ], 1);
                    if (s11 != 0.f) atomicAdd(&bcnt[(size_t)(bb2*C_ + r0 + 1)*N_ + c0 + 1], 1);
                }
            }
        }
        if (PHASE == 1 && mode == 2) {
            int lr = 2*ty + 32*q;
            int i0 = (int)cr0, i1 = (int)cr1;
            if (i0) atomicAdd(&rcnt[lr],     i0);
            if (i1) atomicAdd(&rcnt[lr + 1], i1);
        }
    }

    if (PHASE == 1 && mode == 2) {
        __syncthreads();
        if (tid < 192) {
            int v = rcnt[tid];
            if (v) atomicAdd(&acnt[slice * C_ + oT + tid], v);
        }
    }
}

// ---------------------------------------------------------------------------
// Spatial attention (exact integer): per (t,b,h):
//   M[d1][d2] = sum_n K[d1][n]*V[d2][n]; o[n][d2] = sum_d1 Q[d1][n]*M[d1][d2]
//   spike = (o >= 8)  [ == lif(o*0.25) ]
// ---------------------------------------------------------------------------
__global__ void __launch_bounds__(256)
attn_spatial(const float* __restrict__ Q, const float* __restrict__ K,
             const float* __restrict__ V, float* __restrict__ Sa)
{
    __shared__ float ks[D_][132];
    __shared__ float vs[D_][132];
    __shared__ float Ms[D_][33];

    const int blk = blockIdx.x;            // (t*B+b)*H + h
    const int h   = blk % H_;
    const int tb  = blk / H_;
    const size_t base = (size_t)tb * CN + (size_t)h * D_ * N_;
    const int tid = threadIdx.x;

    const int d1  = tid >> 3;
    const int d2b = (tid & 7) * 4;
    float m0 = 0.f, m1 = 0.f, m2 = 0.f, m3 = 0.f;
    for (int ch = 0; ch < 3; ch++) {
        __syncthreads();
#pragma unroll
        for (int q = 0; q < 4; q++) {
            int f = tid + 256 * q;
            int r = f >> 5, c4 = (f & 31) * 4;
            *(float4*)&ks[r][c4] = *(const float4*)&K[base + (size_t)r * N_ + ch*128 + c4];
            *(float4*)&vs[r][c4] = *(const float4*)&V[base + (size_t)r * N_ + ch*128 + c4];
        }
        __syncthreads();
#pragma unroll 8
        for (int nn = 0; nn < 128; nn++) {
            float kv = ks[d1][nn];
            m0 = fmaf(kv, vs[d2b+0][nn], m0);
            m1 = fmaf(kv, vs[d2b+1][nn], m1);
            m2 = fmaf(kv, vs[d2b+2][nn], m2);
            m3 = fmaf(kv, vs[d2b+3][nn], m3);
        }
    }
    Ms[d1][d2b+0] = m0; Ms[d1][d2b+1] = m1; Ms[d1][d2b+2] = m2; Ms[d1][d2b+3] = m3;
    __syncthreads();

    const int lane = tid & 31, nr = tid >> 5;
    float Mreg[32];
#pragma unroll
    for (int d = 0; d < 32; d++) Mreg[d] = Ms[d][lane];

    for (int ch = 0; ch < 3; ch++) {
        __syncthreads();
#pragma unroll
        for (int q = 0; q < 4; q++) {
            int f = tid + 256 * q;
            int r = f >> 5, c4 = (f & 31) * 4;
            *(float4*)&ks[r][c4] = *(const float4*)&Q[base + (size_t)r * N_ + ch*128 + c4];
        }
        __syncthreads();
        for (int nn = nr; nn < 128; nn += 8) {
            float o = 0.f;
#pragma unroll
            for (int d = 0; d < 32; d++) o = fmaf(ks[d][nn], Mreg[d], o);
            Sa[base + (size_t)lane * N_ + ch*128 + nn] = (o >= 8.0f) ? 1.0f : 0.0f;
        }
    }
}

// ---------------------------------------------------------------------------
// Temporal attention (exact integer): per (n,b,h), T=10, d=32.
// Output St at torch-reshape position: idx=10h+t; t'=idx/12; c'=(idx%12)*32+d
// ---------------------------------------------------------------------------
__global__ void __launch_bounds__(256)
attn_temporal(const float* __restrict__ Q, const float* __restrict__ K,
              const float* __restrict__ V, float* __restrict__ St)
{
    const int blk = blockIdx.x;            // b*H*(N/32) + h*(N/32) + nc
    const int nc  = blk % (N_ / 32);
    const int h   = (blk / (N_ / 32)) % H_;
    const int b   = blk / ((N_ / 32) * H_);
    const int wid = threadIdx.x >> 5, lane = threadIdx.x & 31;

    for (int ni = 0; ni < 4; ni++) {
        const int n = nc * 32 + wid * 4 + ni;
        float qr[10], kr[10], vr[10];
#pragma unroll
        for (int t = 0; t < 10; t++) {
            size_t a = ((size_t)(t * B_ + b) * N_ + n) * C_ + h * D_ + lane;
            qr[t] = Q[a]; kr[t] = K[a]; vr[t] = V[a];
        }
        float Mr[32];
#pragma unroll
        for (int d = 0; d < 32; d++) Mr[d] = 0.f;
#pragma unroll
        for (int t = 0; t < 10; t++) {
#pragma unroll
            for (int d = 0; d < 32; d++)
                Mr[d] = fmaf(vr[t], __shfl_sync(0xffffffffu, kr[t], d), Mr[d]);
        }
#pragma unroll
        for (int t = 0; t < 10; t++) {
            float o = 0.f;
#pragma unroll
            for (int d = 0; d < 32; d++)
                o = fmaf(__shfl_sync(0xffffffffu, qr[t], d), Mr[d], o);
            const int idx = 10 * h + t;
            const int tn = idx / 12, wn = idx % 12;
            St[(((size_t)tn * B_ + b) * C_ + wn * 32 + lane) * N_ + n] =
                (o >= 8.0f) ? 1.0f : 0.0f;
        }
    }
}

// out[t,b,c,n] = (acnt[t,b,c]/384) * (bcnt[b,c,n]/10)
__global__ void finalize_kernel(const int* __restrict__ acnt,
                                const int* __restrict__ bcnt,
                                float* __restrict__ out)
{
    int i = blockIdx.x * 256 + threadIdx.x;
    if (i >= TEN) return;
    int n  = i % N_;
    int c  = (i / N_) % C_;
    int bb = (i / (N_ * C_)) % B_;
    int t  = i / (N_ * C_ * B_);
    float a  = (float)acnt[(t * B_ + bb) * C_ + c] / 384.0f;
    float bt = (float)bcnt[(bb * C_ + c) * N_ + n] / 10.0f;
    out[i] = a * bt;
}

extern "C" void kernel_launch(void* const* d_in, const int* in_sizes, int n_in,
                              void* d_out, int out_size)
{
    (void)in_sizes; (void)n_in; (void)out_size;
    const float* x  = (const float*)d_in[0];
    const float* y  = (const float*)d_in[1];
    const float* Ws = (const float*)d_in[2];
    const float* gs = (const float*)d_in[3];
    const float* bs = (const float*)d_in[4];
    const float* Wt = (const float*)d_in[5];
    const float* gt = (const float*)d_in[6];
    const float* bt = (const float*)d_in[7];
    float* out = (float*)d_out;

    float *Sqs, *Sks, *Svs, *Sqt, *Skt, *Svt, *Sa, *St;
    int *acnt, *bcnt;
    cudaGetSymbolAddress((void**)&Sqs, g_Sqs);
    cudaGetSymbolAddress((void**)&Sks, g_Sks);
    cudaGetSymbolAddress((void**)&Svs, g_Svs);
    cudaGetSymbolAddress((void**)&Sqt, g_Sqt);
    cudaGetSymbolAddress((void**)&Skt, g_Skt);
    cudaGetSymbolAddress((void**)&Svt, g_Svt);
    cudaGetSymbolAddress((void**)&Sa,  g_Sa);
    cudaGetSymbolAddress((void**)&St,  g_St);
    cudaGetSymbolAddress((void**)&acnt, g_acnt);
    cudaGetSymbolAddress((void**)&bcnt, g_bcnt);

    cudaMemsetAsync(acnt, 0, sizeof(int) * T_ * B_ * C_, 0);
    cudaMemsetAsync(bcnt, 0, sizeof(int) * B_ * C_ * N_, 0);

    // All six front convs in one launch: grid z = conv*40 + slice
    dim3 gf(3, 2, 6 * SLICES);
    gemm_all<0><<<gf, 256>>>(x, y, Ws, gs, bs, Wt, gt, bt,
                             Sqs, Sks, Svs, Sqt, Skt, Svt,
                             nullptr, nullptr, nullptr, nullptr);

    // Exact-integer factorized attention + LIF
    attn_spatial <<<SLICES * H_, 256>>>(Sqs, Sks, Svs, Sa);
    attn_temporal<<<B_ * H_ * (N_ / 32), 256>>>(Sqt, Skt, Svt, St);

    // Both back convs in one launch: grid z = which*40 + slice
    dim3 gb(3, 2, 2 * SLICES);
    gemm_all<1><<<gb, 256>>>(x, y, Ws, gs, bs, Wt, gt, bt,
                             Sqs, Sks, Svs, Sqt, Skt, Svt,
                             Sa, St, acnt, bcnt);

    // Rank-1 outer product
    finalize_kernel<<<(TEN + 255) / 256, 256>>>(acnt, bcnt, out);
}

// round 7
// speedup vs baseline: 1.2183x; 1.0770x over previous
#include <cuda_runtime.h>
#include <stdint.h>

// Problem constants
#define T_  10
#define B_  4
#define C_  384
#define N_  384
#define H_  12
#define D_  32
#define SLICES (T_*B_)                 // 40
#define TEN (T_*B_*C_*N_)              // 5,898,240 elements
#define C2  (C_*C_)
#define CN  (C_*N_)

typedef unsigned long long u64;
typedef unsigned int u32;

// Scratch (device globals — no allocations allowed)
__device__ __align__(16) float g_Sqs[TEN];   // spatial q spikes   [t][b][c][n]
__device__ __align__(16) float g_Sks[TEN];
__device__ __align__(16) float g_Svs[TEN];
__device__ __align__(16) float g_Sqt[TEN];   // temporal q spikes  [t][b][n][c]
__device__ __align__(16) float g_Skt[TEN];
__device__ __align__(16) float g_Svt[TEN];
__device__ __align__(16) float g_Sa [TEN];   // spatial post-attn spikes [t][b][c][n]
__device__ __align__(16) float g_St [TEN];   // temporal post-attn spikes (torch-reshape) [t'][b][c'][n]
__device__ __align__(16) float g_WT [8*C2];  // transposed weights [idx][c][o]
__device__ int g_acnt[T_*B_*C_];
__device__ int g_bcnt[B_*C_*N_];

// ---------------------------------------------------------------------------
// Packed f32x2 + cp.async helpers
// ---------------------------------------------------------------------------
__device__ __forceinline__ u64 pack2(float lo, float hi) {
    u64 r;
    asm("mov.b64 %0, {%1, %2};" : "=l"(r) : "f"(lo), "f"(hi));
    return r;
}
__device__ __forceinline__ void ffma2(u64 &d, u64 a, u64 b) {
    asm("fma.rn.f32x2 %0, %1, %2, %0;" : "+l"(d) : "l"(a), "l"(b));
}
__device__ __forceinline__ float2 unpack2(u64 v) {
    float2 f;
    asm("mov.b64 {%0, %1}, %2;" : "=f"(f.x), "=f"(f.y) : "l"(v));
    return f;
}
__device__ __forceinline__ void cpa16(u32 saddr, const float* g) {
    asm volatile("cp.async.cg.shared.global [%0], [%1], 16;" :: "r"(saddr), "l"(g));
}
#define CPA_COMMIT()  asm volatile("cp.async.commit_group;")
#define CPA_WAIT2()   asm volatile("cp.async.wait_group 2;")

// ---------------------------------------------------------------------------
// FFMA2 GEMM, 128x128 tile, KB=16, 256 threads, 2 CTAs/SM, 4-stage cp.async.
// Z[o][n] = sum_c WT[c][o] * X[slice][c][n], affine, spike (z >= 2).
// Per thread: rows {4ty..4ty+3, 64+4ty..64+4ty+3}, cols {2tx,2tx+1}+32p.
// acc in diag/anti f32x2 form (both operands native pairs).
// PHASE 0: z = conv*40+slice, conv 0..5 (3 spatial->[c][n], 3 temporal->[n][c])
// PHASE 1: z = which*40+slice (0: spatial back -> row counts; 1: temporal back
//          -> per-(b,c,n) counts over t).
// ---------------------------------------------------------------------------
#define KB 16
#define NKB (C_/KB)          // 24
#define STG_FLOATS 4096      // (16*128)*2 per stage
#define GEMM_SMEM (4*STG_FLOATS*4)   // 65536 B

template<int PHASE>
__global__ void __launch_bounds__(256, 2)
gemm_all(const float* __restrict__ x,  const float* __restrict__ y,
         const float* __restrict__ WT,
         const float* __restrict__ gs, const float* __restrict__ bs,
         const float* __restrict__ gt, const float* __restrict__ bt,
         float* __restrict__ Sqs, float* __restrict__ Sks, float* __restrict__ Svs,
         float* __restrict__ Sqt, float* __restrict__ Skt, float* __restrict__ Svt,
         const float* __restrict__ Sa, const float* __restrict__ St,
         int* __restrict__ acnt, int* __restrict__ bcnt)
{
    extern __shared__ float sm[];
    __shared__ int rcnt[128];

    const int z     = blockIdx.z;
    const int sel   = z / SLICES;
    const int slice = z % SLICES;

    const float *G, *Bb, *X;
    float* O = nullptr;
    int widx, mode;
    if (PHASE == 0) {
        if (sel < 3) { widx = sel;     G = gs + sel*C_;     Bb = bs + sel*C_;     mode = 0; }
        else         { widx = sel + 1; G = gt + (sel-3)*C_; Bb = bt + (sel-3)*C_; mode = 1; }
        X = (sel == 0 || sel == 3) ? x : y;
        if      (sel == 0) O = Sqs; else if (sel == 1) O = Sks; else if (sel == 2) O = Svs;
        else if (sel == 3) O = Sqt; else if (sel == 4) O = Skt; else               O = Svt;
        O += (size_t)slice * CN;
    } else {
        if (sel == 0) { widx = 3; G = gs + 3*C_; Bb = bs + 3*C_; X = Sa; mode = 2; }
        else          { widx = 7; G = gt + 3*C_; Bb = bt + 3*C_; X = St; mode = 3; }
    }
    const float* A  = WT + (size_t)widx * C2;       // [c][o]
    const float* Xs = X  + (size_t)slice * CN;      // [c][n]

    const int oT = blockIdx.y * 128;
    const int nT = blockIdx.x * 128;
    const int tid = threadIdx.x;
    const int tx = tid & 15, ty = tid >> 4;

    if (PHASE == 1 && mode == 2 && tid < 128) rcnt[tid] = 0;

    const u32 smb = (u32)__cvta_generic_to_shared(sm);

    auto issue = [&](int kb) {
        const u32 sb = smb + (u32)(kb & 3) * (STG_FLOATS * 4);
#pragma unroll
        for (int it = 0; it < 2; it++) {
            int id = tid + 256 * it;
            int k = id >> 5, o4 = (id & 31) * 4;
            cpa16(sb + (u32)id * 16,        A  + (size_t)(kb*KB + k) * C_ + oT + o4);
            cpa16(sb + 8192 + (u32)id * 16, Xs + (size_t)(kb*KB + k) * N_ + nT + o4);
        }
        CPA_COMMIT();
    };

    u64 diag[4][4], anti[4][4];
#pragma unroll
    for (int q = 0; q < 4; q++)
#pragma unroll
        for (int p = 0; p < 4; p++) { diag[q][p] = 0ull; anti[q][p] = 0ull; }

    issue(0); issue(1); issue(2);

#pragma unroll 1
    for (int kb = 0; kb < NKB; kb++) {
        CPA_WAIT2();
        __syncthreads();
        if (kb + 3 < NKB) issue(kb + 3);

        const float* Ab  = sm + (kb & 3) * STG_FLOATS;
        const float* Bp  = Ab + 2048;
#pragma unroll
        for (int kk = 0; kk < KB; kk++) {
            u64 aq[4];
            aq[0] = *(const u64*)&Ab[kk*128 + 4*ty];
            aq[1] = *(const u64*)&Ab[kk*128 + 4*ty + 2];
            aq[2] = *(const u64*)&Ab[kk*128 + 64 + 4*ty];
            aq[3] = *(const u64*)&Ab[kk*128 + 64 + 4*ty + 2];
#pragma unroll
            for (int p = 0; p < 4; p++) {
                float2 f = *(const float2*)&Bp[kk*128 + 2*tx + 32*p];
                u64 bn = pack2(f.x, f.y);
                u64 bw = pack2(f.y, f.x);
#pragma unroll
                for (int q = 0; q < 4; q++) {
                    ffma2(diag[q][p], aq[q], bn);
                    ffma2(anti[q][p], aq[q], bw);
                }
            }
        }
    }

    // ---------------- epilogue: affine + threshold ----------------
    // local row lr 0..7 -> tile row rloc(lr); local col lc 0..7 -> c = 2tx+32*(lc>>1)+(lc&1)
    int rloc[8];
#pragma unroll
    for (int i = 0; i < 4; i++) { rloc[i] = 4*ty + i; rloc[i+4] = 64 + 4*ty + i; }

    float gv[8], sv[8];
#pragma unroll
    for (int i = 0; i < 8; i++) { gv[i] = G[oT + rloc[i]]; sv[i] = Bb[oT + rloc[i]]; }

    float s[8][8];
#pragma unroll
    for (int q = 0; q < 4; q++) {
        const int l0 = 2*q, l1 = 2*q + 1;
#pragma unroll
        for (int p = 0; p < 4; p++) {
            float2 dd = unpack2(diag[q][p]);
            float2 aa = unpack2(anti[q][p]);
            s[l0][2*p]   = (__fadd_rn(__fmul_rn(dd.x, gv[l0]), sv[l0]) >= 2.0f) ? 1.f : 0.f;
            s[l1][2*p+1] = (__fadd_rn(__fmul_rn(dd.y, gv[l1]), sv[l1]) >= 2.0f) ? 1.f : 0.f;
            s[l0][2*p+1] = (__fadd_rn(__fmul_rn(aa.x, gv[l0]), sv[l0]) >= 2.0f) ? 1.f : 0.f;
            s[l1][2*p]   = (__fadd_rn(__fmul_rn(aa.y, gv[l1]), sv[l1]) >= 2.0f) ? 1.f : 0.f;
        }
    }

    const int bb2 = slice & (B_ - 1);

    if (PHASE == 0) {
        if (mode == 0) {            // spatial: [c][n]
#pragma unroll
            for (int lr = 0; lr < 8; lr++) {
                float* row = O + (size_t)(oT + rloc[lr]) * N_ + nT;
#pragma unroll
                for (int p = 0; p < 4; p++)
                    *(float2*)&row[2*tx + 32*p] = make_float2(s[lr][2*p], s[lr][2*p+1]);
            }
        } else {                    // temporal: [n][c]
#pragma unroll
            for (int lc = 0; lc < 8; lc++) {
                const int c = nT + 2*tx + 32*(lc >> 1) + (lc & 1);
                float* col = O + (size_t)c * C_ + oT;
                *(float4*)&col[4*ty]      = make_float4(s[0][lc], s[1][lc], s[2][lc], s[3][lc]);
                *(float4*)&col[64 + 4*ty] = make_float4(s[4][lc], s[5][lc], s[6][lc], s[7][lc]);
            }
        }
    } else if (mode == 2) {
#pragma unroll
        for (int lr = 0; lr < 8; lr++) {
            float fs = s[lr][0]+s[lr][1]+s[lr][2]+s[lr][3]+s[lr][4]+s[lr][5]+s[lr][6]+s[lr][7];
            int ci = (int)fs;
            if (ci) atomicAdd(&rcnt[rloc[lr]], ci);
        }
        __syncthreads();
        if (tid < 128) {
            int v = rcnt[tid];
            if (v) atomicAdd(&acnt[slice * C_ + oT + tid], v);
        }
    } else { // mode 3
#pragma unroll
        for (int lr = 0; lr < 8; lr++) {
            const int r = oT + rloc[lr];
#pragma unroll
            for (int lc = 0; lc < 8; lc++) {
                if (s[lr][lc] != 0.f) {
                    const int c = nT + 2*tx + 32*(lc >> 1) + (lc & 1);
                    atomicAdd(&bcnt[(size_t)(bb2 * C_ + r) * N_ + c], 1);
                }
            }
        }
    }
}

// ---------------------------------------------------------------------------
// Transpose all 8 weight matrices: WT[idx][c][o] = W[idx][o][c]
// ---------------------------------------------------------------------------
__global__ void transpose_w(const float* __restrict__ Ws, const float* __restrict__ Wt2,
                            float* __restrict__ WT)
{
    __shared__ float tile[32][33];
    const int m = blockIdx.z;
    const float* src = (m < 4) ? (Ws + (size_t)m * C2) : (Wt2 + (size_t)(m - 4) * C2);
    const int o0 = blockIdx.x * 32, c0 = blockIdx.y * 32;
    const int tx = threadIdx.x, ty0 = threadIdx.y;
#pragma unroll
    for (int j = 0; j < 32; j += 8)
        tile[ty0 + j][tx] = src[(size_t)(o0 + ty0 + j) * C_ + c0 + tx];
    __syncthreads();
    float* dst = WT + (size_t)m * C2;
#pragma unroll
    for (int j = 0; j < 32; j += 8)
        dst[(size_t)(c0 + ty0 + j) * C_ + o0 + tx] = tile[tx][ty0 + j];
}

// ---------------------------------------------------------------------------
// Spatial attention (exact integer): per (t,b,h):
//   M[d1][d2] = sum_n K[d1][n]*V[d2][n]; o[n][d2] = sum_d1 Q[d1][n]*M[d1][d2]
//   spike = (o >= 8)  [ == lif(o*0.25) ]
// ---------------------------------------------------------------------------
__global__ void __launch_bounds__(256)
attn_spatial(const float* __restrict__ Q, const float* __restrict__ K,
             const float* __restrict__ V, float* __restrict__ Sa)
{
    __shared__ float ks[D_][132];
    __shared__ float vs[D_][132];
    __shared__ float Ms[D_][33];

    const int blk = blockIdx.x;            // (t*B+b)*H + h
    const int h   = blk % H_;
    const int tb  = blk / H_;
    const size_t base = (size_t)tb * CN + (size_t)h * D_ * N_;
    const int tid = threadIdx.x;

    const int d1  = tid >> 3;
    const int d2b = (tid & 7) * 4;
    float m0 = 0.f, m1 = 0.f, m2 = 0.f, m3 = 0.f;
    for (int ch = 0; ch < 3; ch++) {
        __syncthreads();
#pragma unroll
        for (int q = 0; q < 4; q++) {
            int f = tid + 256 * q;
            int r = f >> 5, c4 = (f & 31) * 4;
            *(float4*)&ks[r][c4] = *(const float4*)&K[base + (size_t)r * N_ + ch*128 + c4];
            *(float4*)&vs[r][c4] = *(const float4*)&V[base + (size_t)r * N_ + ch*128 + c4];
        }
        __syncthreads();
#pragma unroll 8
        for (int nn = 0; nn < 128; nn++) {
            float kv = ks[d1][nn];
            m0 = fmaf(kv, vs[d2b+0][nn], m0);
            m1 = fmaf(kv, vs[d2b+1][nn], m1);
            m2 = fmaf(kv, vs[d2b+2][nn], m2);
            m3 = fmaf(kv, vs[d2b+3][nn], m3);
        }
    }
    Ms[d1][d2b+0] = m0; Ms[d1][d2b+1] = m1; Ms[d1][d2b+2] = m2; Ms[d1][d2b+3] = m3;
    __syncthreads();

    const int lane = tid & 31, nr = tid >> 5;
    float Mreg[32];
#pragma unroll
    for (int d = 0; d < 32; d++) Mreg[d] = Ms[d][lane];

    for (int ch = 0; ch < 3; ch++) {
        __syncthreads();
#pragma unroll
        for (int q = 0; q < 4; q++) {
            int f = tid + 256 * q;
            int r = f >> 5, c4 = (f & 31) * 4;
            *(float4*)&ks[r][c4] = *(const float4*)&Q[base + (size_t)r * N_ + ch*128 + c4];
        }
        __syncthreads();
        for (int nn = nr; nn < 128; nn += 8) {
            float o = 0.f;
#pragma unroll
            for (int d = 0; d < 32; d++) o = fmaf(ks[d][nn], Mreg[d], o);
            Sa[base + (size_t)lane * N_ + ch*128 + nn] = (o >= 8.0f) ? 1.0f : 0.0f;
        }
    }
}

// ---------------------------------------------------------------------------
// Temporal attention (exact integer): per (n,b,h), T=10, d=32.
// Output St at torch-reshape position: idx=10h+t; t'=idx/12; c'=(idx%12)*32+d
// ---------------------------------------------------------------------------
__global__ void __launch_bounds__(256)
attn_temporal(const float* __restrict__ Q, const float* __restrict__ K,
              const float* __restrict__ V, float* __restrict__ St)
{
    const int blk = blockIdx.x;            // b*H*(N/32) + h*(N/32) + nc
    const int nc  = blk % (N_ / 32);
    const int h   = (blk / (N_ / 32)) % H_;
    const int b   = blk / ((N_ / 32) * H_);
    const int wid = threadIdx.x >> 5, lane = threadIdx.x & 31;

    for (int ni = 0; ni < 4; ni++) {
        const int n = nc * 32 + wid * 4 + ni;
        float qr[10], kr[10], vr[10];
#pragma unroll
        for (int t = 0; t < 10; t++) {
            size_t a = ((size_t)(t * B_ + b) * N_ + n) * C_ + h * D_ + lane;
            qr[t] = Q[a]; kr[t] = K[a]; vr[t] = V[a];
        }
        float Mr[32];
#pragma unroll
        for (int d = 0; d < 32; d++) Mr[d] = 0.f;
#pragma unroll
        for (int t = 0; t < 10; t++) {
#pragma unroll
            for (int d = 0; d < 32; d++)
                Mr[d] = fmaf(vr[t], __shfl_sync(0xffffffffu, kr[t], d), Mr[d]);
        }
#pragma unroll
        for (int t = 0; t < 10; t++) {
            float o = 0.f;
#pragma unroll
            for (int d = 0; d < 32; d++)
                o = fmaf(__shfl_sync(0xffffffffu, qr[t], d), Mr[d], o);
            const int idx = 10 * h + t;
            const int tn = idx / 12, wn = idx % 12;
            St[(((size_t)tn * B_ + b) * C_ + wn * 32 + lane) * N_ + n] =
                (o >= 8.0f) ? 1.0f : 0.0f;
        }
    }
}

// out[t,b,c,n] = (acnt[t,b,c]/384) * (bcnt[b,c,n]/10)
__global__ void finalize_kernel(const int* __restrict__ acnt,
                                const int* __restrict__ bcnt,
                                float* __restrict__ out)
{
    int i = blockIdx.x * 256 + threadIdx.x;
    if (i >= TEN) return;
    int n  = i % N_;
    int c  = (i / N_) % C_;
    int bb = (i / (N_ * C_)) % B_;
    int t  = i / (N_ * C_ * B_);
    float a  = (float)acnt[(t * B_ + bb) * C_ + c] / 384.0f;
    float bt = (float)bcnt[(bb * C_ + c) * N_ + n] / 10.0f;
    out[i] = a * bt;
}

extern "C" void kernel_launch(void* const* d_in, const int* in_sizes, int n_in,
                              void* d_out, int out_size)
{
    (void)in_sizes; (void)n_in; (void)out_size;
    const float* x  = (const float*)d_in[0];
    const float* y  = (const float*)d_in[1];
    const float* Ws = (const float*)d_in[2];
    const float* gs = (const float*)d_in[3];
    const float* bs = (const float*)d_in[4];
    const float* Wt = (const float*)d_in[5];
    const float* gt = (const float*)d_in[6];
    const float* bt = (const float*)d_in[7];
    float* out = (float*)d_out;

    float *Sqs, *Sks, *Svs, *Sqt, *Skt, *Svt, *Sa, *St, *WT;
    int *acnt, *bcnt;
    cudaGetSymbolAddress((void**)&Sqs, g_Sqs);
    cudaGetSymbolAddress((void**)&Sks, g_Sks);
    cudaGetSymbolAddress((void**)&Svs, g_Svs);
    cudaGetSymbolAddress((void**)&Sqt, g_Sqt);
    cudaGetSymbolAddress((void**)&Skt, g_Skt);
    cudaGetSymbolAddress((void**)&Svt, g_Svt);
    cudaGetSymbolAddress((void**)&Sa,  g_Sa);
    cudaGetSymbolAddress((void**)&St,  g_St);
    cudaGetSymbolAddress((void**)&WT,  g_WT);
    cudaGetSymbolAddress((void**)&acnt, g_acnt);
    cudaGetSymbolAddress((void**)&bcnt, g_bcnt);

    cudaFuncSetAttribute(gemm_all<0>, cudaFuncAttributeMaxDynamicSharedMemorySize, GEMM_SMEM);
    cudaFuncSetAttribute(gemm_all<1>, cudaFuncAttributeMaxDynamicSharedMemorySize, GEMM_SMEM);

    cudaMemsetAsync(acnt, 0, sizeof(int) * T_ * B_ * C_, 0);
    cudaMemsetAsync(bcnt, 0, sizeof(int) * B_ * C_ * N_, 0);

    // Pre-transpose all 8 weight matrices into [c][o] layout
    transpose_w<<<dim3(C_/32, C_/32, 8), dim3(32, 8)>>>(Ws, Wt, WT);

    // All six front convs in one launch: grid z = conv*40 + slice
    dim3 gf(3, 3, 6 * SLICES);
    gemm_all<0><<<gf, 256, GEMM_SMEM>>>(x, y, WT, gs, bs, gt, bt,
                                        Sqs, Sks, Svs, Sqt, Skt, Svt,
                                        nullptr, nullptr, nullptr, nullptr);

    // Exact-integer factorized attention + LIF
    attn_spatial <<<SLICES * H_, 256>>>(Sqs, Sks, Svs, Sa);
    attn_temporal<<<B_ * H_ * (N_ / 32), 256>>>(Sqt, Skt, Svt, St);

    // Both back convs in one launch: grid z = which*40 + slice
    dim3 gb(3, 3, 2 * SLICES);
    gemm_all<1><<<gb, 256, GEMM_SMEM>>>(x, y, WT, gs, bs, gt, bt,
                                        Sqs, Sks, Svs, Sqt, Skt, Svt,
                                        Sa, St, acnt, bcnt);

    // Rank-1 outer product
    finalize_kernel<<<(TEN + 255) / 256, 256>>>(acnt, bcnt, out);
}

// round 8
// speedup vs baseline: 1.4577x; 1.1965x over previous
#include <cuda_runtime.h>
#include <stdint.h>

// Problem constants
#define T_  10
#define B_  4
#define C_  384
#define N_  384
#define H_  12
#define D_  32
#define SLICES (T_*B_)                 // 40
#define TEN (T_*B_*C_*N_)              // 5,898,240 elements
#define C2  (C_*C_)
#define CN  (C_*N_)

typedef unsigned long long u64;
typedef unsigned int u32;

// Scratch (device globals — no allocations allowed)
__device__ __align__(16) float g_Sqs[TEN];   // spatial q spikes   [t][b][c][n]
__device__ __align__(16) float g_Sks[TEN];
__device__ __align__(16) float g_Svs[TEN];
__device__ __align__(16) float g_Sqt[TEN];   // temporal q spikes  [t][b][n][c]
__device__ __align__(16) float g_Skt[TEN];
__device__ __align__(16) float g_Svt[TEN];
__device__ __align__(16) float g_Sa [TEN];   // spatial post-attn spikes [t][b][c][n]
__device__ __align__(16) float g_St [TEN];   // temporal post-attn spikes (torch-reshape) [t'][b][c'][n]
__device__ __align__(16) float g_WT [8*C2];  // transposed weights [idx][c][o]
__device__ int g_acnt[T_*B_*C_];
__device__ int g_bcnt[B_*C_*N_];

// ---------------------------------------------------------------------------
// Packed f32x2 + cp.async helpers
// ---------------------------------------------------------------------------
__device__ __forceinline__ u64 pack2(float lo, float hi) {
    u64 r;
    asm("mov.b64 %0, {%1, %2};" : "=l"(r) : "f"(lo), "f"(hi));
    return r;
}
__device__ __forceinline__ void ffma2(u64 &d, u64 a, u64 b) {
    asm("fma.rn.f32x2 %0, %1, %2, %0;" : "+l"(d) : "l"(a), "l"(b));
}
__device__ __forceinline__ float2 unpack2(u64 v) {
    float2 f;
    asm("mov.b64 {%0, %1}, %2;" : "=f"(f.x), "=f"(f.y) : "l"(v));
    return f;
}
__device__ __forceinline__ void cpa16(u32 saddr, const float* g) {
    asm volatile("cp.async.cg.shared.global [%0], [%1], 16;" :: "r"(saddr), "l"(g));
}
#define CPA_COMMIT()  asm volatile("cp.async.commit_group;")
#define CPA_WAIT2()   asm volatile("cp.async.wait_group 2;")

// ---------------------------------------------------------------------------
// FFMA2 GEMM, 128x128 tile, KB=16, 256 threads, 2 CTAs/SM, 4-stage cp.async.
// Z[o][n] = sum_c WT[c][o] * X[slice][c][n], affine, spike (z >= 2).
// PHASE 0: z = conv*40+slice, conv 0..5 (3 spatial->[c][n], 3 temporal->[n][c])
// PHASE 1: z = which*40+slice (0: spatial back -> row counts; 1: temporal back
//          -> per-(b,c,n) counts over t).
// ---------------------------------------------------------------------------
#define KB 16
#define NKB (C_/KB)          // 24
#define STG_FLOATS 4096      // (16*128)*2 per stage
#define GEMM_SMEM (4*STG_FLOATS*4)   // 65536 B

template<int PHASE>
__global__ void __launch_bounds__(256, 2)
gemm_all(const float* __restrict__ x,  const float* __restrict__ y,
         const float* __restrict__ WT,
         const float* __restrict__ gs, const float* __restrict__ bs,
         const float* __restrict__ gt, const float* __restrict__ bt,
         float* __restrict__ Sqs, float* __restrict__ Sks, float* __restrict__ Svs,
         float* __restrict__ Sqt, float* __restrict__ Skt, float* __restrict__ Svt,
         const float* __restrict__ Sa, const float* __restrict__ St,
         int* __restrict__ acnt, int* __restrict__ bcnt)
{
    extern __shared__ float sm[];
    __shared__ int rcnt[128];

    const int z     = blockIdx.z;
    const int sel   = z / SLICES;
    const int slice = z % SLICES;

    const float *G, *Bb, *X;
    float* O = nullptr;
    int widx, mode;
    if (PHASE == 0) {
        if (sel < 3) { widx = sel;     G = gs + sel*C_;     Bb = bs + sel*C_;     mode = 0; }
        else         { widx = sel + 1; G = gt + (sel-3)*C_; Bb = bt + (sel-3)*C_; mode = 1; }
        X = (sel == 0 || sel == 3) ? x : y;
        if      (sel == 0) O = Sqs; else if (sel == 1) O = Sks; else if (sel == 2) O = Svs;
        else if (sel == 3) O = Sqt; else if (sel == 4) O = Skt; else               O = Svt;
        O += (size_t)slice * CN;
    } else {
        if (sel == 0) { widx = 3; G = gs + 3*C_; Bb = bs + 3*C_; X = Sa; mode = 2; }
        else          { widx = 7; G = gt + 3*C_; Bb = bt + 3*C_; X = St; mode = 3; }
    }
    const float* A  = WT + (size_t)widx * C2;       // [c][o]
    const float* Xs = X  + (size_t)slice * CN;      // [c][n]

    const int oT = blockIdx.y * 128;
    const int nT = blockIdx.x * 128;
    const int tid = threadIdx.x;
    const int tx = tid & 15, ty = tid >> 4;

    if (PHASE == 1 && mode == 2 && tid < 128) rcnt[tid] = 0;

    const u32 smb = (u32)__cvta_generic_to_shared(sm);

    auto issue = [&](int kb) {
        const u32 sb = smb + (u32)(kb & 3) * (STG_FLOATS * 4);
#pragma unroll
        for (int it = 0; it < 2; it++) {
            int id = tid + 256 * it;
            int k = id >> 5, o4 = (id & 31) * 4;
            cpa16(sb + (u32)id * 16,        A  + (size_t)(kb*KB + k) * C_ + oT + o4);
            cpa16(sb + 8192 + (u32)id * 16, Xs + (size_t)(kb*KB + k) * N_ + nT + o4);
        }
        CPA_COMMIT();
    };

    u64 diag[4][4], anti[4][4];
#pragma unroll
    for (int q = 0; q < 4; q++)
#pragma unroll
        for (int p = 0; p < 4; p++) { diag[q][p] = 0ull; anti[q][p] = 0ull; }

    issue(0); issue(1); issue(2);

#pragma unroll 1
    for (int kb = 0; kb < NKB; kb++) {
        CPA_WAIT2();
        __syncthreads();
        if (kb + 3 < NKB) issue(kb + 3);

        const float* Ab  = sm + (kb & 3) * STG_FLOATS;
        const float* Bp  = Ab + 2048;
#pragma unroll
        for (int kk = 0; kk < KB; kk++) {
            u64 aq[4];
            aq[0] = *(const u64*)&Ab[kk*128 + 4*ty];
            aq[1] = *(const u64*)&Ab[kk*128 + 4*ty + 2];
            aq[2] = *(const u64*)&Ab[kk*128 + 64 + 4*ty];
            aq[3] = *(const u64*)&Ab[kk*128 + 64 + 4*ty + 2];
#pragma unroll
            for (int p = 0; p < 4; p++) {
                float2 f = *(const float2*)&Bp[kk*128 + 2*tx + 32*p];
                u64 bn = pack2(f.x, f.y);
                u64 bw = pack2(f.y, f.x);
#pragma unroll
                for (int q = 0; q < 4; q++) {
                    ffma2(diag[q][p], aq[q], bn);
                    ffma2(anti[q][p], aq[q], bw);
                }
            }
        }
    }

    // ---------------- epilogue: affine + threshold ----------------
    int rloc[8];
#pragma unroll
    for (int i = 0; i < 4; i++) { rloc[i] = 4*ty + i; rloc[i+4] = 64 + 4*ty + i; }

    float gv[8], sv[8];
#pragma unroll
    for (int i = 0; i < 8; i++) { gv[i] = G[oT + rloc[i]]; sv[i] = Bb[oT + rloc[i]]; }

    float s[8][8];
#pragma unroll
    for (int q = 0; q < 4; q++) {
        const int l0 = 2*q, l1 = 2*q + 1;
#pragma unroll
        for (int p = 0; p < 4; p++) {
            float2 dd = unpack2(diag[q][p]);
            float2 aa = unpack2(anti[q][p]);
            s[l0][2*p]   = (__fadd_rn(__fmul_rn(dd.x, gv[l0]), sv[l0]) >= 2.0f) ? 1.f : 0.f;
            s[l1][2*p+1] = (__fadd_rn(__fmul_rn(dd.y, gv[l1]), sv[l1]) >= 2.0f) ? 1.f : 0.f;
            s[l0][2*p+1] = (__fadd_rn(__fmul_rn(aa.x, gv[l0]), sv[l0]) >= 2.0f) ? 1.f : 0.f;
            s[l1][2*p]   = (__fadd_rn(__fmul_rn(aa.y, gv[l1]), sv[l1]) >= 2.0f) ? 1.f : 0.f;
        }
    }

    const int bb2 = slice & (B_ - 1);

    if (PHASE == 0) {
        if (mode == 0) {            // spatial: [c][n]
#pragma unroll
            for (int lr = 0; lr < 8; lr++) {
                float* row = O + (size_t)(oT + rloc[lr]) * N_ + nT;
#pragma unroll
                for (int p = 0; p < 4; p++)
                    *(float2*)&row[2*tx + 32*p] = make_float2(s[lr][2*p], s[lr][2*p+1]);
            }
        } else {                    // temporal: [n][c]
#pragma unroll
            for (int lc = 0; lc < 8; lc++) {
                const int c = nT + 2*tx + 32*(lc >> 1) + (lc & 1);
                float* col = O + (size_t)c * C_ + oT;
                *(float4*)&col[4*ty]      = make_float4(s[0][lc], s[1][lc], s[2][lc], s[3][lc]);
                *(float4*)&col[64 + 4*ty] = make_float4(s[4][lc], s[5][lc], s[6][lc], s[7][lc]);
            }
        }
    } else if (mode == 2) {
#pragma unroll
        for (int lr = 0; lr < 8; lr++) {
            float fs = s[lr][0]+s[lr][1]+s[lr][2]+s[lr][3]+s[lr][4]+s[lr][5]+s[lr][6]+s[lr][7];
            int ci = (int)fs;
            if (ci) atomicAdd(&rcnt[rloc[lr]], ci);
        }
        __syncthreads();
        if (tid < 128) {
            int v = rcnt[tid];
            if (v) atomicAdd(&acnt[slice * C_ + oT + tid], v);
        }
    } else { // mode 3
#pragma unroll
        for (int lr = 0; lr < 8; lr++) {
            const int r = oT + rloc[lr];
#pragma unroll
            for (int lc = 0; lc < 8; lc++) {
                if (s[lr][lc] != 0.f) {
                    const int c = nT + 2*tx + 32*(lc >> 1) + (lc & 1);
                    atomicAdd(&bcnt[(size_t)(bb2 * C_ + r) * N_ + c], 1);
                }
            }
        }
    }
}

// ---------------------------------------------------------------------------
// Transpose all 8 weight matrices: WT[idx][c][o] = W[idx][o][c]
// ---------------------------------------------------------------------------
__global__ void transpose_w(const float* __restrict__ Ws, const float* __restrict__ Wt2,
                            float* __restrict__ WT)
{
    __shared__ float tile[32][33];
    const int m = blockIdx.z;
    const float* src = (m < 4) ? (Ws + (size_t)m * C2) : (Wt2 + (size_t)(m - 4) * C2);
    const int o0 = blockIdx.x * 32, c0 = blockIdx.y * 32;
    const int tx = threadIdx.x, ty0 = threadIdx.y;
#pragma unroll
    for (int j = 0; j < 32; j += 8)
        tile[ty0 + j][tx] = src[(size_t)(o0 + ty0 + j) * C_ + c0 + tx];
    __syncthreads();
    float* dst = WT + (size_t)m * C2;
#pragma unroll
    for (int j = 0; j < 32; j += 8)
        dst[(size_t)(c0 + ty0 + j) * C_ + o0 + tx] = tile[tx][ty0 + j];
}

// ---------------------------------------------------------------------------
// Spatial attention — exact integer via bit-packing + popc.
// Per (t,b,h):  M[d1][d2] = sum_n K[d1][n]*V[d2][n] = sum_w popc(Kb&Vb)
//               o[n][d2]  = sum_{d1 : Q[d1][n]=1} M[d1][d2];  spike = (o >= 8)
// ---------------------------------------------------------------------------
__global__ void __launch_bounds__(256)
attn_spatial(const float* __restrict__ Q, const float* __restrict__ K,
             const float* __restrict__ V, float* __restrict__ Sa)
{
    __shared__ u32 Qb[32][12], Kb[32][12], Vb[32][12];
    __shared__ int Ms[32][33];

    const int blk = blockIdx.x;            // (t*B+b)*H + h
    const int h   = blk % H_;
    const int tb  = blk / H_;
    const size_t base = (size_t)tb * CN + (size_t)h * D_ * N_;
    const int tid = threadIdx.x;
    const int wid = tid >> 5, lane = tid & 31;

    // bit-pack Q,K,V: warp wid owns rows d = wid*4 .. wid*4+3
#pragma unroll
    for (int i = 0; i < 4; i++) {
        const int d = wid*4 + i;
        const float* qr = Q + base + (size_t)d * N_;
        const float* kr = K + base + (size_t)d * N_;
        const float* vr = V + base + (size_t)d * N_;
#pragma unroll
        for (int w = 0; w < 12; w++) {
            u32 qm = __ballot_sync(0xffffffffu, qr[w*32 + lane] != 0.f);
            u32 km = __ballot_sync(0xffffffffu, kr[w*32 + lane] != 0.f);
            u32 vm = __ballot_sync(0xffffffffu, vr[w*32 + lane] != 0.f);
            if (lane == 0) { Qb[d][w] = qm; Kb[d][w] = km; Vb[d][w] = vm; }
        }
    }
    __syncthreads();

    // phase 1: M[32][32] counts, 4 entries per thread
    {
        const int d1  = tid >> 3;
        const int d2b = (tid & 7) * 4;
#pragma unroll
        for (int j = 0; j < 4; j++) {
            int s = 0;
#pragma unroll
            for (int w = 0; w < 12; w++) s += __popc(Kb[d1][w] & Vb[d2b + j][w]);
            Ms[d1][d2b + j] = s;
        }
    }
    __syncthreads();

    // phase 2: warp wid handles n in [wid*48, wid*48+48), lane = d2, groups of 8
    float* orow = Sa + base + (size_t)lane * N_;
#pragma unroll
    for (int g = 0; g < 6; g++) {
        const int nb = wid*48 + g*8;      // multiple of 8 -> stays within one word
        const int w  = nb >> 5, sh = nb & 31;
        int o[8];
#pragma unroll
        for (int j = 0; j < 8; j++) o[j] = 0;
#pragma unroll 4
        for (int d1 = 0; d1 < 32; d1++) {
            const int m = Ms[d1][lane];
            const u32 bits = (Qb[d1][w] >> sh) & 0xffu;
#pragma unroll
            for (int j = 0; j < 8; j++)
                if (bits & (1u << j)) o[j] += m;
        }
        float4 v0 = make_float4(o[0]>=8?1.f:0.f, o[1]>=8?1.f:0.f,
                                o[2]>=8?1.f:0.f, o[3]>=8?1.f:0.f);
        float4 v1 = make_float4(o[4]>=8?1.f:0.f, o[5]>=8?1.f:0.f,
                                o[6]>=8?1.f:0.f, o[7]>=8?1.f:0.f);
        *(float4*)&orow[nb]     = v0;
        *(float4*)&orow[nb + 4] = v1;
    }
}

// ---------------------------------------------------------------------------
// Temporal attention — exact integer via ballot + popc.  Per (n,b,h):
//   attn[t][s] = popc(qb[t] & kb[s]);  o[t][d] = sum_{s: v[s][d]=1} attn[t][s]
//   spike = (o >= 8).  Output at torch-reshape position:
//   idx=10h+t; t'=idx/12; c'=(idx%12)*32+d
// ---------------------------------------------------------------------------
__global__ void __launch_bounds__(256)
attn_temporal(const float* __restrict__ Q, const float* __restrict__ K,
              const float* __restrict__ V, float* __restrict__ St)
{
    const int blk = blockIdx.x;            // b*H*(N/32) + h*(N/32) + nc
    const int nc  = blk % (N_ / 32);
    const int h   = (blk / (N_ / 32)) % H_;
    const int b   = blk / ((N_ / 32) * H_);
    const int wid = threadIdx.x >> 5, lane = threadIdx.x & 31;
    const int n0  = nc * 32 + wid * 4;

    u32 spk[10];
#pragma unroll
    for (int t = 0; t < 10; t++) spk[t] = 0;

#pragma unroll
    for (int ni = 0; ni < 4; ni++) {
        const int n = n0 + ni;
        u32 qb[10], kb[10], vloc = 0;
#pragma unroll
        for (int t = 0; t < 10; t++) {
            size_t a = ((size_t)(t * B_ + b) * N_ + n) * C_ + h * D_ + lane;
            qb[t] = __ballot_sync(0xffffffffu, Q[a] != 0.f);
            kb[t] = __ballot_sync(0xffffffffu, K[a] != 0.f);
            vloc |= (V[a] != 0.f) ? (1u << t) : 0u;
        }
#pragma unroll
        for (int t = 0; t < 10; t++) {
            int o = 0;
#pragma unroll
            for (int s = 0; s < 10; s++)
                if (vloc & (1u << s)) o += __popc(qb[t] & kb[s]);
            if (o >= 8) spk[t] |= 1u << ni;
        }
    }

#pragma unroll
    for (int t = 0; t < 10; t++) {
        const int idx = 10 * h + t;
        const int tn = idx / 12, wn = idx % 12;
        float4 v = make_float4((spk[t] & 1u) ? 1.f : 0.f,
                               (spk[t] & 2u) ? 1.f : 0.f,
                               (spk[t] & 4u) ? 1.f : 0.f,
                               (spk[t] & 8u) ? 1.f : 0.f);
        *(float4*)&St[(((size_t)tn * B_ + b) * C_ + wn * 32 + lane) * N_ + n0] = v;
    }
}

// out[t,b,c,n] = (acnt[t,b,c]/384) * (bcnt[b,c,n]/10)
__global__ void finalize_kernel(const int* __restrict__ acnt,
                                const int* __restrict__ bcnt,
                                float* __restrict__ out)
{
    int i = blockIdx.x * 256 + threadIdx.x;
    if (i >= TEN) return;
    int n  = i % N_;
    int c  = (i / N_) % C_;
    int bb = (i / (N_ * C_)) % B_;
    int t  = i / (N_ * C_ * B_);
    float a  = (float)acnt[(t * B_ + bb) * C_ + c] / 384.0f;
    float bt = (float)bcnt[(bb * C_ + c) * N_ + n] / 10.0f;
    out[i] = a * bt;
}

extern "C" void kernel_launch(void* const* d_in, const int* in_sizes, int n_in,
                              void* d_out, int out_size)
{
    (void)in_sizes; (void)n_in; (void)out_size;
    const float* x  = (const float*)d_in[0];
    const float* y  = (const float*)d_in[1];
    const float* Ws = (const float*)d_in[2];
    const float* gs = (const float*)d_in[3];
    const float* bs = (const float*)d_in[4];
    const float* Wt = (const float*)d_in[5];
    const float* gt = (const float*)d_in[6];
    const float* bt = (const float*)d_in[7];
    float* out = (float*)d_out;

    float *Sqs, *Sks, *Svs, *Sqt, *Skt, *Svt, *Sa, *St, *WT;
    int *acnt, *bcnt;
    cudaGetSymbolAddress((void**)&Sqs, g_Sqs);
    cudaGetSymbolAddress((void**)&Sks, g_Sks);
    cudaGetSymbolAddress((void**)&Svs, g_Svs);
    cudaGetSymbolAddress((void**)&Sqt, g_Sqt);
    cudaGetSymbolAddress((void**)&Skt, g_Skt);
    cudaGetSymbolAddress((void**)&Svt, g_Svt);
    cudaGetSymbolAddress((void**)&Sa,  g_Sa);
    cudaGetSymbolAddress((void**)&St,  g_St);
    cudaGetSymbolAddress((void**)&WT,  g_WT);
    cudaGetSymbolAddress((void**)&acnt, g_acnt);
    cudaGetSymbolAddress((void**)&bcnt, g_bcnt);

    cudaFuncSetAttribute(gemm_all<0>, cudaFuncAttributeMaxDynamicSharedMemorySize, GEMM_SMEM);
    cudaFuncSetAttribute(gemm_all<1>, cudaFuncAttributeMaxDynamicSharedMemorySize, GEMM_SMEM);

    cudaMemsetAsync(acnt, 0, sizeof(int) * T_ * B_ * C_, 0);
    cudaMemsetAsync(bcnt, 0, sizeof(int) * B_ * C_ * N_, 0);

    // Pre-transpose all 8 weight matrices into [c][o] layout
    transpose_w<<<dim3(C_/32, C_/32, 8), dim3(32, 8)>>>(Ws, Wt, WT);

    // All six front convs in one launch: grid z = conv*40 + slice
    dim3 gf(3, 3, 6 * SLICES);
    gemm_all<0><<<gf, 256, GEMM_SMEM>>>(x, y, WT, gs, bs, gt, bt,
                                        Sqs, Sks, Svs, Sqt, Skt, Svt,
                                        nullptr, nullptr, nullptr, nullptr);

    // Exact-integer attention + LIF (ballot/popc)
    attn_spatial <<<SLICES * H_, 256>>>(Sqs, Sks, Svs, Sa);
    attn_temporal<<<B_ * H_ * (N_ / 32), 256>>>(Sqt, Skt, Svt, St);

    // Both back convs in one launch: grid z = which*40 + slice
    dim3 gb(3, 3, 2 * SLICES);
    gemm_all<1><<<gb, 256, GEMM_SMEM>>>(x, y, WT, gs, bs, gt, bt,
                                        Sqs, Sks, Svs, Sqt, Skt, Svt,
                                        Sa, St, acnt, bcnt);

    // Rank-1 outer product
    finalize_kernel<<<(TEN + 255) / 256, 256>>>(acnt, bcnt, out);
}

// round 11
// speedup vs baseline: 2.3510x; 1.6128x over previous
#include <cuda_runtime.h>
#include <cuda_fp16.h>
#include <stdint.h>

// Problem constants
#define T_  10
#define B_  4
#define C_  384
#define N_  384
#define H_  12
#define D_  32
#define SLICES (T_*B_)                 // 40
#define TEN (T_*B_*C_*N_)              // 5,898,240
#define C2  (C_*C_)
#define CN  (C_*N_)

typedef unsigned int u32;

// Scratch (device globals — no allocations allowed)
__device__ __align__(16) float  g_Sqs[TEN];   // spatial q spikes [slice][c][n]
__device__ __align__(16) float  g_Sks[TEN];
__device__ __align__(16) float  g_Svs[TEN];
__device__ __align__(16) float  g_Sqt[TEN];   // temporal q spikes [slice][n][c]
__device__ __align__(16) float  g_Skt[TEN];
__device__ __align__(16) float  g_Svt[TEN];
__device__ __align__(16) __half g_Sab[TEN];   // spatial attn spikes fp16 [slice][n][c]
__device__ __align__(16) __half g_Stb[TEN];   // temporal attn spikes fp16 [t'][b][n][c']
__device__ __align__(16) __half g_Wh[8*2*C2];                  // [conv][split h/m][o][c]
__device__ __align__(16) __half g_Xh[(size_t)2*2*SLICES*CN];   // [src][split][slice][n][c]
__device__ int g_acnt[T_*B_*C_];
__device__ int g_bcnt[B_*C_*N_];

// ---------------------------------------------------------------------------
// helpers: cp.async, ldmatrix, mma.sync (all portable to compute_103)
// ---------------------------------------------------------------------------
__device__ __forceinline__ u32 smem_u32(const void* p) {
    u32 a;
    asm("{ .reg .u64 t; cvta.to.shared.u64 t, %1; cvt.u32.u64 %0, t; }" : "=r"(a) : "l"(p));
    return a;
}
__device__ __forceinline__ void cpa16(u32 saddr, const void* g) {
    asm volatile("cp.async.cg.shared.global [%0], [%1], 16;" :: "r"(saddr), "l"(g));
}
#define CPA_COMMIT() asm volatile("cp.async.commit_group;")
#define CPA_WAIT1()  asm volatile("cp.async.wait_group 1;")
#define CPA_WAIT0()  asm volatile("cp.async.wait_group 0;")

#define LDSM4(R, addr) \
    asm volatile("ldmatrix.sync.aligned.m8n8.x4.shared.b16 {%0,%1,%2,%3}, [%4];" \
                 : "=r"((R)[0]), "=r"((R)[1]), "=r"((R)[2]), "=r"((R)[3]) : "r"(addr))

#define MMA_16816(C4, A4, b0, b1) \
    asm volatile("mma.sync.aligned.m16n8k16.row.col.f32.f16.f16.f32 " \
                 "{%0,%1,%2,%3},{%4,%5,%6,%7},{%8,%9},{%0,%1,%2,%3};" \
                 : "+f"((C4)[0]), "+f"((C4)[1]), "+f"((C4)[2]), "+f"((C4)[3]) \
                 : "r"((A4)[0]), "r"((A4)[1]), "r"((A4)[2]), "r"((A4)[3]), \
                   "r"(b0), "r"(b1))

// ---------------------------------------------------------------------------
// prep_w: fp16 2-split of all 8 W matrices: [conv][split][o][c]
// ---------------------------------------------------------------------------
__global__ void prep_w(const float* __restrict__ Ws, const float* __restrict__ Wt,
                       __half* __restrict__ Wh)
{
    int i = blockIdx.x * 256 + threadIdx.x;
    if (i >= 8 * C2) return;
    int m = i / C2, r = i % C2;
    float w = (m < 4) ? Ws[i] : Wt[i - 4*C2];
    __half h = __float2half_rn(w);
    float rh = w - __half2float(h);
    __half md = __float2half_rn(rh);
    Wh[((size_t)m*2 + 0)*C2 + r] = h;
    Wh[((size_t)m*2 + 1)*C2 + r] = md;
}

// ---------------------------------------------------------------------------
// prep_x: transpose x,y slices [c][n] -> [n][c], fp16 2-split
// layout [src][split][slice][n][c]
// ---------------------------------------------------------------------------
__global__ void prep_x(const float* __restrict__ x, const float* __restrict__ y,
                       __half* __restrict__ Xh)
{
    __shared__ float t[32][33];
    const int z = blockIdx.z;
    const int src = z / SLICES, slice = z % SLICES;
    const float* X = (src ? y : x) + (size_t)slice * CN;
    const int n0 = blockIdx.x * 32, c0 = blockIdx.y * 32;
    const int tx = threadIdx.x, ty = threadIdx.y;
#pragma unroll
    for (int j = 0; j < 32; j += 8)
        t[ty + j][tx] = X[(size_t)(c0 + ty + j) * N_ + n0 + tx];
    __syncthreads();
    const size_t so = (size_t)SLICES * CN;
    const size_t ob = ((size_t)src * 2 * SLICES + slice) * CN;
#pragma unroll
    for (int j = 0; j < 32; j += 8) {
        float v = t[tx][ty + j];
        __half h = __float2half_rn(v);
        float rh = v - __half2float(h);
        __half md = __float2half_rn(rh);
        size_t a = ob + (size_t)(n0 + ty + j) * C_ + c0 + tx;
        Xh[a] = h; Xh[a + so] = md;
    }
}

// ---------------------------------------------------------------------------
// HMMA fp16-split GEMM.  Z[o][n] = sum_c W[o][c] X[c][n] (fp32 accum), affine,
// spike (z >= 2).  CTA 128x128, 8 warps (2M x 4N), warp tile 64x32.
// K chunks of 32 halves, double-buffered cp.async, padded rows (80B).
// PHASE 0 (front): combos (Ah,Bh)(Ah,Bm)(Am,Bh); tiles {Ah,Am,Bh,Bm}
// PHASE 1 (back):  combos (Ah,Bs)(Am,Bs);        tiles {Ah,Am,Bs}
// Modes: 0 spatial->float [c][n]; 1 temporal->float [n][c] (smem-staged);
//        2 spatial back -> acnt row counts; 3 temporal back -> bcnt counts.
// ---------------------------------------------------------------------------
#define ROWB   80                      // bytes per smem row: 32 halves + 8 pad
#define TILE_B (128*ROWB)              // 10240
#define SMEM_F (2*4*TILE_B)            // 81920
#define SMEM_K (2*3*TILE_B)            // 61440

template<int PHASE>
__global__ void __launch_bounds__(256)
hmma_gemm(const __half* __restrict__ Wh, const __half* __restrict__ Xh,
          const __half* __restrict__ Sab, const __half* __restrict__ Stb,
          const float* __restrict__ gs, const float* __restrict__ bs,
          const float* __restrict__ gt, const float* __restrict__ bt,
          float* __restrict__ Sqs, float* __restrict__ Sks, float* __restrict__ Svs,
          float* __restrict__ Sqt, float* __restrict__ Skt, float* __restrict__ Svt,
          int* __restrict__ acnt, int* __restrict__ bcnt)
{
    extern __shared__ char smem[];
    __shared__ int rcnt[128];
    const u32 smb = smem_u32(smem);
    const int tid = threadIdx.x;
    const int wid = tid >> 5, lane = tid & 31;
    const int g = lane >> 2, t4 = lane & 3;
    const int wm = wid & 1, wn = wid >> 1;       // warp grid 2(M) x 4(N)
    const int m0 = wm * 64, n0w = wn * 32;

    const int z = blockIdx.z;
    const int sel = z / SLICES;
    const int slice = z % SLICES;

    const float *Gp, *Bp;
    float* O = nullptr;
    int widx, mode;
    const __half *Bh_g, *Bm_g;
    if (PHASE == 0) {
        if (sel < 3) { widx = sel;     Gp = gs + sel*C_;     Bp = bs + sel*C_;     mode = 0; }
        else         { widx = sel + 1; Gp = gt + (sel-3)*C_; Bp = bt + (sel-3)*C_; mode = 1; }
        const int src = (sel == 0 || sel == 3) ? 0 : 1;
        Bh_g = Xh + ((size_t)(src*2 + 0) * SLICES + slice) * CN;
        Bm_g = Xh + ((size_t)(src*2 + 1) * SLICES + slice) * CN;
        if      (sel == 0) O = Sqs; else if (sel == 1) O = Sks; else if (sel == 2) O = Svs;
        else if (sel == 3) O = Sqt; else if (sel == 4) O = Skt; else               O = Svt;
        O += (size_t)slice * CN;
    } else {
        if (sel == 0) { widx = 3; Gp = gs + 3*C_; Bp = bs + 3*C_; mode = 2; }
        else          { widx = 7; Gp = gt + 3*C_; Bp = bt + 3*C_; mode = 3; }
        Bh_g = (sel ? Stb : Sab) + (size_t)slice * CN;
        Bm_g = Bh_g;
    }
    const __half* Ah_g = Wh + (size_t)(widx*2 + 0) * C2;
    const __half* Am_g = Wh + (size_t)(widx*2 + 1) * C2;

    const int oT = blockIdx.y * 128;
    const int nT = blockIdx.x * 128;
    constexpr int NTILE = (PHASE == 0) ? 4 : 3;
    constexpr u32 STAGE = NTILE * TILE_B;

    if (tid < 128) rcnt[tid] = 0;

    const __half* tp[4];
    tp[0] = Ah_g; tp[1] = Am_g; tp[2] = Bh_g; tp[3] = (PHASE == 0) ? Bm_g : Bh_g;

    auto issue = [&](int kb) {
        const int k0 = kb * 32;
        const u32 sb = smb + (u32)(kb & 1) * STAGE;
#pragma unroll
        for (int it = 0; it < 2*NTILE; it++) {
            int id = tid + 256 * it;
            int tile = id >> 9, rem = id & 511, row = rem >> 2, ch = rem & 3;
            int rbase = (tile < 2) ? oT : nT;
            const __half* gp = tp[tile] + (size_t)(rbase + row) * C_ + k0 + ch*8;
            cpa16(sb + (u32)tile * TILE_B + (u32)(row * ROWB + ch * 16), gp);
        }
        CPA_COMMIT();
    };

    float acc[4][4][4];
#pragma unroll
    for (int mi = 0; mi < 4; mi++)
#pragma unroll
        for (int ni = 0; ni < 4; ni++)
#pragma unroll
            for (int e = 0; e < 4; e++) acc[mi][ni][e] = 0.f;

    // per-thread ldmatrix offsets (bytes)
    const u32 aoff = (u32)((lane & 15) * ROWB + (lane >> 4) * 16);
    const u32 boff = (u32)(((lane & 7) + 8 * (lane >> 4)) * ROWB + ((lane >> 3) & 1) * 16);

    issue(0);
#pragma unroll 1
    for (int kb = 0; kb < 12; kb++) {
        if (kb + 1 < 12) { issue(kb + 1); CPA_WAIT1(); }
        else             { CPA_WAIT0(); }
        __syncthreads();
        const u32 stg = smb + (u32)(kb & 1) * STAGE;
#pragma unroll
        for (int ks = 0; ks < 2; ks++) {
            const u32 kof = (u32)(ks * 32);
            u32 aH[4][4], aM[4][4], bH[2][4], bM[2][4];
#pragma unroll
            for (int mi = 0; mi < 4; mi++)
                LDSM4(aH[mi], stg + 0*TILE_B + aoff + (u32)((m0 + mi*16) * ROWB) + kof);
#pragma unroll
            for (int mi = 0; mi < 4; mi++)
                LDSM4(aM[mi], stg + 1*TILE_B + aoff + (u32)((m0 + mi*16) * ROWB) + kof);
#pragma unroll
            for (int p = 0; p < 2; p++)
                LDSM4(bH[p], stg + 2*TILE_B + boff + (u32)((n0w + p*16) * ROWB) + kof);
            if (PHASE == 0) {
#pragma unroll
                for (int p = 0; p < 2; p++)
                    LDSM4(bM[p], stg + 3*TILE_B + boff + (u32)((n0w + p*16) * ROWB) + kof);
            }
#pragma unroll
            for (int mi = 0; mi < 4; mi++)
#pragma unroll
                for (int ni = 0; ni < 4; ni++) {
                    const int p = ni >> 1, q = 2 * (ni & 1);
                    MMA_16816(acc[mi][ni], aH[mi], bH[p][q], bH[p][q+1]);
                    MMA_16816(acc[mi][ni], aM[mi], bH[p][q], bH[p][q+1]);
                    if (PHASE == 0)
                        MMA_16816(acc[mi][ni], aH[mi], bM[p][q], bM[p][q+1]);
                }
        }
        __syncthreads();
    }

    // ---------------- epilogue: affine + threshold ----------------
    float gvv[4][2], svv[4][2];
#pragma unroll
    for (int mi = 0; mi < 4; mi++)
#pragma unroll
        for (int h = 0; h < 2; h++) {
            int r = oT + m0 + mi*16 + h*8 + g;
            gvv[mi][h] = Gp[r]; svv[mi][h] = Bp[r];
        }
    auto sp = [](float c, float gg, float ss) {
        return (__fadd_rn(__fmul_rn(c, gg), ss) >= 2.0f) ? 1.f : 0.f;
    };
    const int bb2 = slice & (B_ - 1);

    if (PHASE == 0 && mode == 0) {          // spatial: float [c][n]
#pragma unroll
        for (int mi = 0; mi < 4; mi++)
#pragma unroll
            for (int ni = 0; ni < 4; ni++) {
                int r0 = oT + m0 + mi*16 + g;
                int col = nT + n0w + ni*8 + 2*t4;
                float2 v0 = make_float2(sp(acc[mi][ni][0], gvv[mi][0], svv[mi][0]),
                                        sp(acc[mi][ni][1], gvv[mi][0], svv[mi][0]));
                float2 v1 = make_float2(sp(acc[mi][ni][2], gvv[mi][1], svv[mi][1]),
                                        sp(acc[mi][ni][3], gvv[mi][1], svv[mi][1]));
                *(float2*)&O[(size_t)r0       * N_ + col] = v0;
                *(float2*)&O[(size_t)(r0 + 8) * N_ + col] = v1;
            }
    } else if (PHASE == 0) {                // temporal: float [n][c], smem-staged
        float* buf = (float*)smem;
        const int wbase = wid * 2176;       // 32 n x 68 c (padded)
#pragma unroll
        for (int mi = 0; mi < 4; mi++)
#pragma unroll
            for (int ni = 0; ni < 4; ni++) {
                int cl = mi*16 + g, nl = ni*8 + 2*t4;
                buf[wbase + nl*68 + cl]         = sp(acc[mi][ni][0], gvv[mi][0], svv[mi][0]);
                buf[wbase + (nl+1)*68 + cl]     = sp(acc[mi][ni][1], gvv[mi][0], svv[mi][0]);
                buf[wbase + nl*68 + cl + 8]     = sp(acc[mi][ni][2], gvv[mi][1], svv[mi][1]);
                buf[wbase + (nl+1)*68 + cl + 8] = sp(acc[mi][ni][3], gvv[mi][1], svv[mi][1]);
            }
        __syncthreads();
        const int cl4 = (tid & 31) * 4;
        const int nr0 = tid >> 5;
#pragma unroll
        for (int i = 0; i < 16; i++) {
            int nn = nr0 + i*8;
            int srcw = ((nn >> 5) << 1) + (cl4 >> 6);
            float4 v = *(float4*)&buf[srcw*2176 + (nn & 31)*68 + (cl4 & 63)];
            *(float4*)&O[(size_t)(nT + nn) * C_ + oT + cl4] = v;
        }
    } else if (mode == 2) {                 // spatial back: row spike counts
        __syncthreads();
#pragma unroll
        for (int mi = 0; mi < 4; mi++) {
            int c0 = 0, c1 = 0;
#pragma unroll
            for (int ni = 0; ni < 4; ni++) {
                c0 += (int)sp(acc[mi][ni][0], gvv[mi][0], svv[mi][0])
                    + (int)sp(acc[mi][ni][1], gvv[mi][0], svv[mi][0]);
                c1 += (int)sp(acc[mi][ni][2], gvv[mi][1], svv[mi][1])
                    + (int)sp(acc[mi][ni][3], gvv[mi][1], svv[mi][1]);
            }
            if (c0) atomicAdd(&rcnt[m0 + mi*16 + g], c0);
            if (c1) atomicAdd(&rcnt[m0 + mi*16 + 8 + g], c1);
        }
        __syncthreads();
        if (tid < 128) {
            int v = rcnt[tid];
            if (v) atomicAdd(&acnt[slice * C_ + oT + tid], v);
        }
    } else {                                // temporal back: per-(b,c,n) counts
#pragma unroll
        for (int mi = 0; mi < 4; mi++)
#pragma unroll
            for (int ni = 0; ni < 4; ni++) {
                int r0 = oT + m0 + mi*16 + g;
                int col = nT + n0w + ni*8 + 2*t4;
                if (sp(acc[mi][ni][0], gvv[mi][0], svv[mi][0]) != 0.f)
                    atomicAdd(&bcnt[(size_t)(bb2*C_ + r0)*N_ + col], 1);
                if (sp(acc[mi][ni][1], gvv[mi][0], svv[mi][0]) != 0.f)
                    atomicAdd(&bcnt[(size_t)(bb2*C_ + r0)*N_ + col + 1], 1);
                if (sp(acc[mi][ni][2], gvv[mi][1], svv[mi][1]) != 0.f)
                    atomicAdd(&bcnt[(size_t)(bb2*C_ + r0 + 8)*N_ + col], 1);
                if (sp(acc[mi][ni][3], gvv[mi][1], svv[mi][1]) != 0.f)
                    atomicAdd(&bcnt[(size_t)(bb2*C_ + r0 + 8)*N_ + col + 1], 1);
            }
    }
}

// ---------------------------------------------------------------------------
// Spatial attention — exact integer via bit-packing + popc.  Output fp16 [n][c].
// ---------------------------------------------------------------------------
__global__ void __launch_bounds__(256)
attn_spatial(const float* __restrict__ Q, const float* __restrict__ K,
             const float* __restrict__ V, __half* __restrict__ Sab)
{
    __shared__ u32 Qb[32][12], Kb[32][12], Vb[32][12];
    __shared__ int Ms[32][33];

    const int blk = blockIdx.x;            // (t*B+b)*H + h
    const int h   = blk % H_;
    const int tb  = blk / H_;
    const size_t base = (size_t)tb * CN + (size_t)h * D_ * N_;
    const int tid = threadIdx.x;
    const int wid = tid >> 5, lane = tid & 31;

#pragma unroll
    for (int i = 0; i < 4; i++) {
        const int d = wid*4 + i;
        const float* qr = Q + base + (size_t)d * N_;
        const float* kr = K + base + (size_t)d * N_;
        const float* vr = V + base + (size_t)d * N_;
#pragma unroll
        for (int w = 0; w < 12; w++) {
            u32 qm = __ballot_sync(0xffffffffu, qr[w*32 + lane] != 0.f);
            u32 km = __ballot_sync(0xffffffffu, kr[w*32 + lane] != 0.f);
            u32 vm = __ballot_sync(0xffffffffu, vr[w*32 + lane] != 0.f);
            if (lane == 0) { Qb[d][w] = qm; Kb[d][w] = km; Vb[d][w] = vm; }
        }
    }
    __syncthreads();

    {
        const int d1  = tid >> 3;
        const int d2b = (tid & 7) * 4;
#pragma unroll
        for (int j = 0; j < 4; j++) {
            int s = 0;
#pragma unroll
            for (int w = 0; w < 12; w++) s += __popc(Kb[d1][w] & Vb[d2b + j][w]);
            Ms[d1][d2b + j] = s;
        }
    }
    __syncthreads();

    const __half ONE = __float2half(1.f), ZERO = __float2half(0.f);
    __half* ob = Sab + (size_t)tb * CN;   // [n][c]
#pragma unroll
    for (int gg = 0; gg < 6; gg++) {
        const int nb = wid*48 + gg*8;
        const int w  = nb >> 5, sh = nb & 31;
        int o[8];
#pragma unroll
        for (int j = 0; j < 8; j++) o[j] = 0;
#pragma unroll 4
        for (int d1 = 0; d1 < 32; d1++) {
            const int m = Ms[d1][lane];
            const u32 bits = (Qb[d1][w] >> sh) & 0xffu;
#pragma unroll
            for (int j = 0; j < 8; j++)
                if (bits & (1u << j)) o[j] += m;
        }
#pragma unroll
        for (int j = 0; j < 8; j++)
            ob[(size_t)(nb + j) * C_ + h*D_ + lane] = (o[j] >= 8) ? ONE : ZERO;
    }
}

// ---------------------------------------------------------------------------
// Temporal attention — ballot + popc.  Output fp16 at torch-reshape position,
// transposed: St[t'][b][n][c'],  idx=10h+t; t'=idx/12; c'=(idx%12)*32+lane
// ---------------------------------------------------------------------------
__global__ void __launch_bounds__(256)
attn_temporal(const float* __restrict__ Q, const float* __restrict__ K,
              const float* __restrict__ V, __half* __restrict__ Stb)
{
    const int blk = blockIdx.x;            // b*H*(N/32) + h*(N/32) + nc
    const int nc  = blk % (N_ / 32);
    const int h   = (blk / (N_ / 32)) % H_;
    const int b   = blk / ((N_ / 32) * H_);
    const int wid = threadIdx.x >> 5, lane = threadIdx.x & 31;
    const int n0  = nc * 32 + wid * 4;

    const __half ONE = __float2half(1.f), ZERO = __float2half(0.f);
    u32 spk[10];
#pragma unroll
    for (int t = 0; t < 10; t++) spk[t] = 0;

#pragma unroll
    for (int ni = 0; ni < 4; ni++) {
        const int n = n0 + ni;
        u32 qb[10], kb[10], vloc = 0;
#pragma unroll
        for (int t = 0; t < 10; t++) {
            size_t a = ((size_t)(t * B_ + b) * N_ + n) * C_ + h * D_ + lane;
            qb[t] = __ballot_sync(0xffffffffu, Q[a] != 0.f);
            kb[t] = __ballot_sync(0xffffffffu, K[a] != 0.f);
            vloc |= (V[a] != 0.f) ? (1u << t) : 0u;
        }
#pragma unroll
        for (int t = 0; t < 10; t++) {
            int o = 0;
#pragma unroll
            for (int s = 0; s < 10; s++)
                if (vloc & (1u << s)) o += __popc(qb[t] & kb[s]);
            if (o >= 8) spk[t] |= 1u << ni;
        }
    }

#pragma unroll
    for (int t = 0; t < 10; t++) {
        const int idx = 10 * h + t;
        const int tn = idx / 12, wn = idx % 12;
        const size_t a0 = (((size_t)tn * B_ + b) * N_ + n0) * C_ + wn * 32 + lane;
#pragma unroll
        for (int ni = 0; ni < 4; ni++)
            Stb[a0 + (size_t)ni * C_] = (spk[t] & (1u << ni)) ? ONE : ZERO;
    }
}

// out[t,b,c,n] = (acnt[t,b,c]/384) * (bcnt[b,c,n]/10)
__global__ void finalize_kernel(const int* __restrict__ acnt,
                                const int* __restrict__ bcnt,
                                float* __restrict__ out)
{
    int i = blockIdx.x * 256 + threadIdx.x;
    if (i >= TEN) return;
    int n  = i % N_;
    int c  = (i / N_) % C_;
    int bb = (i / (N_ * C_)) % B_;
    int t  = i / (N_ * C_ * B_);
    float a  = (float)acnt[(t * B_ + bb) * C_ + c] / 384.0f;
    float bt = (float)bcnt[(bb * C_ + c) * N_ + n] / 10.0f;
    out[i] = a * bt;
}

extern "C" void kernel_launch(void* const* d_in, const int* in_sizes, int n_in,
                              void* d_out, int out_size)
{
    (void)in_sizes; (void)n_in; (void)out_size;
    const float* x  = (const float*)d_in[0];
    const float* y  = (const float*)d_in[1];
    const float* Ws = (const float*)d_in[2];
    const float* gs = (const float*)d_in[3];
    const float* bs = (const float*)d_in[4];
    const float* Wt = (const float*)d_in[5];
    const float* gt = (const float*)d_in[6];
    const float* bt = (const float*)d_in[7];
    float* out = (float*)d_out;

    float *Sqs, *Sks, *Svs, *Sqt, *Skt, *Svt;
    __half *Sab, *Stb, *Wh, *Xh;
    int *acnt, *bcnt;
    cudaGetSymbolAddress((void**)&Sqs, g_Sqs);
    cudaGetSymbolAddress((void**)&Sks, g_Sks);
    cudaGetSymbolAddress((void**)&Svs, g_Svs);
    cudaGetSymbolAddress((void**)&Sqt, g_Sqt);
    cudaGetSymbolAddress((void**)&Skt, g_Skt);
    cudaGetSymbolAddress((void**)&Svt, g_Svt);
    cudaGetSymbolAddress((void**)&Sab, g_Sab);
    cudaGetSymbolAddress((void**)&Stb, g_Stb);
    cudaGetSymbolAddress((void**)&Wh,  g_Wh);
    cudaGetSymbolAddress((void**)&Xh,  g_Xh);
    cudaGetSymbolAddress((void**)&acnt, g_acnt);
    cudaGetSymbolAddress((void**)&bcnt, g_bcnt);

    cudaFuncSetAttribute(hmma_gemm<0>, cudaFuncAttributeMaxDynamicSharedMemorySize, SMEM_F);
    cudaFuncSetAttribute(hmma_gemm<1>, cudaFuncAttributeMaxDynamicSharedMemorySize, SMEM_K);

    cudaMemsetAsync(acnt, 0, sizeof(int) * T_ * B_ * C_, 0);
    cudaMemsetAsync(bcnt, 0, sizeof(int) * B_ * C_ * N_, 0);

    // Prepasses: W fp16 2-split; X transpose + fp16 2-split
    prep_w<<<(8*C2 + 255)/256, 256>>>(Ws, Wt, Wh);
    prep_x<<<dim3(N_/32, C_/32, 2*SLICES), dim3(32, 8)>>>(x, y, Xh);

    // Six front convs on tensor cores (HMMA): grid z = conv*40 + slice
    hmma_gemm<0><<<dim3(3, 3, 6*SLICES), 256, SMEM_F>>>(
        Wh, Xh, Sab, Stb, gs, bs, gt, bt,
        Sqs, Sks, Svs, Sqt, Skt, Svt, acnt, bcnt);

    // Exact-integer attention + LIF (ballot/popc) -> fp16 [n][c] outputs
    attn_spatial <<<SLICES * H_, 256>>>(Sqs, Sks, Svs, Sab);
    attn_temporal<<<B_ * H_ * (N_ / 32), 256>>>(Sqt, Skt, Svt, Stb);

    // Two back convs on tensor cores: grid z = which*40 + slice
    hmma_gemm<1><<<dim3(3, 3, 2*SLICES), 256, SMEM_K>>>(
        Wh, Xh, Sab, Stb, gs, bs, gt, bt,
        Sqs, Sks, Svs, Sqt, Skt, Svt, acnt, bcnt);

    // Rank-1 outer product
    finalize_kernel<<<(TEN + 255)/256, 256>>>(acnt, bcnt, out);
}

// round 13
// speedup vs baseline: 2.5178x; 1.0709x over previous
#include <cuda_runtime.h>
#include <cuda_fp16.h>
#include <stdint.h>

// Problem constants
#define T_  10
#define B_  4
#define C_  384
#define N_  384
#define H_  12
#define D_  32
#define SLICES (T_*B_)                 // 40
#define TEN (T_*B_*C_*N_)              // 5,898,240
#define C2  (C_*C_)
#define CN  (C_*N_)

typedef unsigned int u32;

// Scratch (device globals — no allocations allowed)
__device__ __align__(16) u32 g_Pqs[SLICES*C_*12];   // spatial q spikes, bits over n: [slice][c][12]
__device__ __align__(16) u32 g_Pks[SLICES*C_*12];
__device__ __align__(16) u32 g_Pvs[SLICES*C_*12];
__device__ __align__(16) u32 g_Pqt[SLICES*N_*12];   // temporal q spikes, bits over c: [slice][n][12]
__device__ __align__(16) u32 g_Pkt[SLICES*N_*12];
__device__ __align__(16) u32 g_Pvt[SLICES*N_*12];
__device__ __align__(16) __half g_Sab[TEN];   // spatial attn spikes fp16 [slice][n][c]
__device__ __align__(16) __half g_Stb[TEN];   // temporal attn spikes fp16 [t'][b][n][c']
__device__ __align__(16) __half g_Wh[8*2*C2];                  // [conv][split h/m][o][c]
__device__ __align__(16) __half g_Xh[(size_t)2*2*SLICES*CN];   // [src][split][slice][n][c]
__device__ int g_acnt[T_*B_*C_];
__device__ int g_bcnt[B_*C_*N_];

// ---------------------------------------------------------------------------
// helpers: cp.async, ldmatrix, mma.sync (portable to compute_103)
// ---------------------------------------------------------------------------
__device__ __forceinline__ u32 smem_u32(const void* p) {
    u32 a;
    asm("{ .reg .u64 t; cvta.to.shared.u64 t, %1; cvt.u32.u64 %0, t; }" : "=r"(a) : "l"(p));
    return a;
}
__device__ __forceinline__ void cpa16(u32 saddr, const void* g) {
    asm volatile("cp.async.cg.shared.global [%0], [%1], 16;" :: "r"(saddr), "l"(g));
}
#define CPA_COMMIT() asm volatile("cp.async.commit_group;")
#define CPA_WAIT1()  asm volatile("cp.async.wait_group 1;")
#define CPA_WAIT0()  asm volatile("cp.async.wait_group 0;")

#define LDSM4(R, addr) \
    asm volatile("ldmatrix.sync.aligned.m8n8.x4.shared.b16 {%0,%1,%2,%3}, [%4];" \
                 : "=r"((R)[0]), "=r"((R)[1]), "=r"((R)[2]), "=r"((R)[3]) : "r"(addr))

#define MMA_16816(C4, A4, b0, b1) \
    asm volatile("mma.sync.aligned.m16n8k16.row.col.f32.f16.f16.f32 " \
                 "{%0,%1,%2,%3},{%4,%5,%6,%7},{%8,%9},{%0,%1,%2,%3};" \
                 : "+f"((C4)[0]), "+f"((C4)[1]), "+f"((C4)[2]), "+f"((C4)[3]) \
                 : "r"((A4)[0]), "r"((A4)[1]), "r"((A4)[2]), "r"((A4)[3]), \
                   "r"(b0), "r"(b1))

// ---------------------------------------------------------------------------
// prep_w: fp16 2-split of all 8 W matrices: [conv][split][o][c]
// ---------------------------------------------------------------------------
__global__ void prep_w(const float* __restrict__ Ws, const float* __restrict__ Wt,
                       __half* __restrict__ Wh)
{
    int i = blockIdx.x * 256 + threadIdx.x;
    if (i >= 8 * C2) return;
    int m = i / C2, r = i % C2;
    float w = (m < 4) ? Ws[i] : Wt[i - 4*C2];
    __half h = __float2half_rn(w);
    float rh = w - __half2float(h);
    __half md = __float2half_rn(rh);
    Wh[((size_t)m*2 + 0)*C2 + r] = h;
    Wh[((size_t)m*2 + 1)*C2 + r] = md;
}

// ---------------------------------------------------------------------------
// prep_x: transpose x,y slices [c][n] -> [n][c], fp16 2-split
// ---------------------------------------------------------------------------
__global__ void prep_x(const float* __restrict__ x, const float* __restrict__ y,
                       __half* __restrict__ Xh)
{
    __shared__ float t[32][33];
    const int z = blockIdx.z;
    const int src = z / SLICES, slice = z % SLICES;
    const float* X = (src ? y : x) + (size_t)slice * CN;
    const int n0 = blockIdx.x * 32, c0 = blockIdx.y * 32;
    const int tx = threadIdx.x, ty = threadIdx.y;
#pragma unroll
    for (int j = 0; j < 32; j += 8)
        t[ty + j][tx] = X[(size_t)(c0 + ty + j) * N_ + n0 + tx];
    __syncthreads();
    const size_t so = (size_t)SLICES * CN;
    const size_t ob = ((size_t)src * 2 * SLICES + slice) * CN;
#pragma unroll
    for (int j = 0; j < 32; j += 8) {
        float v = t[tx][ty + j];
        __half h = __float2half_rn(v);
        float rh = v - __half2float(h);
        __half md = __float2half_rn(rh);
        size_t a = ob + (size_t)(n0 + ty + j) * C_ + c0 + tx;
        Xh[a] = h; Xh[a + so] = md;
    }
}

// probe no-op: aligns ncu's -s 5 -c 1 capture onto hmma_gemm<0>
__global__ void probe_pad() {}

// ---------------------------------------------------------------------------
// HMMA fp16-split GEMM.  Z[o][n] = sum_c W[o][c] X[c][n] (f32 accum), affine,
// spike (z >= 2).  CTA 128x128, 16 warps (4M x 4N), warp tile 32x32.
// K chunks of 32 halves, double-buffered cp.async, padded rows (80B).
// PHASE 0 (front): combos (Ah,Bh)(Am,Bh)(Ah,Bm); tiles {Ah,Am,Bh,Bm}
//   mode 0 spatial  -> packed u32 bits-over-n  [slice][c][12]
//   mode 1 temporal -> packed u32 bits-over-c  [slice][n][12]
// PHASE 1 (back): B = attn spikes fp16 (exact), combos (Ah,Bs)(Am,Bs); tiles {Ah,Am,Bs}
//   mode 2 spatial back  -> acnt row counts
//   mode 3 temporal back -> bcnt per-(b,c,n) counts
// ---------------------------------------------------------------------------
#define ROWB   80                      // bytes per smem row: 32 halves + 8 pad
#define TILE_B (128*ROWB)              // 10240
#define SMEM_F (2*4*TILE_B)            // 81920
#define SMEM_K (2*3*TILE_B)            // 61440

template<int PHASE>
__global__ void __launch_bounds__(512, 1)
hmma_gemm(const __half* __restrict__ Wh, const __half* __restrict__ Xh,
          const __half* __restrict__ Sab, const __half* __restrict__ Stb,
          const float* __restrict__ gs, const float* __restrict__ bs,
          const float* __restrict__ gt, const float* __restrict__ bt,
          u32* __restrict__ Pqs, u32* __restrict__ Pks, u32* __restrict__ Pvs,
          u32* __restrict__ Pqt, u32* __restrict__ Pkt, u32* __restrict__ Pvt,
          int* __restrict__ acnt, int* __restrict__ bcnt)
{
    extern __shared__ char smem[];
    __shared__ int rcnt[128];
    const u32 smb = smem_u32(smem);
    const int tid = threadIdx.x;
    const int wid = tid >> 5, lane = tid & 31;
    const int g = lane >> 2, t4 = lane & 3;
    const int wm = wid & 3, wn = wid >> 2;       // warp grid 4(M) x 4(N)
    const int m0 = wm * 32, n0w = wn * 32;

    const int z = blockIdx.z;
    const int sel = z / SLICES;
    const int slice = z % SLICES;

    const float *Gp, *Bp;
    u32* Po = nullptr;
    int widx, mode;
    const __half *Bh_g, *Bm_g;
    if (PHASE == 0) {
        if (sel < 3) { widx = sel;     Gp = gs + sel*C_;     Bp = bs + sel*C_;     mode = 0; }
        else         { widx = sel + 1; Gp = gt + (sel-3)*C_; Bp = bt + (sel-3)*C_; mode = 1; }
        const int src = (sel == 0 || sel == 3) ? 0 : 1;
        Bh_g = Xh + ((size_t)(src*2 + 0) * SLICES + slice) * CN;
        Bm_g = Xh + ((size_t)(src*2 + 1) * SLICES + slice) * CN;
        if      (sel == 0) Po = Pqs; else if (sel == 1) Po = Pks; else if (sel == 2) Po = Pvs;
        else if (sel == 3) Po = Pqt; else if (sel == 4) Po = Pkt; else               Po = Pvt;
        Po += (size_t)slice * ((mode == 0) ? C_ : N_) * 12;
    } else {
        if (sel == 0) { widx = 3; Gp = gs + 3*C_; Bp = bs + 3*C_; mode = 2; }
        else          { widx = 7; Gp = gt + 3*C_; Bp = bt + 3*C_; mode = 3; }
        Bh_g = (sel ? Stb : Sab) + (size_t)slice * CN;
        Bm_g = Bh_g;
    }
    const __half* Ah_g = Wh + (size_t)(widx*2 + 0) * C2;
    const __half* Am_g = Wh + (size_t)(widx*2 + 1) * C2;

    const int oT = blockIdx.y * 128;
    const int nT = blockIdx.x * 128;
    constexpr int NTILE = (PHASE == 0) ? 4 : 3;
    constexpr u32 STAGE = NTILE * TILE_B;

    if (tid < 128) rcnt[tid] = 0;

    const __half* tp[4];
    tp[0] = Ah_g; tp[1] = Am_g; tp[2] = Bh_g; tp[3] = (PHASE == 0) ? Bm_g : Bh_g;

    auto issue = [&](int kb) {
        const int k0 = kb * 32;
        const u32 sb = smb + (u32)(kb & 1) * STAGE;
        const int row = tid >> 2, ch = tid & 3;
#pragma unroll
        for (int it = 0; it < NTILE; it++) {
            int rbase = (it < 2) ? oT : nT;
            const __half* gp = tp[it] + (size_t)(rbase + row) * C_ + k0 + ch*8;
            cpa16(sb + (u32)it * TILE_B + (u32)(row * ROWB + ch * 16), gp);
        }
        CPA_COMMIT();
    };

    float acc[2][4][4];
#pragma unroll
    for (int mi = 0; mi < 2; mi++)
#pragma unroll
        for (int ni = 0; ni < 4; ni++)
#pragma unroll
            for (int e = 0; e < 4; e++) acc[mi][ni][e] = 0.f;

    // per-thread ldmatrix offsets (bytes)
    const u32 aoff = (u32)((lane & 15) * ROWB + (lane >> 4) * 16);
    const u32 boff = (u32)(((lane & 7) + 8 * (lane >> 4)) * ROWB + ((lane >> 3) & 1) * 16);

    issue(0);
#pragma unroll 1
    for (int kb = 0; kb < 12; kb++) {
        if (kb + 1 < 12) { issue(kb + 1); CPA_WAIT1(); }
        else             { CPA_WAIT0(); }
        __syncthreads();
        const u32 stg = smb + (u32)(kb & 1) * STAGE;
#pragma unroll
        for (int ks = 0; ks < 2; ks++) {
            const u32 kof = (u32)(ks * 32);
            u32 aH[2][4], aM[2][4], bH[2][4], bM[2][4];
#pragma unroll
            for (int mi = 0; mi < 2; mi++)
                LDSM4(aH[mi], stg + 0*TILE_B + aoff + (u32)((m0 + mi*16) * ROWB) + kof);
#pragma unroll
            for (int mi = 0; mi < 2; mi++)
                LDSM4(aM[mi], stg + 1*TILE_B + aoff + (u32)((m0 + mi*16) * ROWB) + kof);
#pragma unroll
            for (int p = 0; p < 2; p++)
                LDSM4(bH[p], stg + 2*TILE_B + boff + (u32)((n0w + p*16) * ROWB) + kof);
            if (PHASE == 0) {
#pragma unroll
                for (int p = 0; p < 2; p++)
                    LDSM4(bM[p], stg + 3*TILE_B + boff + (u32)((n0w + p*16) * ROWB) + kof);
            }
#pragma unroll
            for (int mi = 0; mi < 2; mi++)
#pragma unroll
                for (int ni = 0; ni < 4; ni++) {
                    const int p = ni >> 1, q = 2 * (ni & 1);
                    MMA_16816(acc[mi][ni], aH[mi], bH[p][q], bH[p][q+1]);
                    MMA_16816(acc[mi][ni], aM[mi], bH[p][q], bH[p][q+1]);
                    if (PHASE == 0)
                        MMA_16816(acc[mi][ni], aH[mi], bM[p][q], bM[p][q+1]);
                }
        }
        __syncthreads();
    }

    // ---------------- epilogue: affine + threshold ----------------
    float gvv[2][2], svv[2][2];
#pragma unroll
    for (int mi = 0; mi < 2; mi++)
#pragma unroll
        for (int h = 0; h < 2; h++) {
            int r = oT + m0 + mi*16 + h*8 + g;
            gvv[mi][h] = Gp[r]; svv[mi][h] = Bp[r];
        }
    auto sp = [](float c, float gg, float ss) {
        return (__fadd_rn(__fmul_rn(c, gg), ss) >= 2.0f) ? 1.f : 0.f;
    };
    const int bb2 = slice & (B_ - 1);

    if (PHASE == 0 && mode == 0) {          // spatial: pack bits over n
        const int wq = blockIdx.x * 4 + wn;
#pragma unroll
        for (int mi = 0; mi < 2; mi++)
#pragma unroll
            for (int h = 0; h < 2; h++) {
                u32 wv = 0;
#pragma unroll
                for (int ni = 0; ni < 4; ni++)
#pragma unroll
                    for (int e = 0; e < 2; e++)
                        if (sp(acc[mi][ni][2*h+e], gvv[mi][h], svv[mi][h]) != 0.f)
                            wv |= 1u << (ni*8 + 2*t4 + e);
                wv |= __shfl_xor_sync(0xffffffffu, wv, 1);
                wv |= __shfl_xor_sync(0xffffffffu, wv, 2);
                if (t4 == 0)
                    Po[(size_t)(oT + m0 + mi*16 + 8*h + g) * 12 + wq] = wv;
            }
    } else if (PHASE == 0) {                // temporal: pack bits over c
        const int wqm = blockIdx.y * 4 + wm;
#pragma unroll
        for (int ni = 0; ni < 4; ni++)
#pragma unroll
            for (int e = 0; e < 2; e++) {
                u32 wv = 0;
#pragma unroll
                for (int mi = 0; mi < 2; mi++)
#pragma unroll
                    for (int h = 0; h < 2; h++)
                        if (sp(acc[mi][ni][2*h+e], gvv[mi][h], svv[mi][h]) != 0.f)
                            wv |= 1u << (mi*16 + 8*h + g);
                wv |= __shfl_xor_sync(0xffffffffu, wv, 4);
                wv |= __shfl_xor_sync(0xffffffffu, wv, 8);
                wv |= __shfl_xor_sync(0xffffffffu, wv, 16);
                if (lane < 4) {             // g==0, lane==t4
                    int n = nT + n0w + ni*8 + 2*t4 + e;
                    Po[(size_t)n * 12 + wqm] = wv;
                }
            }
    } else if (mode == 2) {                 // spatial back: row spike counts
        __syncthreads();
#pragma unroll
        for (int mi = 0; mi < 2; mi++)
#pragma unroll
            for (int h = 0; h < 2; h++) {
                int c = 0;
#pragma unroll
                for (int ni = 0; ni < 4; ni++)
#pragma unroll
                    for (int e = 0; e < 2; e++)
                        c += (int)sp(acc[mi][ni][2*h+e], gvv[mi][h], svv[mi][h]);
                if (c) atomicAdd(&rcnt[m0 + mi*16 + 8*h + g], c);
            }
        __syncthreads();
        if (tid < 128) {
            int v = rcnt[tid];
            if (v) atomicAdd(&acnt[slice * C_ + oT + tid], v);
        }
    } else {                                // temporal back: per-(b,c,n) counts
#pragma unroll
        for (int mi = 0; mi < 2; mi++)
#pragma unroll
            for (int h = 0; h < 2; h++) {
                int r = oT + m0 + mi*16 + 8*h + g;
#pragma unroll
                for (int ni = 0; ni < 4; ni++)
#pragma unroll
                    for (int e = 0; e < 2; e++)
                        if (sp(acc[mi][ni][2*h+e], gvv[mi][h], svv[mi][h]) != 0.f)
                            atomicAdd(&bcnt[(size_t)(bb2*C_ + r)*N_ +
                                            nT + n0w + ni*8 + 2*t4 + e], 1);
            }
    }
}

// ---------------------------------------------------------------------------
// Spatial attention — packed-word inputs, popc.  Output fp16 [n][c].
//   M[d1][d2] = sum_w popc(Kb&Vb); o[n][d2] = sum_{d1:Qbit} M; spike = (o>=8)
// ---------------------------------------------------------------------------
__global__ void __launch_bounds__(256)
attn_spatial(const u32* __restrict__ Pq, const u32* __restrict__ Pk,
             const u32* __restrict__ Pv, __half* __restrict__ Sab)
{
    __shared__ u32 Qb[32][12], Kb[32][12], Vb[32][12];
    __shared__ int Ms[32][33];

    const int blk = blockIdx.x;            // (t*B+b)*H + h
    const int h   = blk % H_;
    const int tb  = blk / H_;
    const int tid = threadIdx.x;
    const int wid = tid >> 5, lane = tid & 31;

    const size_t bw = ((size_t)tb * C_ + h*32) * 12;
    for (int i = tid; i < 384; i += 256) {
        (&Qb[0][0])[i] = Pq[bw + i];
        (&Kb[0][0])[i] = Pk[bw + i];
        (&Vb[0][0])[i] = Pv[bw + i];
    }
    __syncthreads();

    {
        const int d1  = tid >> 3;
        const int d2b = (tid & 7) * 4;
#pragma unroll
        for (int j = 0; j < 4; j++) {
            int s = 0;
#pragma unroll
            for (int w = 0; w < 12; w++) s += __popc(Kb[d1][w] & Vb[d2b + j][w]);
            Ms[d1][d2b + j] = s;
        }
    }
    __syncthreads();

    const __half ONE = __float2half(1.f), ZERO = __float2half(0.f);
    __half* ob = Sab + (size_t)tb * CN;   // [n][c]
#pragma unroll
    for (int gg = 0; gg < 6; gg++) {
        const int nb = wid*48 + gg*8;
        const int w  = nb >> 5, sh = nb & 31;
        int o[8];
#pragma unroll
        for (int j = 0; j < 8; j++) o[j] = 0;
#pragma unroll 4
        for (int d1 = 0; d1 < 32; d1++) {
            const int m = Ms[d1][lane];
            const u32 bits = (Qb[d1][w] >> sh) & 0xffu;
#pragma unroll
            for (int j = 0; j < 8; j++)
                if (bits & (1u << j)) o[j] += m;
        }
#pragma unroll
        for (int j = 0; j < 8; j++)
            ob[(size_t)(nb + j) * C_ + h*D_ + lane] = (o[j] >= 8) ? ONE : ZERO;
    }
}

// ---------------------------------------------------------------------------
// Temporal attention — packed-word inputs, popc.  One warp per (n,b,h).
// Output fp16 at torch-reshape position: idx=10h+t; t'=idx/12; c'=(idx%12)*32+lane
// ---------------------------------------------------------------------------
__global__ void __launch_bounds__(256)
attn_temporal(const u32* __restrict__ Pq, const u32* __restrict__ Pk,
              const u32* __restrict__ Pv, __half* __restrict__ Stb)
{
    const int gwid = blockIdx.x * 8 + (threadIdx.x >> 5);   // 0..18431
    const int lane = threadIdx.x & 31;
    const int n = gwid % N_;
    const int b = (gwid / N_) & 3;
    const int h = gwid / (N_ * B_);

    u32 qb[10], kb[10], vloc = 0;
#pragma unroll
    for (int t = 0; t < 10; t++) {
        size_t w = ((size_t)(t*B_ + b) * N_ + n) * 12 + h;
        qb[t] = Pq[w];
        kb[t] = Pk[w];
        vloc |= ((Pv[w] >> lane) & 1u) << t;
    }
    const __half ONE = __float2half(1.f), ZERO = __float2half(0.f);
#pragma unroll
    for (int t = 0; t < 10; t++) {
        int o = 0;
#pragma unroll
        for (int s = 0; s < 10; s++)
            if ((vloc >> s) & 1u) o += __popc(qb[t] & kb[s]);
        const int idx = 10*h + t;
        const int tn = idx / 12, wn2 = idx % 12;
        Stb[(((size_t)tn * B_ + b) * N_ + n) * C_ + wn2*32 + lane] = (o >= 8) ? ONE : ZERO;
    }
}

// out[t,b,c,n] = (acnt[t,b,c]/384) * (bcnt[b,c,n]/10)
__global__ void finalize_kernel(const int* __restrict__ acnt,
                                const int* __restrict__ bcnt,
                                float* __restrict__ out)
{
    int i = blockIdx.x * 256 + threadIdx.x;
    if (i >= TEN) return;
    int n  = i % N_;
    int c  = (i / N_) % C_;
    int bb = (i / (N_ * C_)) % B_;
    int t  = i / (N_ * C_ * B_);
    float a  = (float)acnt[(t * B_ + bb) * C_ + c] / 384.0f;
    float bt = (float)bcnt[(bb * C_ + c) * N_ + n] / 10.0f;
    out[i] = a * bt;
}

extern "C" void kernel_launch(void* const* d_in, const int* in_sizes, int n_in,
                              void* d_out, int out_size)
{
    (void)in_sizes; (void)n_in; (void)out_size;
    const float* x  = (const float*)d_in[0];
    const float* y  = (const float*)d_in[1];
    const float* Ws = (const float*)d_in[2];
    const float* gs = (const float*)d_in[3];
    const float* bs = (const float*)d_in[4];
    const float* Wt = (const float*)d_in[5];
    const float* gt = (const float*)d_in[6];
    const float* bt = (const float*)d_in[7];
    float* out = (float*)d_out;

    u32 *Pqs, *Pks, *Pvs, *Pqt, *Pkt, *Pvt;
    __half *Sab, *Stb, *Wh, *Xh;
    int *acnt, *bcnt;
    cudaGetSymbolAddress((void**)&Pqs, g_Pqs);
    cudaGetSymbolAddress((void**)&Pks, g_Pks);
    cudaGetSymbolAddress((void**)&Pvs, g_Pvs);
    cudaGetSymbolAddress((void**)&Pqt, g_Pqt);
    cudaGetSymbolAddress((void**)&Pkt, g_Pkt);
    cudaGetSymbolAddress((void**)&Pvt, g_Pvt);
    cudaGetSymbolAddress((void**)&Sab, g_Sab);
    cudaGetSymbolAddress((void**)&Stb, g_Stb);
    cudaGetSymbolAddress((void**)&Wh,  g_Wh);
    cudaGetSymbolAddress((void**)&Xh,  g_Xh);
    cudaGetSymbolAddress((void**)&acnt, g_acnt);
    cudaGetSymbolAddress((void**)&bcnt, g_bcnt);

    cudaFuncSetAttribute(hmma_gemm<0>, cudaFuncAttributeMaxDynamicSharedMemorySize, SMEM_F);
    cudaFuncSetAttribute(hmma_gemm<1>, cudaFuncAttributeMaxDynamicSharedMemorySize, SMEM_K);

    cudaMemsetAsync(acnt, 0, sizeof(int) * T_ * B_ * C_, 0);
    cudaMemsetAsync(bcnt, 0, sizeof(int) * B_ * C_ * N_, 0);

    // Prepasses: W fp16 2-split; X transpose + fp16 2-split
    prep_w<<<(8*C2 + 255)/256, 256>>>(Ws, Wt, Wh);
    prep_x<<<dim3(N_/32, C_/32, 2*SLICES), dim3(32, 8)>>>(x, y, Xh);

    probe_pad<<<1, 32>>>();   // aligns ncu -s 5 onto the front GEMM

    // Six front convs on tensor cores: grid z = conv*40 + slice
    hmma_gemm<0><<<dim3(3, 3, 6*SLICES), 512, SMEM_F>>>(
        Wh, Xh, Sab, Stb, gs, bs, gt, bt,
        Pqs, Pks, Pvs, Pqt, Pkt, Pvt, acnt, bcnt);

    // Exact-integer attention on packed spike words -> fp16 [n][c] outputs
    attn_spatial <<<SLICES * H_, 256>>>(Pqs, Pks, Pvs, Sab);
    attn_temporal<<<(N_ * B_ * H_) / 8, 256>>>(Pqt, Pkt, Pvt, Stb);

    // Two back convs on tensor cores: grid z = which*40 + slice
    hmma_gemm<1><<<dim3(3, 3, 2*SLICES), 512, SMEM_K>>>(
        Wh, Xh, Sab, Stb, gs, bs, gt, bt,
        Pqs, Pks, Pvs, Pqt, Pkt, Pvt, acnt, bcnt);

    // Rank-1 outer product
    finalize_kernel<<<(TEN + 255)/256, 256>>>(acnt, bcnt, out);
}

// round 14
// speedup vs baseline: 2.6081x; 1.0359x over previous
#include <cuda_runtime.h>
#include <cuda_fp16.h>
#include <stdint.h>

// Problem constants
#define T_  10
#define B_  4
#define C_  384
#define N_  384
#define H_  12
#define D_  32
#define SLICES (T_*B_)                 // 40
#define TEN (T_*B_*C_*N_)              // 5,898,240
#define C2  (C_*C_)
#define CN  (C_*N_)

typedef unsigned int u32;

// Scratch (device globals — no allocations allowed)
__device__ __align__(16) u32 g_Pqs[SLICES*C_*12];   // spatial q spikes, bits over n: [slice][c][12]
__device__ __align__(16) u32 g_Pks[SLICES*C_*12];
__device__ __align__(16) u32 g_Pvs[SLICES*C_*12];
__device__ __align__(16) u32 g_Pqt[SLICES*N_*12];   // temporal q spikes, bits over c: [slice][n][12]
__device__ __align__(16) u32 g_Pkt[SLICES*N_*12];
__device__ __align__(16) u32 g_Pvt[SLICES*N_*12];
__device__ __align__(16) __half g_Sab[TEN];   // spatial attn spikes fp16 [slice][n][c]
__device__ __align__(16) __half g_Stb[TEN];   // temporal attn spikes fp16 [t'][b][n][c']
__device__ __align__(16) __half g_Wh[8*2*C2];                  // [conv][split h/m][o][c]
__device__ __align__(16) __half g_Xh[(size_t)2*2*SLICES*CN];   // [src][split][slice][n][c]
__device__ int g_acnt[T_*B_*C_];
__device__ int g_bcnt[B_*C_*N_];

// ---------------------------------------------------------------------------
// helpers: cp.async, ldmatrix, mma.sync (portable to compute_103)
// ---------------------------------------------------------------------------
__device__ __forceinline__ u32 smem_u32(const void* p) {
    u32 a;
    asm("{ .reg .u64 t; cvta.to.shared.u64 t, %1; cvt.u32.u64 %0, t; }" : "=r"(a) : "l"(p));
    return a;
}
__device__ __forceinline__ void cpa16(u32 saddr, const void* g) {
    asm volatile("cp.async.cg.shared.global [%0], [%1], 16;" :: "r"(saddr), "l"(g));
}
#define CPA_COMMIT() asm volatile("cp.async.commit_group;")
#define CPA_WAIT2()  asm volatile("cp.async.wait_group 2;")

#define LDSM4(R, addr) \
    asm volatile("ldmatrix.sync.aligned.m8n8.x4.shared.b16 {%0,%1,%2,%3}, [%4];" \
                 : "=r"((R)[0]), "=r"((R)[1]), "=r"((R)[2]), "=r"((R)[3]) : "r"(addr))

#define MMA_16816(C4, A4, b0, b1) \
    asm volatile("mma.sync.aligned.m16n8k16.row.col.f32.f16.f16.f32 " \
                 "{%0,%1,%2,%3},{%4,%5,%6,%7},{%8,%9},{%0,%1,%2,%3};" \
                 : "+f"((C4)[0]), "+f"((C4)[1]), "+f"((C4)[2]), "+f"((C4)[3]) \
                 : "r"((A4)[0]), "r"((A4)[1]), "r"((A4)[2]), "r"((A4)[3]), \
                   "r"(b0), "r"(b1))

// ---------------------------------------------------------------------------
// prep_w: fp16 2-split of all 8 W matrices: [conv][split][o][c]
// ---------------------------------------------------------------------------
__global__ void prep_w(const float* __restrict__ Ws, const float* __restrict__ Wt,
                       __half* __restrict__ Wh)
{
    int i = blockIdx.x * 256 + threadIdx.x;
    if (i >= 8 * C2) return;
    int m = i / C2, r = i % C2;
    float w = (m < 4) ? Ws[i] : Wt[i - 4*C2];
    __half h = __float2half_rn(w);
    float rh = w - __half2float(h);
    __half md = __float2half_rn(rh);
    Wh[((size_t)m*2 + 0)*C2 + r] = h;
    Wh[((size_t)m*2 + 1)*C2 + r] = md;
}

// ---------------------------------------------------------------------------
// prep_x: transpose x,y slices [c][n] -> [n][c], fp16 2-split
// ---------------------------------------------------------------------------
__global__ void prep_x(const float* __restrict__ x, const float* __restrict__ y,
                       __half* __restrict__ Xh)
{
    __shared__ float t[32][33];
    const int z = blockIdx.z;
    const int src = z / SLICES, slice = z % SLICES;
    const float* X = (src ? y : x) + (size_t)slice * CN;
    const int n0 = blockIdx.x * 32, c0 = blockIdx.y * 32;
    const int tx = threadIdx.x, ty = threadIdx.y;
#pragma unroll
    for (int j = 0; j < 32; j += 8)
        t[ty + j][tx] = X[(size_t)(c0 + ty + j) * N_ + n0 + tx];
    __syncthreads();
    const size_t so = (size_t)SLICES * CN;
    const size_t ob = ((size_t)src * 2 * SLICES + slice) * CN;
#pragma unroll
    for (int j = 0; j < 32; j += 8) {
        float v = t[tx][ty + j];
        __half h = __float2half_rn(v);
        float rh = v - __half2float(h);
        __half md = __float2half_rn(rh);
        size_t a = ob + (size_t)(n0 + ty + j) * C_ + c0 + tx;
        Xh[a] = h; Xh[a + so] = md;
    }
}

// probe no-op: aligns ncu's -s 5 -c 1 capture onto hmma_gemm<0>
__global__ void probe_pad() {}

// ---------------------------------------------------------------------------
// HMMA fp16-split GEMM.  Z[o][n] = sum_c W[o][c] X[c][n] (f32 accum), affine,
// spike (z >= 2).  CTA 128x128, 16 warps (4M x 4N), warp tile 32x32.
// K chunks of 32 halves, 4-stage cp.async pipeline, ONE sync per k-block.
// MMA order: combo-outer (hh all tiles, mh all tiles, hm all tiles) — max
// accumulator-reuse distance (8 MMAs) to cover MMA latency.
// PHASE 0 (front): combos (Ah,Bh)(Am,Bh)(Ah,Bm); tiles {Ah,Am,Bh,Bm}
//   mode 0 spatial  -> packed u32 bits-over-n  [slice][c][12]
//   mode 1 temporal -> packed u32 bits-over-c  [slice][n][12]
// PHASE 1 (back): B = attn spikes fp16 (exact), combos (Ah,Bs)(Am,Bs); tiles {Ah,Am,Bs}
//   mode 2 spatial back  -> acnt row counts
//   mode 3 temporal back -> bcnt per-(b,c,n) counts
// ---------------------------------------------------------------------------
#define ROWB   80                      // bytes per smem row: 32 halves + 8 pad
#define TILE_B (128*ROWB)              // 10240
#define STAGES 4
#define SMEM_F (STAGES*4*TILE_B)       // 163840
#define SMEM_K (STAGES*3*TILE_B)       // 122880

template<int PHASE>
__global__ void __launch_bounds__(512, 1)
hmma_gemm(const __half* __restrict__ Wh, const __half* __restrict__ Xh,
          const __half* __restrict__ Sab, const __half* __restrict__ Stb,
          const float* __restrict__ gs, const float* __restrict__ bs,
          const float* __restrict__ gt, const float* __restrict__ bt,
          u32* __restrict__ Pqs, u32* __restrict__ Pks, u32* __restrict__ Pvs,
          u32* __restrict__ Pqt, u32* __restrict__ Pkt, u32* __restrict__ Pvt,
          int* __restrict__ acnt, int* __restrict__ bcnt)
{
    extern __shared__ char smem[];
    __shared__ int rcnt[128];
    const u32 smb = smem_u32(smem);
    const int tid = threadIdx.x;
    const int wid = tid >> 5, lane = tid & 31;
    const int g = lane >> 2, t4 = lane & 3;
    const int wm = wid & 3, wn = wid >> 2;       // warp grid 4(M) x 4(N)
    const int m0 = wm * 32, n0w = wn * 32;

    const int z = blockIdx.z;
    const int sel = z / SLICES;
    const int slice = z % SLICES;

    const float *Gp, *Bp;
    u32* Po = nullptr;
    int widx, mode;
    const __half *Bh_g, *Bm_g;
    if (PHASE == 0) {
        if (sel < 3) { widx = sel;     Gp = gs + sel*C_;     Bp = bs + sel*C_;     mode = 0; }
        else         { widx = sel + 1; Gp = gt + (sel-3)*C_; Bp = bt + (sel-3)*C_; mode = 1; }
        const int src = (sel == 0 || sel == 3) ? 0 : 1;
        Bh_g = Xh + ((size_t)(src*2 + 0) * SLICES + slice) * CN;
        Bm_g = Xh + ((size_t)(src*2 + 1) * SLICES + slice) * CN;
        if      (sel == 0) Po = Pqs; else if (sel == 1) Po = Pks; else if (sel == 2) Po = Pvs;
        else if (sel == 3) Po = Pqt; else if (sel == 4) Po = Pkt; else               Po = Pvt;
        Po += (size_t)slice * ((mode == 0) ? C_ : N_) * 12;
    } else {
        if (sel == 0) { widx = 3; Gp = gs + 3*C_; Bp = bs + 3*C_; mode = 2; }
        else          { widx = 7; Gp = gt + 3*C_; Bp = bt + 3*C_; mode = 3; }
        Bh_g = (sel ? Stb : Sab) + (size_t)slice * CN;
        Bm_g = Bh_g;
    }
    const __half* Ah_g = Wh + (size_t)(widx*2 + 0) * C2;
    const __half* Am_g = Wh + (size_t)(widx*2 + 1) * C2;

    const int oT = blockIdx.y * 128;
    const int nT = blockIdx.x * 128;
    constexpr int NTILE = (PHASE == 0) ? 4 : 3;
    constexpr u32 STAGE = NTILE * TILE_B;

    if (tid < 128) rcnt[tid] = 0;

    const __half* tp[4];
    tp[0] = Ah_g; tp[1] = Am_g; tp[2] = Bh_g; tp[3] = (PHASE == 0) ? Bm_g : Bh_g;

    auto issue = [&](int kb) {
        const int k0 = kb * 32;
        const u32 sb = smb + (u32)(kb & (STAGES-1)) * STAGE;
        const int row = tid >> 2, ch = tid & 3;
#pragma unroll
        for (int it = 0; it < NTILE; it++) {
            int rbase = (it < 2) ? oT : nT;
            const __half* gp = tp[it] + (size_t)(rbase + row) * C_ + k0 + ch*8;
            cpa16(sb + (u32)it * TILE_B + (u32)(row * ROWB + ch * 16), gp);
        }
        CPA_COMMIT();
    };

    float acc[2][4][4];
#pragma unroll
    for (int mi = 0; mi < 2; mi++)
#pragma unroll
        for (int ni = 0; ni < 4; ni++)
#pragma unroll
            for (int e = 0; e < 4; e++) acc[mi][ni][e] = 0.f;

    // per-thread ldmatrix offsets (bytes)
    const u32 aoff = (u32)((lane & 15) * ROWB + (lane >> 4) * 16);
    const u32 boff = (u32)(((lane & 7) + 8 * (lane >> 4)) * ROWB + ((lane >> 3) & 1) * 16);

    // prologue: fill 3 stages, make stage 0 visible
    issue(0); issue(1); issue(2);
    CPA_WAIT2();
    __syncthreads();

#pragma unroll 1
    for (int kb = 0; kb < 12; kb++) {
        if (kb + 3 < 12) issue(kb + 3);      // overwrites stage computed at kb-1 (sync-protected)
        const u32 stg = smb + (u32)(kb & (STAGES-1)) * STAGE;
#pragma unroll
        for (int ks = 0; ks < 2; ks++) {
            const u32 kof = (u32)(ks * 32);
            u32 aH[2][4], aM[2][4], bH[2][4], bM[2][4];
#pragma unroll
            for (int mi = 0; mi < 2; mi++)
                LDSM4(aH[mi], stg + 0*TILE_B + aoff + (u32)((m0 + mi*16) * ROWB) + kof);
#pragma unroll
            for (int mi = 0; mi < 2; mi++)
                LDSM4(aM[mi], stg + 1*TILE_B + aoff + (u32)((m0 + mi*16) * ROWB) + kof);
#pragma unroll
            for (int p = 0; p < 2; p++)
                LDSM4(bH[p], stg + 2*TILE_B + boff + (u32)((n0w + p*16) * ROWB) + kof);
            if (PHASE == 0) {
#pragma unroll
                for (int p = 0; p < 2; p++)
                    LDSM4(bM[p], stg + 3*TILE_B + boff + (u32)((n0w + p*16) * ROWB) + kof);
            }
            // combo-outer: same-acc reuse distance = 8 MMAs
#pragma unroll
            for (int mi = 0; mi < 2; mi++)
#pragma unroll
                for (int ni = 0; ni < 4; ni++) {
                    const int p = ni >> 1, q = 2 * (ni & 1);
                    MMA_16816(acc[mi][ni], aH[mi], bH[p][q], bH[p][q+1]);
                }
#pragma unroll
            for (int mi = 0; mi < 2; mi++)
#pragma unroll
                for (int ni = 0; ni < 4; ni++) {
                    const int p = ni >> 1, q = 2 * (ni & 1);
                    MMA_16816(acc[mi][ni], aM[mi], bH[p][q], bH[p][q+1]);
                }
            if (PHASE == 0) {
#pragma unroll
                for (int mi = 0; mi < 2; mi++)
#pragma unroll
                    for (int ni = 0; ni < 4; ni++) {
                        const int p = ni >> 1, q = 2 * (ni & 1);
                        MMA_16816(acc[mi][ni], aH[mi], bM[p][q], bM[p][q+1]);
                    }
            }
        }
        CPA_WAIT2();            // stage kb+1 ready for next iteration
        __syncthreads();        // all warps done with stage kb (next iter overwrites it)
    }

    // ---------------- epilogue: affine + threshold ----------------
    float gvv[2][2], svv[2][2];
#pragma unroll
    for (int mi = 0; mi < 2; mi++)
#pragma unroll
        for (int h = 0; h < 2; h++) {
            int r = oT + m0 + mi*16 + h*8 + g;
            gvv[mi][h] = Gp[r]; svv[mi][h] = Bp[r];
        }
    auto sp = [](float c, float gg, float ss) {
        return (__fadd_rn(__fmul_rn(c, gg), ss) >= 2.0f) ? 1.f : 0.f;
    };
    const int bb2 = slice & (B_ - 1);

    if (PHASE == 0 && mode == 0) {          // spatial: pack bits over n
        const int wq = blockIdx.x * 4 + wn;
#pragma unroll
        for (int mi = 0; mi < 2; mi++)
#pragma unroll
            for (int h = 0; h < 2; h++) {
                u32 wv = 0;
#pragma unroll
                for (int ni = 0; ni < 4; ni++)
#pragma unroll
                    for (int e = 0; e < 2; e++)
                        if (sp(acc[mi][ni][2*h+e], gvv[mi][h], svv[mi][h]) != 0.f)
                            wv |= 1u << (ni*8 + 2*t4 + e);
                wv |= __shfl_xor_sync(0xffffffffu, wv, 1);
                wv |= __shfl_xor_sync(0xffffffffu, wv, 2);
                if (t4 == 0)
                    Po[(size_t)(oT + m0 + mi*16 + 8*h + g) * 12 + wq] = wv;
            }
    } else if (PHASE == 0) {                // temporal: pack bits over c
        const int wqm = blockIdx.y * 4 + wm;
#pragma unroll
        for (int ni = 0; ni < 4; ni++)
#pragma unroll
            for (int e = 0; e < 2; e++) {
                u32 wv = 0;
#pragma unroll
                for (int mi = 0; mi < 2; mi++)
#pragma unroll
                    for (int h = 0; h < 2; h++)
                        if (sp(acc[mi][ni][2*h+e], gvv[mi][h], svv[mi][h]) != 0.f)
                            wv |= 1u << (mi*16 + 8*h + g);
                wv |= __shfl_xor_sync(0xffffffffu, wv, 4);
                wv |= __shfl_xor_sync(0xffffffffu, wv, 8);
                wv |= __shfl_xor_sync(0xffffffffu, wv, 16);
                if (lane < 4) {             // g==0, lane==t4
                    int n = nT + n0w + ni*8 + 2*t4 + e;
                    Po[(size_t)n * 12 + wqm] = wv;
                }
            }
    } else if (mode == 2) {                 // spatial back: row spike counts
        __syncthreads();
#pragma unroll
        for (int mi = 0; mi < 2; mi++)
#pragma unroll
            for (int h = 0; h < 2; h++) {
                int c = 0;
#pragma unroll
                for (int ni = 0; ni < 4; ni++)
#pragma unroll
                    for (int e = 0; e < 2; e++)
                        c += (int)sp(acc[mi][ni][2*h+e], gvv[mi][h], svv[mi][h]);
                if (c) atomicAdd(&rcnt[m0 + mi*16 + 8*h + g], c);
            }
        __syncthreads();
        if (tid < 128) {
            int v = rcnt[tid];
            if (v) atomicAdd(&acnt[slice * C_ + oT + tid], v);
        }
    } else {                                // temporal back: per-(b,c,n) counts
#pragma unroll
        for (int mi = 0; mi < 2; mi++)
#pragma unroll
            for (int h = 0; h < 2; h++) {
                int r = oT + m0 + mi*16 + 8*h + g;
#pragma unroll
                for (int ni = 0; ni < 4; ni++)
#pragma unroll
                    for (int e = 0; e < 2; e++)
                        if (sp(acc[mi][ni][2*h+e], gvv[mi][h], svv[mi][h]) != 0.f)
                            atomicAdd(&bcnt[(size_t)(bb2*C_ + r)*N_ +
                                            nT + n0w + ni*8 + 2*t4 + e], 1);
            }
    }
}

// ---------------------------------------------------------------------------
// Spatial attention — packed-word inputs, popc.  Output fp16 [n][c].
//   M[d1][d2] = sum_w popc(Kb&Vb); o[n][d2] = sum_{d1:Qbit} M; spike = (o>=8)
// ---------------------------------------------------------------------------
__global__ void __launch_bounds__(256)
attn_spatial(const u32* __restrict__ Pq, const u32* __restrict__ Pk,
             const u32* __restrict__ Pv, __half* __restrict__ Sab)
{
    __shared__ u32 Qb[32][12], Kb[32][12], Vb[32][12];
    __shared__ int Ms[32][33];

    const int blk = blockIdx.x;            // (t*B+b)*H + h
    const int h   = blk % H_;
    const int tb  = blk / H_;
    const int tid = threadIdx.x;
    const int wid = tid >> 5, lane = tid & 31;

    const size_t bw = ((size_t)tb * C_ + h*32) * 12;
    for (int i = tid; i < 384; i += 256) {
        (&Qb[0][0])[i] = Pq[bw + i];
        (&Kb[0][0])[i] = Pk[bw + i];
        (&Vb[0][0])[i] = Pv[bw + i];
    }
    __syncthreads();

    {
        const int d1  = tid >> 3;
        const int d2b = (tid & 7) * 4;
#pragma unroll
        for (int j = 0; j < 4; j++) {
            int s = 0;
#pragma unroll
            for (int w = 0; w < 12; w++) s += __popc(Kb[d1][w] & Vb[d2b + j][w]);
            Ms[d1][d2b + j] = s;
        }
    }
    __syncthreads();

    const __half ONE = __float2half(1.f), ZERO = __float2half(0.f);
    __half* ob = Sab + (size_t)tb * CN;   // [n][c]
#pragma unroll
    for (int gg = 0; gg < 6; gg++) {
        const int nb = wid*48 + gg*8;
        const int w  = nb >> 5, sh = nb & 31;
        int o[8];
#pragma unroll
        for (int j = 0; j < 8; j++) o[j] = 0;
#pragma unroll 4
        for (int d1 = 0; d1 < 32; d1++) {
            const int m = Ms[d1][lane];
            const u32 bits = (Qb[d1][w] >> sh) & 0xffu;
#pragma unroll
            for (int j = 0; j < 8; j++)
                if (bits & (1u << j)) o[j] += m;
        }
#pragma unroll
        for (int j = 0; j < 8; j++)
            ob[(size_t)(nb + j) * C_ + h*D_ + lane] = (o[j] >= 8) ? ONE : ZERO;
    }
}

// ---------------------------------------------------------------------------
// Temporal attention — packed-word inputs, popc.  One warp per (n,b,h).
// Output fp16 at torch-reshape position: idx=10h+t; t'=idx/12; c'=(idx%12)*32+lane
// ---------------------------------------------------------------------------
__global__ void __launch_bounds__(256)
attn_temporal(const u32* __restrict__ Pq, const u32* __restrict__ Pk,
              const u32* __restrict__ Pv, __half* __restrict__ Stb)
{
    const int gwid = blockIdx.x * 8 + (threadIdx.x >> 5);   // 0..18431
    const int lane = threadIdx.x & 31;
    const int n = gwid % N_;
    const int b = (gwid / N_) & 3;
    const int h = gwid / (N_ * B_);

    u32 qb[10], kb[10], vloc = 0;
#pragma unroll
    for (int t = 0; t < 10; t++) {
        size_t w = ((size_t)(t*B_ + b) * N_ + n) * 12 + h;
        qb[t] = Pq[w];
        kb[t] = Pk[w];
        vloc |= ((Pv[w] >> lane) & 1u) << t;
    }
    const __half ONE = __float2half(1.f), ZERO = __float2half(0.f);
#pragma unroll
    for (int t = 0; t < 10; t++) {
        int o = 0;
#pragma unroll
        for (int s = 0; s < 10; s++)
            if ((vloc >> s) & 1u) o += __popc(qb[t] & kb[s]);
        const int idx = 10*h + t;
        const int tn = idx / 12, wn2 = idx % 12;
        Stb[(((size_t)tn * B_ + b) * N_ + n) * C_ + wn2*32 + lane] = (o >= 8) ? ONE : ZERO;
    }
}

// out[t,b,c,n] = (acnt[t,b,c]/384) * (bcnt[b,c,n]/10)
__global__ void finalize_kernel(const int* __restrict__ acnt,
                                const int* __restrict__ bcnt,
                                float* __restrict__ out)
{
    int i = blockIdx.x * 256 + threadIdx.x;
    if (i >= TEN) return;
    int n  = i % N_;
    int c  = (i / N_) % C_;
    int bb = (i / (N_ * C_)) % B_;
    int t  = i / (N_ * C_ * B_);
    float a  = (float)acnt[(t * B_ + bb) * C_ + c] / 384.0f;
    float bt = (float)bcnt[(bb * C_ + c) * N_ + n] / 10.0f;
    out[i] = a * bt;
}

extern "C" void kernel_launch(void* const* d_in, const int* in_sizes, int n_in,
                              void* d_out, int out_size)
{
    (void)in_sizes; (void)n_in; (void)out_size;
    const float* x  = (const float*)d_in[0];
    const float* y  = (const float*)d_in[1];
    const float* Ws = (const float*)d_in[2];
    const float* gs = (const float*)d_in[3];
    const float* bs = (const float*)d_in[4];
    const float* Wt = (const float*)d_in[5];
    const float* gt = (const float*)d_in[6];
    const float* bt = (const float*)d_in[7];
    float* out = (float*)d_out;

    u32 *Pqs, *Pks, *Pvs, *Pqt, *Pkt, *Pvt;
    __half *Sab, *Stb, *Wh, *Xh;
    int *acnt, *bcnt;
    cudaGetSymbolAddress((void**)&Pqs, g_Pqs);
    cudaGetSymbolAddress((void**)&Pks, g_Pks);
    cudaGetSymbolAddress((void**)&Pvs, g_Pvs);
    cudaGetSymbolAddress((void**)&Pqt, g_Pqt);
    cudaGetSymbolAddress((void**)&Pkt, g_Pkt);
    cudaGetSymbolAddress((void**)&Pvt, g_Pvt);
    cudaGetSymbolAddress((void**)&Sab, g_Sab);
    cudaGetSymbolAddress((void**)&Stb, g_Stb);
    cudaGetSymbolAddress((void**)&Wh,  g_Wh);
    cudaGetSymbolAddress((void**)&Xh,  g_Xh);
    cudaGetSymbolAddress((void**)&acnt, g_acnt);
    cudaGetSymbolAddress((void**)&bcnt, g_bcnt);

    cudaFuncSetAttribute(hmma_gemm<0>, cudaFuncAttributeMaxDynamicSharedMemorySize, SMEM_F);
    cudaFuncSetAttribute(hmma_gemm<1>, cudaFuncAttributeMaxDynamicSharedMemorySize, SMEM_K);

    cudaMemsetAsync(acnt, 0, sizeof(int) * T_ * B_ * C_, 0);
    cudaMemsetAsync(bcnt, 0, sizeof(int) * B_ * C_ * N_, 0);

    // Prepasses: W fp16 2-split; X transpose + fp16 2-split
    prep_w<<<(8*C2 + 255)/256, 256>>>(Ws, Wt, Wh);
    prep_x<<<dim3(N_/32, C_/32, 2*SLICES), dim3(32, 8)>>>(x, y, Xh);

    probe_pad<<<1, 32>>>();   // aligns ncu -s 5 onto the front GEMM

    // Six front convs on tensor cores: grid z = conv*40 + slice
    hmma_gemm<0><<<dim3(3, 3, 6*SLICES), 512, SMEM_F>>>(
        Wh, Xh, Sab, Stb, gs, bs, gt, bt,
        Pqs, Pks, Pvs, Pqt, Pkt, Pvt, acnt, bcnt);

    // Exact-integer attention on packed spike words -> fp16 [n][c] outputs
    attn_spatial <<<SLICES * H_, 256>>>(Pqs, Pks, Pvs, Sab);
    attn_temporal<<<(N_ * B_ * H_) / 8, 256>>>(Pqt, Pkt, Pvt, Stb);

    // Two back convs on tensor cores: grid z = which*40 + slice
    hmma_gemm<1><<<dim3(3, 3, 2*SLICES), 512, SMEM_K>>>(
        Wh, Xh, Sab, Stb, gs, bs, gt, bt,
        Pqs, Pks, Pvs, Pqt, Pkt, Pvt, acnt, bcnt);

    // Rank-1 outer product
    finalize_kernel<<<(TEN + 255)/256, 256>>>(acnt, bcnt, out);
}

// round 15
// speedup vs baseline: 2.6422x; 1.0131x over previous
#include <cuda_runtime.h>
#include <cuda_fp16.h>
#include <stdint.h>

// Problem constants
#define T_  10
#define B_  4
#define C_  384
#define N_  384
#define H_  12
#define D_  32
#define SLICES (T_*B_)                 // 40
#define TEN (T_*B_*C_*N_)              // 5,898,240
#define C2  (C_*C_)
#define CN  (C_*N_)

typedef unsigned int u32;

// Scratch (device globals — no allocations allowed)
__device__ __align__(16) u32 g_Pqs[SLICES*C_*12];   // spatial q spikes, bits over n: [slice][c][12]
__device__ __align__(16) u32 g_Pks[SLICES*C_*12];
__device__ __align__(16) u32 g_Pvs[SLICES*C_*12];
__device__ __align__(16) u32 g_Pqt[SLICES*N_*12];   // temporal q spikes, bits over c: [slice][n][12]
__device__ __align__(16) u32 g_Pkt[SLICES*N_*12];
__device__ __align__(16) u32 g_Pvt[SLICES*N_*12];
__device__ __align__(16) __half g_Sab[TEN];   // spatial attn spikes fp16 [slice][n][c]
__device__ __align__(16) __half g_Stb[TEN];   // temporal attn spikes fp16 [t'][b][n][c']
__device__ __align__(16) __half g_Wh[8*2*C2];                  // [conv][split h/m][o][c]
__device__ __align__(16) __half g_Xh[(size_t)2*2*SLICES*CN];   // [src][split][slice][n][c]
__device__ int g_acnt[T_*B_*C_];
__device__ int g_bcnt[B_*C_*N_];

// ---------------------------------------------------------------------------
// helpers: cp.async, ldmatrix, mma.sync (portable to compute_103)
// ---------------------------------------------------------------------------
__device__ __forceinline__ u32 smem_u32(const void* p) {
    u32 a;
    asm("{ .reg .u64 t; cvta.to.shared.u64 t, %1; cvt.u32.u64 %0, t; }" : "=r"(a) : "l"(p));
    return a;
}
__device__ __forceinline__ void cpa16(u32 saddr, const void* g) {
    asm volatile("cp.async.cg.shared.global [%0], [%1], 16;" :: "r"(saddr), "l"(g));
}
#define CPA_COMMIT() asm volatile("cp.async.commit_group;")
#define CPA_WAIT2()  asm volatile("cp.async.wait_group 2;")

#define LDSM4(R, addr) \
    asm volatile("ldmatrix.sync.aligned.m8n8.x4.shared.b16 {%0,%1,%2,%3}, [%4];" \
                 : "=r"((R)[0]), "=r"((R)[1]), "=r"((R)[2]), "=r"((R)[3]) : "r"(addr))

// fp32-accumulate MMA (main term)
#define MMA_16816(C4, A4, b0, b1) \
    asm volatile("mma.sync.aligned.m16n8k16.row.col.f32.f16.f16.f32 " \
                 "{%0,%1,%2,%3},{%4,%5,%6,%7},{%8,%9},{%0,%1,%2,%3};" \
                 : "+f"((C4)[0]), "+f"((C4)[1]), "+f"((C4)[2]), "+f"((C4)[3]) \
                 : "r"((A4)[0]), "r"((A4)[1]), "r"((A4)[2]), "r"((A4)[3]), \
                   "r"(b0), "r"(b1))

// fp16-accumulate MMA (correction terms ~2^-11 of main — fp16 precision ample)
#define MMA_16816_F16(C2v, A4, b0, b1) \
    asm volatile("mma.sync.aligned.m16n8k16.row.col.f16.f16.f16.f16 " \
                 "{%0,%1},{%2,%3,%4,%5},{%6,%7},{%0,%1};" \
                 : "+r"((C2v)[0]), "+r"((C2v)[1]) \
                 : "r"((A4)[0]), "r"((A4)[1]), "r"((A4)[2]), "r"((A4)[3]), \
                   "r"(b0), "r"(b1))

// ---------------------------------------------------------------------------
// prep_w: fp16 2-split of all 8 W matrices: [conv][split][o][c]
// ---------------------------------------------------------------------------
__global__ void prep_w(const float* __restrict__ Ws, const float* __restrict__ Wt,
                       __half* __restrict__ Wh)
{
    int i = blockIdx.x * 256 + threadIdx.x;
    if (i >= 8 * C2) return;
    int m = i / C2, r = i % C2;
    float w = (m < 4) ? Ws[i] : Wt[i - 4*C2];
    __half h = __float2half_rn(w);
    float rh = w - __half2float(h);
    __half md = __float2half_rn(rh);
    Wh[((size_t)m*2 + 0)*C2 + r] = h;
    Wh[((size_t)m*2 + 1)*C2 + r] = md;
}

// ---------------------------------------------------------------------------
// prep_x: transpose x,y slices [c][n] -> [n][c], fp16 2-split
// ---------------------------------------------------------------------------
__global__ void prep_x(const float* __restrict__ x, const float* __restrict__ y,
                       __half* __restrict__ Xh)
{
    __shared__ float t[32][33];
    const int z = blockIdx.z;
    const int src = z / SLICES, slice = z % SLICES;
    const float* X = (src ? y : x) + (size_t)slice * CN;
    const int n0 = blockIdx.x * 32, c0 = blockIdx.y * 32;
    const int tx = threadIdx.x, ty = threadIdx.y;
#pragma unroll
    for (int j = 0; j < 32; j += 8)
        t[ty + j][tx] = X[(size_t)(c0 + ty + j) * N_ + n0 + tx];
    __syncthreads();
    const size_t so = (size_t)SLICES * CN;
    const size_t ob = ((size_t)src * 2 * SLICES + slice) * CN;
#pragma unroll
    for (int j = 0; j < 32; j += 8) {
        float v = t[tx][ty + j];
        __half h = __float2half_rn(v);
        float rh = v - __half2float(h);
        __half md = __float2half_rn(rh);
        size_t a = ob + (size_t)(n0 + ty + j) * C_ + c0 + tx;
        Xh[a] = h; Xh[a + so] = md;
    }
}

// probe no-op: aligns ncu's -s 5 -c 1 capture onto hmma_gemm<0>
__global__ void probe_pad() {}

// ---------------------------------------------------------------------------
// HMMA fp16-split GEMM.  Z[o][n] = sum_c W[o][c] X[c][n], affine, spike (z>=2).
// Main pass (Ah,Bh) in f32-accum; correction passes in f16-accum (values
// ~2^-11 of main), folded into f32 at epilogue.
// CTA 128x128, 16 warps (4M x 4N), warp tile 32x32, K chunks of 32 halves,
// 4-stage cp.async pipeline, one sync per k-block.
// PHASE 0 (front): f32 (Ah,Bh); f16 (Am,Bh)+(Ah,Bm); tiles {Ah,Am,Bh,Bm}
//   mode 0 spatial  -> packed u32 bits-over-n  [slice][c][12]
//   mode 1 temporal -> packed u32 bits-over-c  [slice][n][12]
// PHASE 1 (back): B = attn spikes fp16 (exact); f32 (Ah,B); f16 (Am,B)
//   mode 2 spatial back  -> acnt row counts
//   mode 3 temporal back -> bcnt per-(b,c,n) counts
// ---------------------------------------------------------------------------
#define ROWB   80                      // bytes per smem row: 32 halves + 8 pad
#define TILE_B (128*ROWB)              // 10240
#define STAGES 4
#define SMEM_F (STAGES*4*TILE_B)       // 163840
#define SMEM_K (STAGES*3*TILE_B)       // 122880

template<int PHASE>
__global__ void __launch_bounds__(512, 1)
hmma_gemm(const __half* __restrict__ Wh, const __half* __restrict__ Xh,
          const __half* __restrict__ Sab, const __half* __restrict__ Stb,
          const float* __restrict__ gs, const float* __restrict__ bs,
          const float* __restrict__ gt, const float* __restrict__ bt,
          u32* __restrict__ Pqs, u32* __restrict__ Pks, u32* __restrict__ Pvs,
          u32* __restrict__ Pqt, u32* __restrict__ Pkt, u32* __restrict__ Pvt,
          int* __restrict__ acnt, int* __restrict__ bcnt)
{
    extern __shared__ char smem[];
    __shared__ int rcnt[128];
    const u32 smb = smem_u32(smem);
    const int tid = threadIdx.x;
    const int wid = tid >> 5, lane = tid & 31;
    const int g = lane >> 2, t4 = lane & 3;
    const int wm = wid & 3, wn = wid >> 2;       // warp grid 4(M) x 4(N)
    const int m0 = wm * 32, n0w = wn * 32;

    const int z = blockIdx.z;
    const int sel = z / SLICES;
    const int slice = z % SLICES;

    const float *Gp, *Bp;
    u32* Po = nullptr;
    int widx, mode;
    const __half *Bh_g, *Bm_g;
    if (PHASE == 0) {
        if (sel < 3) { widx = sel;     Gp = gs + sel*C_;     Bp = bs + sel*C_;     mode = 0; }
        else         { widx = sel + 1; Gp = gt + (sel-3)*C_; Bp = bt + (sel-3)*C_; mode = 1; }
        const int src = (sel == 0 || sel == 3) ? 0 : 1;
        Bh_g = Xh + ((size_t)(src*2 + 0) * SLICES + slice) * CN;
        Bm_g = Xh + ((size_t)(src*2 + 1) * SLICES + slice) * CN;
        if      (sel == 0) Po = Pqs; else if (sel == 1) Po = Pks; else if (sel == 2) Po = Pvs;
        else if (sel == 3) Po = Pqt; else if (sel == 4) Po = Pkt; else               Po = Pvt;
        Po += (size_t)slice * ((mode == 0) ? C_ : N_) * 12;
    } else {
        if (sel == 0) { widx = 3; Gp = gs + 3*C_; Bp = bs + 3*C_; mode = 2; }
        else          { widx = 7; Gp = gt + 3*C_; Bp = bt + 3*C_; mode = 3; }
        Bh_g = (sel ? Stb : Sab) + (size_t)slice * CN;
        Bm_g = Bh_g;
    }
    const __half* Ah_g = Wh + (size_t)(widx*2 + 0) * C2;
    const __half* Am_g = Wh + (size_t)(widx*2 + 1) * C2;

    const int oT = blockIdx.y * 128;
    const int nT = blockIdx.x * 128;
    constexpr int NTILE = (PHASE == 0) ? 4 : 3;
    constexpr u32 STAGE = NTILE * TILE_B;

    if (tid < 128) rcnt[tid] = 0;

    const __half* tp[4];
    tp[0] = Ah_g; tp[1] = Am_g; tp[2] = Bh_g; tp[3] = (PHASE == 0) ? Bm_g : Bh_g;

    auto issue = [&](int kb) {
        const int k0 = kb * 32;
        const u32 sb = smb + (u32)(kb & (STAGES-1)) * STAGE;
        const int row = tid >> 2, ch = tid & 3;
#pragma unroll
        for (int it = 0; it < NTILE; it++) {
            int rbase = (it < 2) ? oT : nT;
            const __half* gp = tp[it] + (size_t)(rbase + row) * C_ + k0 + ch*8;
            cpa16(sb + (u32)it * TILE_B + (u32)(row * ROWB + ch * 16), gp);
        }
        CPA_COMMIT();
    };

    float acc[2][4][4];
    u32 corr[2][4][2];                   // fp16x2 correction accumulators
#pragma unroll
    for (int mi = 0; mi < 2; mi++)
#pragma unroll
        for (int ni = 0; ni < 4; ni++) {
#pragma unroll
            for (int e = 0; e < 4; e++) acc[mi][ni][e] = 0.f;
            corr[mi][ni][0] = 0u; corr[mi][ni][1] = 0u;
        }

    // per-thread ldmatrix offsets (bytes)
    const u32 aoff = (u32)((lane & 15) * ROWB + (lane >> 4) * 16);
    const u32 boff = (u32)(((lane & 7) + 8 * (lane >> 4)) * ROWB + ((lane >> 3) & 1) * 16);

    // prologue: fill 3 stages, make stage 0 visible
    issue(0); issue(1); issue(2);
    CPA_WAIT2();
    __syncthreads();

#pragma unroll 1
    for (int kb = 0; kb < 12; kb++) {
        if (kb + 3 < 12) issue(kb + 3);
        const u32 stg = smb + (u32)(kb & (STAGES-1)) * STAGE;
#pragma unroll
        for (int ks = 0; ks < 2; ks++) {
            const u32 kof = (u32)(ks * 32);
            u32 aH[2][4], aM[2][4], bH[2][4], bM[2][4];
#pragma unroll
            for (int mi = 0; mi < 2; mi++)
                LDSM4(aH[mi], stg + 0*TILE_B + aoff + (u32)((m0 + mi*16) * ROWB) + kof);
#pragma unroll
            for (int mi = 0; mi < 2; mi++)
                LDSM4(aM[mi], stg + 1*TILE_B + aoff + (u32)((m0 + mi*16) * ROWB) + kof);
#pragma unroll
            for (int p = 0; p < 2; p++)
                LDSM4(bH[p], stg + 2*TILE_B + boff + (u32)((n0w + p*16) * ROWB) + kof);
            if (PHASE == 0) {
#pragma unroll
                for (int p = 0; p < 2; p++)
                    LDSM4(bM[p], stg + 3*TILE_B + boff + (u32)((n0w + p*16) * ROWB) + kof);
            }
            // main pass: f32 accumulate
#pragma unroll
            for (int mi = 0; mi < 2; mi++)
#pragma unroll
                for (int ni = 0; ni < 4; ni++) {
                    const int p = ni >> 1, q = 2 * (ni & 1);
                    MMA_16816(acc[mi][ni], aH[mi], bH[p][q], bH[p][q+1]);
                }
            // correction pass 1: Am*Bh, f16 accumulate
#pragma unroll
            for (int mi = 0; mi < 2; mi++)
#pragma unroll
                for (int ni = 0; ni < 4; ni++) {
                    const int p = ni >> 1, q = 2 * (ni & 1);
                    MMA_16816_F16(corr[mi][ni], aM[mi], bH[p][q], bH[p][q+1]);
                }
            // correction pass 2 (front only): Ah*Bm, f16 accumulate
            if (PHASE == 0) {
#pragma unroll
                for (int mi = 0; mi < 2; mi++)
#pragma unroll
                    for (int ni = 0; ni < 4; ni++) {
                        const int p = ni >> 1, q = 2 * (ni & 1);
                        MMA_16816_F16(corr[mi][ni], aH[mi], bM[p][q], bM[p][q+1]);
                    }
            }
        }
        CPA_WAIT2();
        __syncthreads();
    }

    // fold fp16 corrections into fp32 accumulators
#pragma unroll
    for (int mi = 0; mi < 2; mi++)
#pragma unroll
        for (int ni = 0; ni < 4; ni++) {
            __half2 h0 = *reinterpret_cast<__half2*>(&corr[mi][ni][0]);
            __half2 h1 = *reinterpret_cast<__half2*>(&corr[mi][ni][1]);
            acc[mi][ni][0] += __low2float(h0);
            acc[mi][ni][1] += __high2float(h0);
            acc[mi][ni][2] += __low2float(h1);
            acc[mi][ni][3] += __high2float(h1);
        }

    // ---------------- epilogue: affine + threshold ----------------
    float gvv[2][2], svv[2][2];
#pragma unroll
    for (int mi = 0; mi < 2; mi++)
#pragma unroll
        for (int h = 0; h < 2; h++) {
            int r = oT + m0 + mi*16 + h*8 + g;
            gvv[mi][h] = Gp[r]; svv[mi][h] = Bp[r];
        }
    auto sp = [](float c, float gg, float ss) {
        return (__fadd_rn(__fmul_rn(c, gg), ss) >= 2.0f) ? 1.f : 0.f;
    };
    const int bb2 = slice & (B_ - 1);

    if (PHASE == 0 && mode == 0) {          // spatial: pack bits over n
        const int wq = blockIdx.x * 4 + wn;
#pragma unroll
        for (int mi = 0; mi < 2; mi++)
#pragma unroll
            for (int h = 0; h < 2; h++) {
                u32 wv = 0;
#pragma unroll
                for (int ni = 0; ni < 4; ni++)
#pragma unroll
                    for (int e = 0; e < 2; e++)
                        if (sp(acc[mi][ni][2*h+e], gvv[mi][h], svv[mi][h]) != 0.f)
                            wv |= 1u << (ni*8 + 2*t4 + e);
                wv |= __shfl_xor_sync(0xffffffffu, wv, 1);
                wv |= __shfl_xor_sync(0xffffffffu, wv, 2);
                if (t4 == 0)
                    Po[(size_t)(oT + m0 + mi*16 + 8*h + g) * 12 + wq] = wv;
            }
    } else if (PHASE == 0) {                // temporal: pack bits over c
        const int wqm = blockIdx.y * 4 + wm;
#pragma unroll
        for (int ni = 0; ni < 4; ni++)
#pragma unroll
            for (int e = 0; e < 2; e++) {
                u32 wv = 0;
#pragma unroll
                for (int mi = 0; mi < 2; mi++)
#pragma unroll
                    for (int h = 0; h < 2; h++)
                        if (sp(acc[mi][ni][2*h+e], gvv[mi][h], svv[mi][h]) != 0.f)
                            wv |= 1u << (mi*16 + 8*h + g);
                wv |= __shfl_xor_sync(0xffffffffu, wv, 4);
                wv |= __shfl_xor_sync(0xffffffffu, wv, 8);
                wv |= __shfl_xor_sync(0xffffffffu, wv, 16);
                if (lane < 4) {             // g==0, lane==t4
                    int n = nT + n0w + ni*8 + 2*t4 + e;
                    Po[(size_t)n * 12 + wqm] = wv;
                }
            }
    } else if (mode == 2) {                 // spatial back: row spike counts
        __syncthreads();
#pragma unroll
        for (int mi = 0; mi < 2; mi++)
#pragma unroll
            for (int h = 0; h < 2; h++) {
                int c = 0;
#pragma unroll
                for (int ni = 0; ni < 4; ni++)
#pragma unroll
                    for (int e = 0; e < 2; e++)
                        c += (int)sp(acc[mi][ni][2*h+e], gvv[mi][h], svv[mi][h]);
                if (c) atomicAdd(&rcnt[m0 + mi*16 + 8*h + g], c);
            }
        __syncthreads();
        if (tid < 128) {
            int v = rcnt[tid];
            if (v) atomicAdd(&acnt[slice * C_ + oT + tid], v);
        }
    } else {                                // temporal back: per-(b,c,n) counts
#pragma unroll
        for (int mi = 0; mi < 2; mi++)
#pragma unroll
            for (int h = 0; h < 2; h++) {
                int r = oT + m0 + mi*16 + 8*h + g;
#pragma unroll
                for (int ni = 0; ni < 4; ni++)
#pragma unroll
                    for (int e = 0; e < 2; e++)
                        if (sp(acc[mi][ni][2*h+e], gvv[mi][h], svv[mi][h]) != 0.f)
                            atomicAdd(&bcnt[(size_t)(bb2*C_ + r)*N_ +
                                            nT + n0w + ni*8 + 2*t4 + e], 1);
            }
    }
}

// ---------------------------------------------------------------------------
// Spatial attention — packed-word inputs, popc.  Output fp16 [n][c].
//   M[d1][d2] = sum_w popc(Kb&Vb); o[n][d2] = sum_{d1:Qbit} M; spike = (o>=8)
// ---------------------------------------------------------------------------
__global__ void __launch_bounds__(256)
attn_spatial(const u32* __restrict__ Pq, const u32* __restrict__ Pk,
             const u32* __restrict__ Pv, __half* __restrict__ Sab)
{
    __shared__ u32 Qb[32][12], Kb[32][12], Vb[32][12];
    __shared__ int Ms[32][33];

    const int blk = blockIdx.x;            // (t*B+b)*H + h
    const int h   = blk % H_;
    const int tb  = blk / H_;
    const int tid = threadIdx.x;
    const int wid = tid >> 5, lane = tid & 31;

    const size_t bw = ((size_t)tb * C_ + h*32) * 12;
    for (int i = tid; i < 384; i += 256) {
        (&Qb[0][0])[i] = Pq[bw + i];
        (&Kb[0][0])[i] = Pk[bw + i];
        (&Vb[0][0])[i] = Pv[bw + i];
    }
    __syncthreads();

    {
        const int d1  = tid >> 3;
        const int d2b = (tid & 7) * 4;
#pragma unroll
        for (int j = 0; j < 4; j++) {
            int s = 0;
#pragma unroll
            for (int w = 0; w < 12; w++) s += __popc(Kb[d1][w] & Vb[d2b + j][w]);
            Ms[d1][d2b + j] = s;
        }
    }
    __syncthreads();

    const __half ONE = __float2half(1.f), ZERO = __float2half(0.f);
    __half* ob = Sab + (size_t)tb * CN;   // [n][c]
#pragma unroll
    for (int gg = 0; gg < 6; gg++) {
        const int nb = wid*48 + gg*8;
        const int w  = nb >> 5, sh = nb & 31;
        int o[8];
#pragma unroll
        for (int j = 0; j < 8; j++) o[j] = 0;
#pragma unroll 4
        for (int d1 = 0; d1 < 32; d1++) {
            const int m = Ms[d1][lane];
            const u32 bits = (Qb[d1][w] >> sh) & 0xffu;
#pragma unroll
            for (int j = 0; j < 8; j++)
                if (bits & (1u << j)) o[j] += m;
        }
#pragma unroll
        for (int j = 0; j < 8; j++)
            ob[(size_t)(nb + j) * C_ + h*D_ + lane] = (o[j] >= 8) ? ONE : ZERO;
    }
}

// ---------------------------------------------------------------------------
// Temporal attention — packed-word inputs, popc.  One warp per (n,b,h).
// Output fp16 at torch-reshape position: idx=10h+t; t'=idx/12; c'=(idx%12)*32+lane
// ---------------------------------------------------------------------------
__global__ void __launch_bounds__(256)
attn_temporal(const u32* __restrict__ Pq, const u32* __restrict__ Pk,
              const u32* __restrict__ Pv, __half* __restrict__ Stb)
{
    const int gwid = blockIdx.x * 8 + (threadIdx.x >> 5);   // 0..18431
    const int lane = threadIdx.x & 31;
    const int n = gwid % N_;
    const int b = (gwid / N_) & 3;
    const int h = gwid / (N_ * B_);

    u32 qb[10], kb[10], vloc = 0;
#pragma unroll
    for (int t = 0; t < 10; t++) {
        size_t w = ((size_t)(t*B_ + b) * N_ + n) * 12 + h;
        qb[t] = Pq[w];
        kb[t] = Pk[w];
        vloc |= ((Pv[w] >> lane) & 1u) << t;
    }
    const __half ONE = __float2half(1.f), ZERO = __float2half(0.f);
#pragma unroll
    for (int t = 0; t < 10; t++) {
        int o = 0;
#pragma unroll
        for (int s = 0; s < 10; s++)
            if ((vloc >> s) & 1u) o += __popc(qb[t] & kb[s]);
        const int idx = 10*h + t;
        const int tn = idx / 12, wn2 = idx % 12;
        Stb[(((size_t)tn * B_ + b) * N_ + n) * C_ + wn2*32 + lane] = (o >= 8) ? ONE : ZERO;
    }
}

// out[t,b,c,n] = (acnt[t,b,c]/384) * (bcnt[b,c,n]/10)
__global__ void finalize_kernel(const int* __restrict__ acnt,
                                const int* __restrict__ bcnt,
                                float* __restrict__ out)
{
    int i = blockIdx.x * 256 + threadIdx.x;
    if (i >= TEN) return;
    int n  = i % N_;
    int c  = (i / N_) % C_;
    int bb = (i / (N_ * C_)) % B_;
    int t  = i / (N_ * C_ * B_);
    float a  = (float)acnt[(t * B_ + bb) * C_ + c] / 384.0f;
    float bt = (float)bcnt[(bb * C_ + c) * N_ + n] / 10.0f;
    out[i] = a * bt;
}

extern "C" void kernel_launch(void* const* d_in, const int* in_sizes, int n_in,
                              void* d_out, int out_size)
{
    (void)in_sizes; (void)n_in; (void)out_size;
    const float* x  = (const float*)d_in[0];
    const float* y  = (const float*)d_in[1];
    const float* Ws = (const float*)d_in[2];
    const float* gs = (const float*)d_in[3];
    const float* bs = (const float*)d_in[4];
    const float* Wt = (const float*)d_in[5];
    const float* gt = (const float*)d_in[6];
    const float* bt = (const float*)d_in[7];
    float* out = (float*)d_out;

    u32 *Pqs, *Pks, *Pvs, *Pqt, *Pkt, *Pvt;
    __half *Sab, *Stb, *Wh, *Xh;
    int *acnt, *bcnt;
    cudaGetSymbolAddress((void**)&Pqs, g_Pqs);
    cudaGetSymbolAddress((void**)&Pks, g_Pks);
    cudaGetSymbolAddress((void**)&Pvs, g_Pvs);
    cudaGetSymbolAddress((void**)&Pqt, g_Pqt);
    cudaGetSymbolAddress((void**)&Pkt, g_Pkt);
    cudaGetSymbolAddress((void**)&Pvt, g_Pvt);
    cudaGetSymbolAddress((void**)&Sab, g_Sab);
    cudaGetSymbolAddress((void**)&Stb, g_Stb);
    cudaGetSymbolAddress((void**)&Wh,  g_Wh);
    cudaGetSymbolAddress((void**)&Xh,  g_Xh);
    cudaGetSymbolAddress((void**)&acnt, g_acnt);
    cudaGetSymbolAddress((void**)&bcnt, g_bcnt);

    cudaFuncSetAttribute(hmma_gemm<0>, cudaFuncAttributeMaxDynamicSharedMemorySize, SMEM_F);
    cudaFuncSetAttribute(hmma_gemm<1>, cudaFuncAttributeMaxDynamicSharedMemorySize, SMEM_K);

    cudaMemsetAsync(acnt, 0, sizeof(int) * T_ * B_ * C_, 0);
    cudaMemsetAsync(bcnt, 0, sizeof(int) * B_ * C_ * N_, 0);

    // Prepasses: W fp16 2-split; X transpose + fp16 2-split
    prep_w<<<(8*C2 + 255)/256, 256>>>(Ws, Wt, Wh);
    prep_x<<<dim3(N_/32, C_/32, 2*SLICES), dim3(32, 8)>>>(x, y, Xh);

    probe_pad<<<1, 32>>>();   // aligns ncu -s 5 onto the front GEMM

    // Six front convs on tensor cores: grid z = conv*40 + slice
    hmma_gemm<0><<<dim3(3, 3, 6*SLICES), 512, SMEM_F>>>(
        Wh, Xh, Sab, Stb, gs, bs, gt, bt,
        Pqs, Pks, Pvs, Pqt, Pkt, Pvt, acnt, bcnt);

    // Exact-integer attention on packed spike words -> fp16 [n][c] outputs
    attn_spatial <<<SLICES * H_, 256>>>(Pqs, Pks, Pvs, Sab);
    attn_temporal<<<(N_ * B_ * H_) / 8, 256>>>(Pqt, Pkt, Pvt, Stb);

    // Two back convs on tensor cores: grid z = which*40 + slice
    hmma_gemm<1><<<dim3(3, 3, 2*SLICES), 512, SMEM_K>>>(
        Wh, Xh, Sab, Stb, gs, bs, gt, bt,
        Pqs, Pks, Pvs, Pqt, Pkt, Pvt, acnt, bcnt);

    // Rank-1 outer product
    finalize_kernel<<<(TEN + 255)/256, 256>>>(acnt, bcnt, out);
}

// round 16
// speedup vs baseline: 3.0914x; 1.1700x over previous
#include <cuda_runtime.h>
#include <cuda_fp16.h>
#include <stdint.h>

// Problem constants
#define T_  10
#define B_  4
#define C_  384
#define N_  384
#define H_  12
#define D_  32
#define SLICES (T_*B_)                 // 40
#define TEN (T_*B_*C_*N_)              // 5,898,240
#define C2  (C_*C_)
#define CN  (C_*N_)

typedef unsigned int u32;

// Scratch (device globals — no allocations allowed)
__device__ __align__(16) u32 g_Pqs[SLICES*C_*12];   // spatial q spikes, bits over n: [slice][c][12]
__device__ __align__(16) u32 g_Pks[SLICES*C_*12];
__device__ __align__(16) u32 g_Pvs[SLICES*C_*12];
__device__ __align__(16) u32 g_Pqt[SLICES*N_*12];   // temporal q spikes, bits over c: [slice][n][12]
__device__ __align__(16) u32 g_Pkt[SLICES*N_*12];
__device__ __align__(16) u32 g_Pvt[SLICES*N_*12];
__device__ __align__(16) __half g_Sab[TEN];   // spatial attn spikes fp16 [slice][n][c]
__device__ __align__(16) __half g_Stb[TEN];   // temporal attn spikes fp16 [t'][b][n][c']
__device__ __align__(16) __half g_Wh[8*2*C2];                  // [conv][split h/m][o][c]
__device__ __align__(16) __half g_Xh[(size_t)2*2*SLICES*CN];   // [src][split][slice][n][c]
__device__ int g_acnt[T_*B_*C_];
__device__ int g_bcnt[B_*C_*N_];

// ---------------------------------------------------------------------------
// helpers: cp.async, ldmatrix, mma.sync (portable to compute_103)
// ---------------------------------------------------------------------------
__device__ __forceinline__ u32 smem_u32(const void* p) {
    u32 a;
    asm("{ .reg .u64 t; cvta.to.shared.u64 t, %1; cvt.u32.u64 %0, t; }" : "=r"(a) : "l"(p));
    return a;
}
__device__ __forceinline__ void cpa16(u32 saddr, const void* g) {
    asm volatile("cp.async.cg.shared.global [%0], [%1], 16;" :: "r"(saddr), "l"(g));
}
#define CPA_COMMIT() asm volatile("cp.async.commit_group;")
#define CPA_WAIT1()  asm volatile("cp.async.wait_group 1;")

#define LDSM4(R, addr) \
    asm volatile("ldmatrix.sync.aligned.m8n8.x4.shared.b16 {%0,%1,%2,%3}, [%4];" \
                 : "=r"((R)[0]), "=r"((R)[1]), "=r"((R)[2]), "=r"((R)[3]) : "r"(addr))

// fp32-accumulate MMA (main term)
#define MMA_16816(C4, A4, b0, b1) \
    asm volatile("mma.sync.aligned.m16n8k16.row.col.f32.f16.f16.f32 " \
                 "{%0,%1,%2,%3},{%4,%5,%6,%7},{%8,%9},{%0,%1,%2,%3};" \
                 : "+f"((C4)[0]), "+f"((C4)[1]), "+f"((C4)[2]), "+f"((C4)[3]) \
                 : "r"((A4)[0]), "r"((A4)[1]), "r"((A4)[2]), "r"((A4)[3]), \
                   "r"(b0), "r"(b1))

// fp16-accumulate MMA (correction terms ~2^-11 of main — fp16 precision ample)
#define MMA_16816_F16(C2v, A4, b0, b1) \
    asm volatile("mma.sync.aligned.m16n8k16.row.col.f16.f16.f16.f16 " \
                 "{%0,%1},{%2,%3,%4,%5},{%6,%7},{%0,%1};" \
                 : "+r"((C2v)[0]), "+r"((C2v)[1]) \
                 : "r"((A4)[0]), "r"((A4)[1]), "r"((A4)[2]), "r"((A4)[3]), \
                   "r"(b0), "r"(b1))

// ---------------------------------------------------------------------------
// prep_w: fp16 2-split of all 8 W matrices: [conv][split][o][c]
// ---------------------------------------------------------------------------
__global__ void prep_w(const float* __restrict__ Ws, const float* __restrict__ Wt,
                       __half* __restrict__ Wh)
{
    int i = blockIdx.x * 256 + threadIdx.x;
    if (i >= 8 * C2) return;
    int m = i / C2, r = i % C2;
    float w = (m < 4) ? Ws[i] : Wt[i - 4*C2];
    __half h = __float2half_rn(w);
    float rh = w - __half2float(h);
    __half md = __float2half_rn(rh);
    Wh[((size_t)m*2 + 0)*C2 + r] = h;
    Wh[((size_t)m*2 + 1)*C2 + r] = md;
}

// ---------------------------------------------------------------------------
// prep_x: transpose x,y slices [c][n] -> [n][c], fp16 2-split
// ---------------------------------------------------------------------------
__global__ void prep_x(const float* __restrict__ x, const float* __restrict__ y,
                       __half* __restrict__ Xh)
{
    __shared__ float t[32][33];
    const int z = blockIdx.z;
    const int src = z / SLICES, slice = z % SLICES;
    const float* X = (src ? y : x) + (size_t)slice * CN;
    const int n0 = blockIdx.x * 32, c0 = blockIdx.y * 32;
    const int tx = threadIdx.x, ty = threadIdx.y;
#pragma unroll
    for (int j = 0; j < 32; j += 8)
        t[ty + j][tx] = X[(size_t)(c0 + ty + j) * N_ + n0 + tx];
    __syncthreads();
    const size_t so = (size_t)SLICES * CN;
    const size_t ob = ((size_t)src * 2 * SLICES + slice) * CN;
#pragma unroll
    for (int j = 0; j < 32; j += 8) {
        float v = t[tx][ty + j];
        __half h = __float2half_rn(v);
        float rh = v - __half2float(h);
        __half md = __float2half_rn(rh);
        size_t a = ob + (size_t)(n0 + ty + j) * C_ + c0 + tx;
        Xh[a] = h; Xh[a + so] = md;
    }
}

// probe no-op: aligns ncu's -s 5 -c 1 capture onto hmma_gemm<0>
__global__ void probe_pad() {}

// ---------------------------------------------------------------------------
// HMMA fp16-split GEMM with register-level fragment double buffering.
// Z[o][n] = sum_c W[o][c] X[c][n], affine, spike (z>=2).
// CTA 128x128, 16 warps (4M x 4N), warp tile 32x32, K chunks of 32 halves,
// 4-stage cp.async pipeline.  aH/bH fragments double-buffered; aM/bM loaded
// mid-iteration (latency covered by pass-1 MMAs) so LDSM (smem pipe) overlaps
// MMA (tensor pipe) instead of phase-alternating.
// PHASE 0 (front): f32 (Ah,Bh); f16 (Am,Bh)+(Ah,Bm); tiles {Ah,Am,Bh,Bm}
//   mode 0 spatial  -> packed u32 bits-over-n  [slice][c][12]
//   mode 1 temporal -> packed u32 bits-over-c  [slice][n][12]
// PHASE 1 (back): B = attn spikes fp16 (exact); f32 (Ah,B); f16 (Am,B)
//   mode 2 spatial back  -> acnt row counts
//   mode 3 temporal back -> bcnt per-(b,c,n) counts
// ---------------------------------------------------------------------------
#define ROWB   80                      // bytes per smem row: 32 halves + 8 pad
#define TILE_B (128*ROWB)              // 10240
#define STAGES 4
#define SMEM_F (STAGES*4*TILE_B)       // 163840
#define SMEM_K (STAGES*3*TILE_B)       // 122880

template<int PHASE>
__global__ void __launch_bounds__(512, 1)
hmma_gemm(const __half* __restrict__ Wh, const __half* __restrict__ Xh,
          const __half* __restrict__ Sab, const __half* __restrict__ Stb,
          const float* __restrict__ gs, const float* __restrict__ bs,
          const float* __restrict__ gt, const float* __restrict__ bt,
          u32* __restrict__ Pqs, u32* __restrict__ Pks, u32* __restrict__ Pvs,
          u32* __restrict__ Pqt, u32* __restrict__ Pkt, u32* __restrict__ Pvt,
          int* __restrict__ acnt, int* __restrict__ bcnt)
{
    extern __shared__ char smem[];
    __shared__ int rcnt[128];
    const u32 smb = smem_u32(smem);
    const int tid = threadIdx.x;
    const int wid = tid >> 5, lane = tid & 31;
    const int g = lane >> 2, t4 = lane & 3;
    const int wm = wid & 3, wn = wid >> 2;       // warp grid 4(M) x 4(N)
    const int m0 = wm * 32, n0w = wn * 32;

    const int z = blockIdx.z;
    const int sel = z / SLICES;
    const int slice = z % SLICES;

    const float *Gp, *Bp;
    u32* Po = nullptr;
    int widx, mode;
    const __half *Bh_g, *Bm_g;
    if (PHASE == 0) {
        if (sel < 3) { widx = sel;     Gp = gs + sel*C_;     Bp = bs + sel*C_;     mode = 0; }
        else         { widx = sel + 1; Gp = gt + (sel-3)*C_; Bp = bt + (sel-3)*C_; mode = 1; }
        const int src = (sel == 0 || sel == 3) ? 0 : 1;
        Bh_g = Xh + ((size_t)(src*2 + 0) * SLICES + slice) * CN;
        Bm_g = Xh + ((size_t)(src*2 + 1) * SLICES + slice) * CN;
        if      (sel == 0) Po = Pqs; else if (sel == 1) Po = Pks; else if (sel == 2) Po = Pvs;
        else if (sel == 3) Po = Pqt; else if (sel == 4) Po = Pkt; else               Po = Pvt;
        Po += (size_t)slice * ((mode == 0) ? C_ : N_) * 12;
    } else {
        if (sel == 0) { widx = 3; Gp = gs + 3*C_; Bp = bs + 3*C_; mode = 2; }
        else          { widx = 7; Gp = gt + 3*C_; Bp = bt + 3*C_; mode = 3; }
        Bh_g = (sel ? Stb : Sab) + (size_t)slice * CN;
        Bm_g = Bh_g;
    }
    const __half* Ah_g = Wh + (size_t)(widx*2 + 0) * C2;
    const __half* Am_g = Wh + (size_t)(widx*2 + 1) * C2;

    const int oT = blockIdx.y * 128;
    const int nT = blockIdx.x * 128;
    constexpr int NTILE = (PHASE == 0) ? 4 : 3;
    constexpr u32 STAGE = NTILE * TILE_B;

    if (tid < 128) rcnt[tid] = 0;

    const __half* tp[4];
    tp[0] = Ah_g; tp[1] = Am_g; tp[2] = Bh_g; tp[3] = (PHASE == 0) ? Bm_g : Bh_g;

    auto issue = [&](int kb) {
        const int k0 = kb * 32;
        const u32 sb = smb + (u32)(kb & (STAGES-1)) * STAGE;
        const int row = tid >> 2, ch = tid & 3;
#pragma unroll
        for (int it = 0; it < NTILE; it++) {
            int rbase = (it < 2) ? oT : nT;
            const __half* gp = tp[it] + (size_t)(rbase + row) * C_ + k0 + ch*8;
            cpa16(sb + (u32)it * TILE_B + (u32)(row * ROWB + ch * 16), gp);
        }
        CPA_COMMIT();
    };

    float acc[2][4][4];
    u32 corr[2][4][2];                   // fp16x2 correction accumulators
#pragma unroll
    for (int mi = 0; mi < 2; mi++)
#pragma unroll
        for (int ni = 0; ni < 4; ni++) {
#pragma unroll
            for (int e = 0; e < 4; e++) acc[mi][ni][e] = 0.f;
            corr[mi][ni][0] = 0u; corr[mi][ni][1] = 0u;
        }

    // per-thread ldmatrix offsets (bytes)
    const u32 aoff = (u32)((lane & 15) * ROWB + (lane >> 4) * 16);
    const u32 boff = (u32)(((lane & 7) + 8 * (lane >> 4)) * ROWB + ((lane >> 3) & 1) * 16);

    // fragment buffers: aH/bH double-buffered; aM/bM single
    u32 aH0[2][4], aH1[2][4], bH0[2][4], bH1[2][4], aM[2][4], bM[2][4];

    auto ldA = [&](u32 (*dst)[4], u32 stg, int tile, u32 kof) {
#pragma unroll
        for (int mi = 0; mi < 2; mi++)
            LDSM4(dst[mi], stg + (u32)tile*TILE_B + aoff + (u32)((m0 + mi*16) * ROWB) + kof);
    };
    auto ldB = [&](u32 (*dst)[4], u32 stg, int tile, u32 kof) {
#pragma unroll
        for (int p = 0; p < 2; p++)
            LDSM4(dst[p], stg + (u32)tile*TILE_B + boff + (u32)((n0w + p*16) * ROWB) + kof);
    };
    auto passAcc = [&](u32 (*a)[4], u32 (*b)[4]) {
#pragma unroll
        for (int mi = 0; mi < 2; mi++)
#pragma unroll
            for (int ni = 0; ni < 4; ni++) {
                const int p = ni >> 1, q = 2 * (ni & 1);
                MMA_16816(acc[mi][ni], a[mi], b[p][q], b[p][q+1]);
            }
    };
    auto passCorr = [&](u32 (*a)[4], u32 (*b)[4]) {
#pragma unroll
        for (int mi = 0; mi < 2; mi++)
#pragma unroll
            for (int ni = 0; ni < 4; ni++) {
                const int p = ni >> 1, q = 2 * (ni & 1);
                MMA_16816_F16(corr[mi][ni], a[mi], b[p][q], b[p][q+1]);
            }
    };

    // prologue: 3 stages in flight; stages 0,1 resident; preload ks0 frags
    issue(0); issue(1); issue(2);
    CPA_WAIT1();
    __syncthreads();
    ldA(aH0, smb, 0, 0);
    ldB(bH0, smb, 2, 0);

#pragma unroll 1
    for (int s = 0; s < 12; s++) {
        const u32 stg  = smb + (u32)(s & 3) * STAGE;
        const u32 stgn = smb + (u32)((s + 1) & 3) * STAGE;
        // ---- ks0 (kof = 0) ----
        ldA(aM, stg, 1, 0);
        if (PHASE == 0) ldB(bM, stg, 3, 0);
        passAcc(aH0, bH0);
        ldA(aH1, stg, 0, 32);          // prefetch ks1 frags (overlaps tensor)
        ldB(bH1, stg, 2, 32);
        passCorr(aM, bH0);
        if (PHASE == 0) passCorr(aH0, bM);
        // ---- ks1 (kof = 32) ----
        if (s + 3 < 12) issue(s + 3);  // overwrites stage s-1 (sync-protected)
        ldA(aM, stg, 1, 32);
        if (PHASE == 0) ldB(bM, stg, 3, 32);
        passAcc(aH1, bH1);
        if (s < 11) {                  // prefetch next stage's ks0 frags
            ldA(aH0, stgn, 0, 0);
            ldB(bH0, stgn, 2, 0);
        }
        passCorr(aM, bH1);
        if (PHASE == 0) passCorr(aH1, bM);
        CPA_WAIT1();                   // stage s+2 resident
        __syncthreads();               // visibility + protects stage s reuse
    }

    // fold fp16 corrections into fp32 accumulators
#pragma unroll
    for (int mi = 0; mi < 2; mi++)
#pragma unroll
        for (int ni = 0; ni < 4; ni++) {
            __half2 h0 = *reinterpret_cast<__half2*>(&corr[mi][ni][0]);
            __half2 h1 = *reinterpret_cast<__half2*>(&corr[mi][ni][1]);
            acc[mi][ni][0] += __low2float(h0);
            acc[mi][ni][1] += __high2float(h0);
            acc[mi][ni][2] += __low2float(h1);
            acc[mi][ni][3] += __high2float(h1);
        }

    // ---------------- epilogue: affine + threshold ----------------
    float gvv[2][2], svv[2][2];
#pragma unroll
    for (int mi = 0; mi < 2; mi++)
#pragma unroll
        for (int h = 0; h < 2; h++) {
            int r = oT + m0 + mi*16 + h*8 + g;
            gvv[mi][h] = Gp[r]; svv[mi][h] = Bp[r];
        }
    auto sp = [](float c, float gg, float ss) {
        return (__fadd_rn(__fmul_rn(c, gg), ss) >= 2.0f) ? 1.f : 0.f;
    };
    const int bb2 = slice & (B_ - 1);

    if (PHASE == 0 && mode == 0) {          // spatial: pack bits over n
        const int wq = blockIdx.x * 4 + wn;
#pragma unroll
        for (int mi = 0; mi < 2; mi++)
#pragma unroll
            for (int h = 0; h < 2; h++) {
                u32 wv = 0;
#pragma unroll
                for (int ni = 0; ni < 4; ni++)
#pragma unroll
                    for (int e = 0; e < 2; e++)
                        if (sp(acc[mi][ni][2*h+e], gvv[mi][h], svv[mi][h]) != 0.f)
                            wv |= 1u << (ni*8 + 2*t4 + e);
                wv |= __shfl_xor_sync(0xffffffffu, wv, 1);
                wv |= __shfl_xor_sync(0xffffffffu, wv, 2);
                if (t4 == 0)
                    Po[(size_t)(oT + m0 + mi*16 + 8*h + g) * 12 + wq] = wv;
            }
    } else if (PHASE == 0) {                // temporal: pack bits over c
        const int wqm = blockIdx.y * 4 + wm;
#pragma unroll
        for (int ni = 0; ni < 4; ni++)
#pragma unroll
            for (int e = 0; e < 2; e++) {
                u32 wv = 0;
#pragma unroll
                for (int mi = 0; mi < 2; mi++)
#pragma unroll
                    for (int h = 0; h < 2; h++)
                        if (sp(acc[mi][ni][2*h+e], gvv[mi][h], svv[mi][h]) != 0.f)
                            wv |= 1u << (mi*16 + 8*h + g);
                wv |= __shfl_xor_sync(0xffffffffu, wv, 4);
                wv |= __shfl_xor_sync(0xffffffffu, wv, 8);
                wv |= __shfl_xor_sync(0xffffffffu, wv, 16);
                if (lane < 4) {             // g==0, lane==t4
                    int n = nT + n0w + ni*8 + 2*t4 + e;
                    Po[(size_t)n * 12 + wqm] = wv;
                }
            }
    } else if (mode == 2) {                 // spatial back: row spike counts
        __syncthreads();
#pragma unroll
        for (int mi = 0; mi < 2; mi++)
#pragma unroll
            for (int h = 0; h < 2; h++) {
                int c = 0;
#pragma unroll
                for (int ni = 0; ni < 4; ni++)
#pragma unroll
                    for (int e = 0; e < 2; e++)
                        c += (int)sp(acc[mi][ni][2*h+e], gvv[mi][h], svv[mi][h]);
                if (c) atomicAdd(&rcnt[m0 + mi*16 + 8*h + g], c);
            }
        __syncthreads();
        if (tid < 128) {
            int v = rcnt[tid];
            if (v) atomicAdd(&acnt[slice * C_ + oT + tid], v);
        }
    } else {                                // temporal back: per-(b,c,n) counts
#pragma unroll
        for (int mi = 0; mi < 2; mi++)
#pragma unroll
            for (int h = 0; h < 2; h++) {
                int r = oT + m0 + mi*16 + 8*h + g;
#pragma unroll
                for (int ni = 0; ni < 4; ni++)
#pragma unroll
                    for (int e = 0; e < 2; e++)
                        if (sp(acc[mi][ni][2*h+e], gvv[mi][h], svv[mi][h]) != 0.f)
                            atomicAdd(&bcnt[(size_t)(bb2*C_ + r)*N_ +
                                            nT + n0w + ni*8 + 2*t4 + e], 1);
            }
    }
}

// ---------------------------------------------------------------------------
// Spatial attention — packed-word inputs, popc.  Output fp16 [n][c].
//   M[d1][d2] = sum_w popc(Kb&Vb); o[n][d2] = sum_{d1:Qbit} M; spike = (o>=8)
// ---------------------------------------------------------------------------
__global__ void __launch_bounds__(256)
attn_spatial(const u32* __restrict__ Pq, const u32* __restrict__ Pk,
             const u32* __restrict__ Pv, __half* __restrict__ Sab)
{
    __shared__ u32 Qb[32][12], Kb[32][12], Vb[32][12];
    __shared__ int Ms[32][33];

    const int blk = blockIdx.x;            // (t*B+b)*H + h
    const int h   = blk % H_;
    const int tb  = blk / H_;
    const int tid = threadIdx.x;
    const int wid = tid >> 5, lane = tid & 31;

    const size_t bw = ((size_t)tb * C_ + h*32) * 12;
    for (int i = tid; i < 384; i += 256) {
        (&Qb[0][0])[i] = Pq[bw + i];
        (&Kb[0][0])[i] = Pk[bw + i];
        (&Vb[0][0])[i] = Pv[bw + i];
    }
    __syncthreads();

    {
        const int d1  = tid >> 3;
        const int d2b = (tid & 7) * 4;
#pragma unroll
        for (int j = 0; j < 4; j++) {
            int s = 0;
#pragma unroll
            for (int w = 0; w < 12; w++) s += __popc(Kb[d1][w] & Vb[d2b + j][w]);
            Ms[d1][d2b + j] = s;
        }
    }
    __syncthreads();

    const __half ONE = __float2half(1.f), ZERO = __float2half(0.f);
    __half* ob = Sab + (size_t)tb * CN;   // [n][c]
#pragma unroll
    for (int gg = 0; gg < 6; gg++) {
        const int nb = wid*48 + gg*8;
        const int w  = nb >> 5, sh = nb & 31;
        int o[8];
#pragma unroll
        for (int j = 0; j < 8; j++) o[j] = 0;
#pragma unroll 4
        for (int d1 = 0; d1 < 32; d1++) {
            const int m = Ms[d1][lane];
            const u32 bits = (Qb[d1][w] >> sh) & 0xffu;
#pragma unroll
            for (int j = 0; j < 8; j++)
                if (bits & (1u << j)) o[j] += m;
        }
#pragma unroll
        for (int j = 0; j < 8; j++)
            ob[(size_t)(nb + j) * C_ + h*D_ + lane] = (o[j] >= 8) ? ONE : ZERO;
    }
}

// ---------------------------------------------------------------------------
// Temporal attention — packed-word inputs, popc.  One warp per (n,b,h).
// Output fp16 at torch-reshape position: idx=10h+t; t'=idx/12; c'=(idx%12)*32+lane
// ---------------------------------------------------------------------------
__global__ void __launch_bounds__(256)
attn_temporal(const u32* __restrict__ Pq, const u32* __restrict__ Pk,
              const u32* __restrict__ Pv, __half* __restrict__ Stb)
{
    const int gwid = blockIdx.x * 8 + (threadIdx.x >> 5);   // 0..18431
    const int lane = threadIdx.x & 31;
    const int n = gwid % N_;
    const int b = (gwid / N_) & 3;
    const int h = gwid / (N_ * B_);

    u32 qb[10], kb[10], vloc = 0;
#pragma unroll
    for (int t = 0; t < 10; t++) {
        size_t w = ((size_t)(t*B_ + b) * N_ + n) * 12 + h;
        qb[t] = Pq[w];
        kb[t] = Pk[w];
        vloc |= ((Pv[w] >> lane) & 1u) << t;
    }
    const __half ONE = __float2half(1.f), ZERO = __float2half(0.f);
#pragma unroll
    for (int t = 0; t < 10; t++) {
        int o = 0;
#pragma unroll
        for (int s = 0; s < 10; s++)
            if ((vloc >> s) & 1u) o += __popc(qb[t] & kb[s]);
        const int idx = 10*h + t;
        const int tn = idx / 12, wn2 = idx % 12;
        Stb[(((size_t)tn * B_ + b) * N_ + n) * C_ + wn2*32 + lane] = (o >= 8) ? ONE : ZERO;
    }
}

// out[t,b,c,n] = (acnt[t,b,c]/384) * (bcnt[b,c,n]/10)
__global__ void finalize_kernel(const int* __restrict__ acnt,
                                const int* __restrict__ bcnt,
                                float* __restrict__ out)
{
    int i = blockIdx.x * 256 + threadIdx.x;
    if (i >= TEN) return;
    int n  = i % N_;
    int c  = (i / N_) % C_;
    int bb = (i / (N_ * C_)) % B_;
    int t  = i / (N_ * C_ * B_);
    float a  = (float)acnt[(t * B_ + bb) * C_ + c] / 384.0f;
    float bt = (float)bcnt[(bb * C_ + c) * N_ + n] / 10.0f;
    out[i] = a * bt;
}

extern "C" void kernel_launch(void* const* d_in, const int* in_sizes, int n_in,
                              void* d_out, int out_size)
{
    (void)in_sizes; (void)n_in; (void)out_size;
    const float* x  = (const float*)d_in[0];
    const float* y  = (const float*)d_in[1];
    const float* Ws = (const float*)d_in[2];
    const float* gs = (const float*)d_in[3];
    const float* bs = (const float*)d_in[4];
    const float* Wt = (const float*)d_in[5];
    const float* gt = (const float*)d_in[6];
    const float* bt = (const float*)d_in[7];
    float* out = (float*)d_out;

    u32 *Pqs, *Pks, *Pvs, *Pqt, *Pkt, *Pvt;
    __half *Sab, *Stb, *Wh, *Xh;
    int *acnt, *bcnt;
    cudaGetSymbolAddress((void**)&Pqs, g_Pqs);
    cudaGetSymbolAddress((void**)&Pks, g_Pks);
    cudaGetSymbolAddress((void**)&Pvs, g_Pvs);
    cudaGetSymbolAddress((void**)&Pqt, g_Pqt);
    cudaGetSymbolAddress((void**)&Pkt, g_Pkt);
    cudaGetSymbolAddress((void**)&Pvt, g_Pvt);
    cudaGetSymbolAddress((void**)&Sab, g_Sab);
    cudaGetSymbolAddress((void**)&Stb, g_Stb);
    cudaGetSymbolAddress((void**)&Wh,  g_Wh);
    cudaGetSymbolAddress((void**)&Xh,  g_Xh);
    cudaGetSymbolAddress((void**)&acnt, g_acnt);
    cudaGetSymbolAddress((void**)&bcnt, g_bcnt);

    cudaFuncSetAttribute(hmma_gemm<0>, cudaFuncAttributeMaxDynamicSharedMemorySize, SMEM_F);
    cudaFuncSetAttribute(hmma_gemm<1>, cudaFuncAttributeMaxDynamicSharedMemorySize, SMEM_K);

    cudaMemsetAsync(acnt, 0, sizeof(int) * T_ * B_ * C_, 0);
    cudaMemsetAsync(bcnt, 0, sizeof(int) * B_ * C_ * N_, 0);

    // Prepasses: W fp16 2-split; X transpose + fp16 2-split
    prep_w<<<(8*C2 + 255)/256, 256>>>(Ws, Wt, Wh);
    prep_x<<<dim3(N_/32, C_/32, 2*SLICES), dim3(32, 8)>>>(x, y, Xh);

    probe_pad<<<1, 32>>>();   // aligns ncu -s 5 onto the front GEMM

    // Six front convs on tensor cores: grid z = conv*40 + slice
    hmma_gemm<0><<<dim3(3, 3, 6*SLICES), 512, SMEM_F>>>(
        Wh, Xh, Sab, Stb, gs, bs, gt, bt,
        Pqs, Pks, Pvs, Pqt, Pkt, Pvt, acnt, bcnt);

    // Exact-integer attention on packed spike words -> fp16 [n][c] outputs
    attn_spatial <<<SLICES * H_, 256>>>(Pqs, Pks, Pvs, Sab);
    attn_temporal<<<(N_ * B_ * H_) / 8, 256>>>(Pqt, Pkt, Pvt, Stb);

    // Two back convs on tensor cores: grid z = which*40 + slice
    hmma_gemm<1><<<dim3(3, 3, 2*SLICES), 512, SMEM_K>>>(
        Wh, Xh, Sab, Stb, gs, bs, gt, bt,
        Pqs, Pks, Pvs, Pqt, Pkt, Pvt, acnt, bcnt);

    // Rank-1 outer product
    finalize_kernel<<<(TEN + 255)/256, 256>>>(acnt, bcnt, out);
}